// round 1
// baseline (speedup 1.0000x reference)
#include <cuda_runtime.h>
#include <float.h>

// ---------------- problem constants ----------------
#define BB    8
#define NPT   2048
#define BNP   16384          // BB*NPT
#define KNN   20
#define CH    64
#define FD    256            // 4*CH
#define EMB   1024

// ---------------- scratch (device globals; no mallocs allowed) ----------------
__device__ float d_P[BB*3*NPT];        // scrambled pts, [b][c][n]
__device__ float d_XX[BNP];            // squared norms of scrambled pts
__device__ int   d_nbr[BNP*KNN];       // forward knn (global q indices)
__device__ int   d_deg[BNP];
__device__ int   d_rowstart[BNP+1];
__device__ int   d_cursor[BNP];
__device__ int   d_rev[BNP*KNN];       // reverse CSR payload (source p per in-edge)
__device__ float d_F[BNP*FD];          // concat features (h0..h3), row-major 256
__device__ float d_sup[BNP*CH];        // support = h @ W
__device__ float d_z[BNP*CH];          // gathered pre-BN
__device__ float d_rz[BNP*CH];         // layer0 residual pre-BN
__device__ float d_Y[(size_t)EMB*BNP]; // conv output [e][p], 64 MB
__device__ float d_x12[BB*2*EMB];      // pooled features (B, 2048)
__device__ float d_h512[BB*512];
__device__ float d_h256[BB*256];
__device__ float d_sumA[CH], d_sqA[CH], d_sumB[CH], d_sqB[CH];

// ---------------- init / prep ----------------
__global__ void k_zero_deg() {
    int t = blockIdx.x*256 + threadIdx.x;
    if (t < BNP) d_deg[t] = 0;
}

__global__ void k_zero_stats(int both) {
    int t = threadIdx.x;
    if (t < CH) {
        d_sumA[t] = 0.f; d_sqA[t] = 0.f;
        if (both) { d_sumB[t] = 0.f; d_sqB[t] = 0.f; }
    }
}

// pts[b,c,n] = x[b, (c*N+n)%3, (c*N+n)/3]  (faithful to the torch view bug)
__global__ void k_prep(const float* __restrict__ x) {
    int t = blockIdx.x*256 + threadIdx.x;
    if (t >= BNP) return;
    int b = t >> 11, n = t & 2047;
    const float* xb = x + b*3*NPT;
    float acc = 0.f;
    #pragma unroll
    for (int c = 0; c < 3; c++) {
        int L = c*NPT + n;
        float v = xb[(L % 3)*NPT + (L / 3)];
        d_P[b*3*NPT + c*NPT + n] = v;
        acc += v*v;                      // order c0,c1,c2 (matches jnp.sum over axis=1)
    }
    d_XX[t] = acc;
}

// ---------------- knn: warp per row, per-lane top-20 + warp merge ----------------
__global__ void k_knn() {
    __shared__ float s0[NPT], s1[NPT], s2[NPT], sxx[NPT];
    int b = blockIdx.x >> 5;             // 8 batches
    int chunk = blockIdx.x & 31;         // 32 chunks of 64 rows
    for (int i = threadIdx.x; i < NPT; i += 256) {
        s0[i]  = d_P[b*3*NPT + 0*NPT + i];
        s1[i]  = d_P[b*3*NPT + 1*NPT + i];
        s2[i]  = d_P[b*3*NPT + 2*NPT + i];
        sxx[i] = d_XX[b*NPT + i];
    }
    __syncthreads();

    int warp = threadIdx.x >> 5, lane = threadIdx.x & 31;
    for (int r = 0; r < 8; r++) {
        int n = chunk*64 + warp*8 + r;
        float qx = s0[n], qy = s1[n], qz = s2[n], qxx = sxx[n];
        float v[KNN]; int id[KNN]; int cnt = 0;

        for (int m = lane; m < NPT; m += 32) {
            float dot = qx*s0[m] + qy*s1[m] + qz*s2[m];
            // pd = (-xx_n) - (-2*dot) - xx_m  (bit-identical regrouping)
            float pd = (-qxx + 2.f*dot) - sxx[m];
            if (cnt < KNN) {
                int pos = cnt;
                while (pos > 0 && pd > v[pos-1]) { v[pos] = v[pos-1]; id[pos] = id[pos-1]; pos--; }
                v[pos] = pd; id[pos] = m; cnt++;
            } else if (pd > v[KNN-1]) {
                int pos = KNN-1;
                while (pos > 0 && pd > v[pos-1]) { v[pos] = v[pos-1]; id[pos] = id[pos-1]; pos--; }
                v[pos] = pd; id[pos] = m;
            }
        }
        // merge 32 sorted lists: 20 rounds of warp argmax (value desc, index asc = lax.top_k ties)
        int ptr = 0;
        int pg = b*NPT + n;
        for (int k = 0; k < KNN; k++) {
            float mv = (ptr < KNN) ? v[ptr] : -FLT_MAX;
            int   mi = (ptr < KNN) ? id[ptr] : 0x7fffffff;
            #pragma unroll
            for (int off = 16; off; off >>= 1) {
                float ov = __shfl_xor_sync(0xffffffffu, mv, off);
                int   oi = __shfl_xor_sync(0xffffffffu, mi, off);
                if (ov > mv || (ov == mv && oi < mi)) { mv = ov; mi = oi; }
            }
            if (lane == 0) {
                int q = b*NPT + mi;
                d_nbr[pg*KNN + k] = q;
                atomicAdd(&d_deg[q], 1);
            }
            if (ptr < KNN && v[ptr] == mv && id[ptr] == mi) ptr++;
        }
    }
}

// exclusive scan of 16384 degrees (single block)
__global__ void k_scan() {
    int t = threadIdx.x;
    int base = t*16;
    int loc[16]; int s = 0;
    #pragma unroll
    for (int i = 0; i < 16; i++) { loc[i] = s; s += d_deg[base+i]; }
    int lane = t & 31, wid = t >> 5;
    int vv = s;
    #pragma unroll
    for (int o = 1; o < 32; o <<= 1) { int u = __shfl_up_sync(0xffffffffu, vv, o); if (lane >= o) vv += u; }
    __shared__ int ws[32];
    if (lane == 31) ws[wid] = vv;
    __syncthreads();
    if (wid == 0) {
        int w = ws[lane];
        #pragma unroll
        for (int o = 1; o < 32; o <<= 1) { int u = __shfl_up_sync(0xffffffffu, w, o); if (lane >= o) w += u; }
        ws[lane] = w;
    }
    __syncthreads();
    int excl = vv - s + (wid ? ws[wid-1] : 0);
    #pragma unroll
    for (int i = 0; i < 16; i++) { int rs = excl + loc[i]; d_rowstart[base+i] = rs; d_cursor[base+i] = rs; }
    if (t == 1023) d_rowstart[BNP] = excl + s;
}

__global__ void k_fill() {
    int p = blockIdx.x*256 + threadIdx.x;
    if (p >= BNP) return;
    #pragma unroll
    for (int k = 0; k < KNN; k++) {
        int q = d_nbr[p*KNN + k];
        int pos = atomicAdd(&d_cursor[q], 1);
        d_rev[pos] = p;
    }
}

// ---------------- layer 0: support = flat@w0 ; rz = flat@wr + br ----------------
__global__ void k_l0mm(const float* __restrict__ x, const float* __restrict__ w0,
                       const float* __restrict__ wr, const float* __restrict__ br) {
    int t = blockIdx.x*256 + threadIdx.x;   // BNP*CH threads
    int p = t >> 6, c = t & 63;
    int b = p >> 11, n = p & 2047;
    const float* xb = x + b*3*NPT;
    float x0 = xb[n], x1 = xb[NPT + n], x2 = xb[2*NPT + n];
    d_sup[t] = x0*w0[c] + x1*w0[64+c] + x2*w0[128+c];
    d_rz[t]  = x0*wr[c] + x1*wr[64+c] + x2*wr[128+c] + br[c];
}

// ---------------- support = h @ W (64x64), h = d_F + off (ld=256) ----------------
__global__ void k_mm64(int off, const float* __restrict__ Wl) {
    __shared__ float Ws[64*64];
    __shared__ float Hs[64*64];
    int tid = threadIdx.x;
    int p0 = blockIdx.x*64;
    for (int i = tid; i < 4096; i += 256) Ws[i] = Wl[i];
    for (int i = tid; i < 4096; i += 256) {
        int r = i >> 6, k = i & 63;
        Hs[i] = d_F[(p0 + r)*FD + off + k];
    }
    __syncthreads();
    int c = tid & 63, rr = tid >> 6;
    for (int r = rr; r < 64; r += 4) {
        float acc = 0.f;
        #pragma unroll 16
        for (int k = 0; k < 64; k++) acc += Hs[r*64 + k] * Ws[k*64 + c];
        d_sup[(p0 + r)*64 + c] = acc;
    }
}

// ---------------- gather (reverse CSR) + bias ----------------
__global__ void k_gather(const float* __restrict__ bias) {
    int t = threadIdx.x;
    int q = blockIdx.x*4 + (t >> 6);
    int c = t & 63;
    float acc = bias[c];
    int s0 = d_rowstart[q], e0 = d_rowstart[q+1];
    for (int i = s0; i < e0; i++) acc += d_sup[d_rev[i]*64 + c];
    d_z[q*64 + c] = acc;
}

// ---------------- per-channel stats (sum, sumsq) ----------------
__global__ void k_colstats(int which) {  // 0: d_z->A, 1: d_rz->B
    const float* Z = which ? d_rz : d_z;
    int tid = threadIdx.x;
    int c = tid & 63, g = tid >> 6;
    int r0 = blockIdx.x*256;
    float s = 0.f, s2 = 0.f;
    for (int r = g; r < 256; r += 4) {
        float v = Z[(r0 + r)*64 + c];
        s += v; s2 += v*v;
    }
    __shared__ float sh[256], sh2[256];
    sh[tid] = s; sh2[tid] = s2;
    __syncthreads();
    if (g == 0) {
        s  = sh[c] + sh[64+c] + sh[128+c] + sh[192+c];
        s2 = sh2[c] + sh2[64+c] + sh2[128+c] + sh2[192+c];
        if (which) { atomicAdd(&d_sumB[c], s); atomicAdd(&d_sqB[c], s2); }
        else       { atomicAdd(&d_sumA[c], s); atomicAdd(&d_sqA[c], s2); }
    }
}

// ---------------- layer 0 post: h = relu(relu(bn(z)) + bn(rz)) ----------------
__global__ void k_l0post(const float* __restrict__ g0, const float* __restrict__ be0,
                         const float* __restrict__ gr, const float* __restrict__ ber) {
    int t = blockIdx.x*256 + threadIdx.x;
    int p = t >> 6, c = t & 63;
    float mA = d_sumA[c]*(1.f/BNP);
    float vA = d_sqA[c]*(1.f/BNP) - mA*mA;
    float o = (d_z[t] - mA)*rsqrtf(vA + 1e-5f)*g0[c] + be0[c];
    o = fmaxf(o, 0.f);
    float mB = d_sumB[c]*(1.f/BNP);
    float vB = d_sqB[c]*(1.f/BNP) - mB*mB;
    float r = (d_rz[t] - mB)*rsqrtf(vB + 1e-5f)*gr[c] + ber[c];
    d_F[p*FD + c] = fmaxf(o + r, 0.f);
}

// ---------------- layers 1..3 post: h = relu(relu(bn(z)) + h_prev) ----------------
__global__ void k_lpost(int layer, const float* __restrict__ G, const float* __restrict__ Be) {
    int t = blockIdx.x*256 + threadIdx.x;
    int p = t >> 6, c = t & 63;
    float m = d_sumA[c]*(1.f/BNP);
    float var = d_sqA[c]*(1.f/BNP) - m*m;
    float a = (d_z[t] - m)*rsqrtf(var + 1e-5f)*G[c] + Be[c];
    a = fmaxf(a, 0.f);
    float hp = d_F[p*FD + (layer-1)*64 + c];
    d_F[p*FD + layer*64 + c] = fmaxf(a + hp, 0.f);
}

// ---------------- conv GEMM: Y[e][p] = wconv[e,:] . F[p,:]  (1024 x 16384 x 256) ----------------
__global__ void __launch_bounds__(256) k_conv(const float* __restrict__ A) {
    __shared__ float As[16*128];
    __shared__ float Bs[16*128];
    int t = threadIdx.x;
    int tx = t & 15, ty = t >> 4;
    int bn = blockIdx.x;       // 0..127  (p tiles)
    int bm = blockIdx.y;       // 0..7    (e tiles)
    const float* Ag = A + bm*128*256;
    const float* Bg = d_F + bn*128*256;
    float acc[8][8];
    #pragma unroll
    for (int i = 0; i < 8; i++)
        #pragma unroll
        for (int j = 0; j < 8; j++) acc[i][j] = 0.f;

    for (int k0 = 0; k0 < 256; k0 += 16) {
        #pragma unroll
        for (int l = 0; l < 2; l++) {
            int lin = t + l*256;
            int row = lin >> 2, kq = lin & 3;
            float4 va = *(const float4*)(Ag + row*256 + k0 + kq*4);
            As[(kq*4+0)*128 + row] = va.x; As[(kq*4+1)*128 + row] = va.y;
            As[(kq*4+2)*128 + row] = va.z; As[(kq*4+3)*128 + row] = va.w;
            float4 vb = *(const float4*)(Bg + row*256 + k0 + kq*4);
            Bs[(kq*4+0)*128 + row] = vb.x; Bs[(kq*4+1)*128 + row] = vb.y;
            Bs[(kq*4+2)*128 + row] = vb.z; Bs[(kq*4+3)*128 + row] = vb.w;
        }
        __syncthreads();
        #pragma unroll
        for (int kk = 0; kk < 16; kk++) {
            float a[8], b[8];
            float4 a0 = *(const float4*)&As[kk*128 + ty*8];
            float4 a1 = *(const float4*)&As[kk*128 + ty*8 + 4];
            a[0]=a0.x; a[1]=a0.y; a[2]=a0.z; a[3]=a0.w; a[4]=a1.x; a[5]=a1.y; a[6]=a1.z; a[7]=a1.w;
            float4 b0 = *(const float4*)&Bs[kk*128 + tx*8];
            float4 b1 = *(const float4*)&Bs[kk*128 + tx*8 + 4];
            b[0]=b0.x; b[1]=b0.y; b[2]=b0.z; b[3]=b0.w; b[4]=b1.x; b[5]=b1.y; b[6]=b1.z; b[7]=b1.w;
            #pragma unroll
            for (int i = 0; i < 8; i++)
                #pragma unroll
                for (int j = 0; j < 8; j++) acc[i][j] += a[i]*b[j];
        }
        __syncthreads();
    }
    #pragma unroll
    for (int i = 0; i < 8; i++) {
        size_t base = (size_t)(bm*128 + ty*8 + i)*BNP + bn*128 + tx*8;
        *(float4*)&d_Y[base]     = make_float4(acc[i][0], acc[i][1], acc[i][2], acc[i][3]);
        *(float4*)&d_Y[base + 4] = make_float4(acc[i][4], acc[i][5], acc[i][6], acc[i][7]);
    }
}

// ---------------- conv BN + leaky + per-batch max/mean pooling ----------------
__global__ void k_reduce(const float* __restrict__ gf, const float* __restrict__ bef) {
    int e = blockIdx.x;
    const float* y = d_Y + (size_t)e*BNP;
    int t = threadIdx.x;
    float s = 0.f, s2 = 0.f;
    for (int p = t; p < BNP; p += 256) { float v = y[p]; s += v; s2 += v*v; }
    __shared__ float r1[256], r2[256];
    r1[t] = s; r2[t] = s2;
    __syncthreads();
    for (int o = 128; o; o >>= 1) { if (t < o) { r1[t] += r1[t+o]; r2[t] += r2[t+o]; } __syncthreads(); }
    __shared__ float smu, srs;
    if (t == 0) {
        float mu = r1[0]*(1.f/BNP);
        float var = r2[0]*(1.f/BNP) - mu*mu;
        smu = mu; srs = rsqrtf(var + 1e-5f);
    }
    __syncthreads();
    float mu = smu, sc = srs*gf[e], sh = bef[e];
    for (int b = 0; b < BB; b++) {
        float mx = -FLT_MAX, sm = 0.f;
        for (int j = t; j < NPT; j += 256) {
            float v = y[b*NPT + j];
            v = (v - mu)*sc + sh;
            v = v > 0.f ? v : 0.2f*v;
            mx = fmaxf(mx, v); sm += v;
        }
        r1[t] = mx; r2[t] = sm;
        __syncthreads();
        for (int o = 128; o; o >>= 1) { if (t < o) { r1[t] = fmaxf(r1[t], r1[t+o]); r2[t] += r2[t+o]; } __syncthreads(); }
        if (t == 0) {
            d_x12[b*2*EMB + e] = r1[0];
            d_x12[b*2*EMB + EMB + e] = r2[0]*(1.f/NPT);
        }
        __syncthreads();
    }
}

// ---------------- head ----------------
__global__ void k_head1(const float* __restrict__ w1, const float* __restrict__ g6,
                        const float* __restrict__ b6) {
    int j = blockIdx.x*256 + threadIdx.x;   // < 512
    float acc[BB];
    #pragma unroll
    for (int b = 0; b < BB; b++) acc[b] = 0.f;
    for (int k = 0; k < 2*EMB; k++) {
        float wv = w1[k*512 + j];
        #pragma unroll
        for (int b = 0; b < BB; b++) acc[b] += d_x12[b*2*EMB + k]*wv;
    }
    float m = 0.f;
    #pragma unroll
    for (int b = 0; b < BB; b++) m += acc[b];
    m *= (1.f/BB);
    float var = 0.f;
    #pragma unroll
    for (int b = 0; b < BB; b++) { float d = acc[b]-m; var += d*d; }
    var *= (1.f/BB);
    float sc = rsqrtf(var + 1e-5f)*g6[j], bb = b6[j];
    #pragma unroll
    for (int b = 0; b < BB; b++) {
        float o = (acc[b]-m)*sc + bb;
        d_h512[b*512 + j] = o > 0.f ? o : 0.2f*o;
    }
}

__global__ void k_head2(const float* __restrict__ w2, const float* __restrict__ b2,
                        const float* __restrict__ g7, const float* __restrict__ b7) {
    int j = threadIdx.x;   // 256
    float acc[BB];
    #pragma unroll
    for (int b = 0; b < BB; b++) acc[b] = 0.f;
    for (int k = 0; k < 512; k++) {
        float wv = w2[k*256 + j];
        #pragma unroll
        for (int b = 0; b < BB; b++) acc[b] += d_h512[b*512 + k]*wv;
    }
    #pragma unroll
    for (int b = 0; b < BB; b++) acc[b] += b2[j];
    float m = 0.f;
    #pragma unroll
    for (int b = 0; b < BB; b++) m += acc[b];
    m *= (1.f/BB);
    float var = 0.f;
    #pragma unroll
    for (int b = 0; b < BB; b++) { float d = acc[b]-m; var += d*d; }
    var *= (1.f/BB);
    float sc = rsqrtf(var + 1e-5f)*g7[j], bb = b7[j];
    #pragma unroll
    for (int b = 0; b < BB; b++) {
        float o = (acc[b]-m)*sc + bb;
        d_h256[b*256 + j] = o > 0.f ? o : 0.2f*o;
    }
}

__global__ void k_head3(const float* __restrict__ w3, const float* __restrict__ b3,
                        float* __restrict__ out) {
    int t = threadIdx.x;
    if (t >= BB*40) return;
    int b = t / 40, j = t % 40;
    float acc = b3[j];
    for (int k = 0; k < 256; k++) acc += d_h256[b*256 + k]*w3[k*40 + j];
    out[b*40 + j] = acc;
}

// ---------------- launch ----------------
extern "C" void kernel_launch(void* const* d_in, const int* in_sizes, int n_in,
                              void* d_out, int out_size) {
    const float* x     = (const float*)d_in[0];
    const float* w0    = (const float*)d_in[1];
    const float* b0    = (const float*)d_in[2];
    const float* g0    = (const float*)d_in[3];
    const float* be0   = (const float*)d_in[4];
    const float* wr    = (const float*)d_in[5];
    const float* br    = (const float*)d_in[6];
    const float* gr    = (const float*)d_in[7];
    const float* ber   = (const float*)d_in[8];
    const float* W     = (const float*)d_in[9];
    const float* Bv    = (const float*)d_in[10];
    const float* G     = (const float*)d_in[11];
    const float* Be    = (const float*)d_in[12];
    const float* wconv = (const float*)d_in[13];
    const float* gf    = (const float*)d_in[14];
    const float* bef   = (const float*)d_in[15];
    const float* w1    = (const float*)d_in[16];
    const float* g6    = (const float*)d_in[17];
    const float* b6    = (const float*)d_in[18];
    const float* w2    = (const float*)d_in[19];
    const float* b2    = (const float*)d_in[20];
    const float* g7    = (const float*)d_in[21];
    const float* b7    = (const float*)d_in[22];
    const float* w3    = (const float*)d_in[23];
    const float* b3    = (const float*)d_in[24];
    float* out = (float*)d_out;

    // graph build
    k_zero_deg<<<64, 256>>>();
    k_prep<<<64, 256>>>(x);
    k_knn<<<256, 256>>>();
    k_scan<<<1, 1024>>>();
    k_fill<<<64, 256>>>();

    // layer 0
    k_l0mm<<<4096, 256>>>(x, w0, wr, br);
    k_gather<<<4096, 256>>>(b0);
    k_zero_stats<<<1, 64>>>(1);
    k_colstats<<<64, 256>>>(0);
    k_colstats<<<64, 256>>>(1);
    k_l0post<<<4096, 256>>>(g0, be0, gr, ber);

    // layers 1..3
    for (int i = 1; i < 4; i++) {
        k_mm64<<<256, 256>>>((i-1)*64, W + (size_t)(i-1)*64*64);
        k_gather<<<4096, 256>>>(Bv + (i-1)*64);
        k_zero_stats<<<1, 64>>>(0);
        k_colstats<<<64, 256>>>(0);
        k_lpost<<<4096, 256>>>(i, G + (i-1)*64, Be + (i-1)*64);
    }

    // conv 256 -> 1024 + BN + leaky + pool
    dim3 cgrid(128, 8);
    k_conv<<<cgrid, 256>>>(wconv);
    k_reduce<<<1024, 256>>>(gf, bef);

    // head
    k_head1<<<2, 256>>>(w1, g6, b6);
    k_head2<<<1, 256>>>(w2, b2, g7, b7);
    k_head3<<<1, 320>>>(w3, b3, out);
}

// round 2
// speedup vs baseline: 4.3981x; 4.3981x over previous
#include <cuda_runtime.h>
#include <float.h>

// ---------------- problem constants ----------------
#define BB    8
#define NPT   2048
#define BNP   16384          // BB*NPT
#define KNN   20
#define CH    64
#define FD    256            // 4*CH
#define EMB   1024

// ---------------- scratch (device globals; no mallocs allowed) ----------------
__device__ float4 d_P4[BB*NPT];        // scrambled pts + sqnorm, [b][n] = (x,y,z,xx)
__device__ int   d_nbr[BNP*KNN];       // forward knn (global q indices)
__device__ int   d_deg[BNP];
__device__ int   d_rowstart[BNP+1];
__device__ int   d_cursor[BNP];
__device__ int   d_rev[BNP*KNN];       // reverse CSR payload (source p per in-edge)
__device__ float d_F[BNP*FD];          // concat features (h0..h3), row-major 256
__device__ float d_sup[BNP*CH];        // support = h @ W
__device__ float d_z[BNP*CH];          // gathered pre-BN
__device__ float d_rz[BNP*CH];         // layer0 residual pre-BN
__device__ float d_Y[(size_t)EMB*BNP]; // conv output [e][p], 64 MB
__device__ float d_x12[BB*2*EMB];      // pooled features (B, 2048)
__device__ float d_h512[BB*512];
__device__ float d_h256[BB*256];
__device__ float d_sumA[CH], d_sqA[CH], d_sumB[CH], d_sqB[CH];

// ---------------- init / prep ----------------
__global__ void k_zero_deg() {
    int t = blockIdx.x*256 + threadIdx.x;
    if (t < BNP) d_deg[t] = 0;
}

__global__ void k_zero_stats(int both) {
    int t = threadIdx.x;
    if (t < CH) {
        d_sumA[t] = 0.f; d_sqA[t] = 0.f;
        if (both) { d_sumB[t] = 0.f; d_sqB[t] = 0.f; }
    }
}

// pts[b,c,n] = x[b, (c*N+n)%3, (c*N+n)/3]  (faithful to the torch view bug)
__global__ void k_prep(const float* __restrict__ x) {
    int t = blockIdx.x*256 + threadIdx.x;
    if (t >= BNP) return;
    int b = t >> 11, n = t & 2047;
    const float* xb = x + b*3*NPT;
    float v[3]; float acc = 0.f;
    #pragma unroll
    for (int c = 0; c < 3; c++) {
        int L = c*NPT + n;
        v[c] = xb[(L % 3)*NPT + (L / 3)];
        acc += v[c]*v[c];                 // order c0,c1,c2 (matches jnp.sum over axis=1)
    }
    d_P4[t] = make_float4(v[0], v[1], v[2], acc);
}

// order-preserving float -> uint key (monotone, exact)
__device__ __forceinline__ unsigned fkey(float f) {
    unsigned u = __float_as_uint(f);
    return (u & 0x80000000u) ? ~u : (u | 0x80000000u);
}

// ---------------- knn: warp per row, register top-20 + redux merge ----------------
__global__ void __launch_bounds__(256) k_knn() {
    __shared__ float4 sP[NPT];           // 32 KB
    int b = blockIdx.x >> 5;             // 8 batches
    int chunk = blockIdx.x & 31;         // 32 chunks of 64 rows
    for (int i = threadIdx.x; i < NPT; i += 256)
        sP[i] = d_P4[b*NPT + i];
    __syncthreads();

    int warp = threadIdx.x >> 5, lane = threadIdx.x & 31;
    for (int r = 0; r < 8; r++) {
        int n = chunk*64 + warp*8 + r;
        float4 q = sP[n];
        float qx = q.x, qy = q.y, qz = q.z, qxx = q.w;

        float v[KNN]; int id[KNN];
        #pragma unroll
        for (int j = 0; j < KNN; j++) { v[j] = -FLT_MAX; id[j] = 0x7fffffff; }

        for (int m = lane; m < NPT; m += 32) {
            float4 pm = sP[m];
            float dot = qx*pm.x + qy*pm.y + qz*pm.z;
            // pd = (-xx_n) - (-2*dot) - xx_m
            float pd = (-qxx + 2.f*dot) - pm.w;
            if (pd > v[KNN-1]) {
                v[KNN-1] = pd; id[KNN-1] = m;
                // one bubble pass restores sorted order; strict > keeps stability
                #pragma unroll
                for (int j = KNN-1; j > 0; j--) {
                    if (v[j] > v[j-1]) {
                        float tv = v[j]; v[j] = v[j-1]; v[j-1] = tv;
                        int   ti = id[j]; id[j] = id[j-1]; id[j-1] = ti;
                    }
                }
            }
        }
        // merge: 20 rounds of warp argmax over heads (value desc, index asc)
        int pg = b*NPT + n;
        #pragma unroll 1
        for (int k = 0; k < KNN; k++) {
            unsigned mykey = fkey(v[0]);
            unsigned best = __reduce_max_sync(0xffffffffu, mykey);
            int cand = (mykey == best) ? id[0] : 0x7fffffff;
            int bmi = __reduce_min_sync(0xffffffffu, cand);
            if (mykey == best && id[0] == bmi) {
                // pop my head: shift left (static indices, registers)
                #pragma unroll
                for (int j = 0; j < KNN-1; j++) { v[j] = v[j+1]; id[j] = id[j+1]; }
                v[KNN-1] = -FLT_MAX; id[KNN-1] = 0x7fffffff;
            }
            if (lane == 0) {
                int qg = b*NPT + bmi;
                d_nbr[pg*KNN + k] = qg;
                atomicAdd(&d_deg[qg], 1);
            }
        }
    }
}

// exclusive scan of 16384 degrees (single block)
__global__ void k_scan() {
    int t = threadIdx.x;
    int base = t*16;
    int loc[16]; int s = 0;
    #pragma unroll
    for (int i = 0; i < 16; i++) { loc[i] = s; s += d_deg[base+i]; }
    int lane = t & 31, wid = t >> 5;
    int vv = s;
    #pragma unroll
    for (int o = 1; o < 32; o <<= 1) { int u = __shfl_up_sync(0xffffffffu, vv, o); if (lane >= o) vv += u; }
    __shared__ int ws[32];
    if (lane == 31) ws[wid] = vv;
    __syncthreads();
    if (wid == 0) {
        int w = ws[lane];
        #pragma unroll
        for (int o = 1; o < 32; o <<= 1) { int u = __shfl_up_sync(0xffffffffu, w, o); if (lane >= o) w += u; }
        ws[lane] = w;
    }
    __syncthreads();
    int excl = vv - s + (wid ? ws[wid-1] : 0);
    #pragma unroll
    for (int i = 0; i < 16; i++) { int rs = excl + loc[i]; d_rowstart[base+i] = rs; d_cursor[base+i] = rs; }
    if (t == 1023) d_rowstart[BNP] = excl + s;
}

__global__ void k_fill() {
    int p = blockIdx.x*256 + threadIdx.x;
    if (p >= BNP) return;
    #pragma unroll
    for (int k = 0; k < KNN; k++) {
        int q = d_nbr[p*KNN + k];
        int pos = atomicAdd(&d_cursor[q], 1);
        d_rev[pos] = p;
    }
}

// ---------------- layer 0: support = flat@w0 ; rz = flat@wr + br ----------------
__global__ void k_l0mm(const float* __restrict__ x, const float* __restrict__ w0,
                       const float* __restrict__ wr, const float* __restrict__ br) {
    int t = blockIdx.x*256 + threadIdx.x;   // BNP*CH threads
    int p = t >> 6, c = t & 63;
    int b = p >> 11, n = p & 2047;
    const float* xb = x + b*3*NPT;
    float x0 = xb[n], x1 = xb[NPT + n], x2 = xb[2*NPT + n];
    d_sup[t] = x0*w0[c] + x1*w0[64+c] + x2*w0[128+c];
    d_rz[t]  = x0*wr[c] + x1*wr[64+c] + x2*wr[128+c] + br[c];
}

// ---------------- support = h @ W (64x64), h = d_F + off (ld=256) ----------------
__global__ void k_mm64(int off, const float* __restrict__ Wl) {
    __shared__ float Ws[64*64];
    __shared__ float Hs[64*64];
    int tid = threadIdx.x;
    int p0 = blockIdx.x*64;
    for (int i = tid; i < 4096; i += 256) Ws[i] = Wl[i];
    for (int i = tid; i < 4096; i += 256) {
        int r = i >> 6, k = i & 63;
        Hs[i] = d_F[(p0 + r)*FD + off + k];
    }
    __syncthreads();
    int c = tid & 63, rr = tid >> 6;
    for (int r = rr; r < 64; r += 4) {
        float acc = 0.f;
        #pragma unroll 16
        for (int k = 0; k < 64; k++) acc += Hs[r*64 + k] * Ws[k*64 + c];
        d_sup[(p0 + r)*64 + c] = acc;
    }
}

// ---------------- gather (reverse CSR) + bias ----------------
__global__ void k_gather(const float* __restrict__ bias) {
    int t = threadIdx.x;
    int q = blockIdx.x*4 + (t >> 6);
    int c = t & 63;
    float acc = bias[c];
    int s0 = d_rowstart[q], e0 = d_rowstart[q+1];
    for (int i = s0; i < e0; i++) acc += d_sup[d_rev[i]*64 + c];
    d_z[q*64 + c] = acc;
}

// ---------------- per-channel stats (sum, sumsq) ----------------
__global__ void k_colstats(int which) {  // 0: d_z->A, 1: d_rz->B
    const float* Z = which ? d_rz : d_z;
    int tid = threadIdx.x;
    int c = tid & 63, g = tid >> 6;
    int r0 = blockIdx.x*256;
    float s = 0.f, s2 = 0.f;
    for (int r = g; r < 256; r += 4) {
        float v = Z[(r0 + r)*64 + c];
        s += v; s2 += v*v;
    }
    __shared__ float sh[256], sh2[256];
    sh[tid] = s; sh2[tid] = s2;
    __syncthreads();
    if (g == 0) {
        s  = sh[c] + sh[64+c] + sh[128+c] + sh[192+c];
        s2 = sh2[c] + sh2[64+c] + sh2[128+c] + sh2[192+c];
        if (which) { atomicAdd(&d_sumB[c], s); atomicAdd(&d_sqB[c], s2); }
        else       { atomicAdd(&d_sumA[c], s); atomicAdd(&d_sqA[c], s2); }
    }
}

// ---------------- layer 0 post: h = relu(relu(bn(z)) + bn(rz)) ----------------
__global__ void k_l0post(const float* __restrict__ g0, const float* __restrict__ be0,
                         const float* __restrict__ gr, const float* __restrict__ ber) {
    int t = blockIdx.x*256 + threadIdx.x;
    int p = t >> 6, c = t & 63;
    float mA = d_sumA[c]*(1.f/BNP);
    float vA = d_sqA[c]*(1.f/BNP) - mA*mA;
    float o = (d_z[t] - mA)*rsqrtf(vA + 1e-5f)*g0[c] + be0[c];
    o = fmaxf(o, 0.f);
    float mB = d_sumB[c]*(1.f/BNP);
    float vB = d_sqB[c]*(1.f/BNP) - mB*mB;
    float r = (d_rz[t] - mB)*rsqrtf(vB + 1e-5f)*gr[c] + ber[c];
    d_F[p*FD + c] = fmaxf(o + r, 0.f);
}

// ---------------- layers 1..3 post: h = relu(relu(bn(z)) + h_prev) ----------------
__global__ void k_lpost(int layer, const float* __restrict__ G, const float* __restrict__ Be) {
    int t = blockIdx.x*256 + threadIdx.x;
    int p = t >> 6, c = t & 63;
    float m = d_sumA[c]*(1.f/BNP);
    float var = d_sqA[c]*(1.f/BNP) - m*m;
    float a = (d_z[t] - m)*rsqrtf(var + 1e-5f)*G[c] + Be[c];
    a = fmaxf(a, 0.f);
    float hp = d_F[p*FD + (layer-1)*64 + c];
    d_F[p*FD + layer*64 + c] = fmaxf(a + hp, 0.f);
}

// ---------------- conv GEMM: Y[e][p] = wconv[e,:] . F[p,:]  (1024 x 16384 x 256) ----------------
__global__ void __launch_bounds__(256) k_conv(const float* __restrict__ A) {
    __shared__ float As[16*128];
    __shared__ float Bs[16*128];
    int t = threadIdx.x;
    int tx = t & 15, ty = t >> 4;
    int bn = blockIdx.x;       // 0..127  (p tiles)
    int bm = blockIdx.y;       // 0..7    (e tiles)
    const float* Ag = A + bm*128*256;
    const float* Bg = d_F + bn*128*256;
    float acc[8][8];
    #pragma unroll
    for (int i = 0; i < 8; i++)
        #pragma unroll
        for (int j = 0; j < 8; j++) acc[i][j] = 0.f;

    for (int k0 = 0; k0 < 256; k0 += 16) {
        #pragma unroll
        for (int l = 0; l < 2; l++) {
            int lin = t + l*256;
            int row = lin >> 2, kq = lin & 3;
            float4 va = *(const float4*)(Ag + row*256 + k0 + kq*4);
            As[(kq*4+0)*128 + row] = va.x; As[(kq*4+1)*128 + row] = va.y;
            As[(kq*4+2)*128 + row] = va.z; As[(kq*4+3)*128 + row] = va.w;
            float4 vb = *(const float4*)(Bg + row*256 + k0 + kq*4);
            Bs[(kq*4+0)*128 + row] = vb.x; Bs[(kq*4+1)*128 + row] = vb.y;
            Bs[(kq*4+2)*128 + row] = vb.z; Bs[(kq*4+3)*128 + row] = vb.w;
        }
        __syncthreads();
        #pragma unroll
        for (int kk = 0; kk < 16; kk++) {
            float a[8], b[8];
            float4 a0 = *(const float4*)&As[kk*128 + ty*8];
            float4 a1 = *(const float4*)&As[kk*128 + ty*8 + 4];
            a[0]=a0.x; a[1]=a0.y; a[2]=a0.z; a[3]=a0.w; a[4]=a1.x; a[5]=a1.y; a[6]=a1.z; a[7]=a1.w;
            float4 b0 = *(const float4*)&Bs[kk*128 + tx*8];
            float4 b1 = *(const float4*)&Bs[kk*128 + tx*8 + 4];
            b[0]=b0.x; b[1]=b0.y; b[2]=b0.z; b[3]=b0.w; b[4]=b1.x; b[5]=b1.y; b[6]=b1.z; b[7]=b1.w;
            #pragma unroll
            for (int i = 0; i < 8; i++)
                #pragma unroll
                for (int j = 0; j < 8; j++) acc[i][j] += a[i]*b[j];
        }
        __syncthreads();
    }
    #pragma unroll
    for (int i = 0; i < 8; i++) {
        size_t base = (size_t)(bm*128 + ty*8 + i)*BNP + bn*128 + tx*8;
        *(float4*)&d_Y[base]     = make_float4(acc[i][0], acc[i][1], acc[i][2], acc[i][3]);
        *(float4*)&d_Y[base + 4] = make_float4(acc[i][4], acc[i][5], acc[i][6], acc[i][7]);
    }
}

// ---------------- conv BN + leaky + per-batch max/mean pooling ----------------
__global__ void k_reduce(const float* __restrict__ gf, const float* __restrict__ bef) {
    int e = blockIdx.x;
    const float* y = d_Y + (size_t)e*BNP;
    int t = threadIdx.x;
    float s = 0.f, s2 = 0.f;
    for (int p = t; p < BNP; p += 256) { float v = y[p]; s += v; s2 += v*v; }
    __shared__ float r1[256], r2[256];
    r1[t] = s; r2[t] = s2;
    __syncthreads();
    for (int o = 128; o; o >>= 1) { if (t < o) { r1[t] += r1[t+o]; r2[t] += r2[t+o]; } __syncthreads(); }
    __shared__ float smu, srs;
    if (t == 0) {
        float mu = r1[0]*(1.f/BNP);
        float var = r2[0]*(1.f/BNP) - mu*mu;
        smu = mu; srs = rsqrtf(var + 1e-5f);
    }
    __syncthreads();
    float mu = smu, sc = srs*gf[e], sh = bef[e];
    for (int b = 0; b < BB; b++) {
        float mx = -FLT_MAX, sm = 0.f;
        for (int j = t; j < NPT; j += 256) {
            float v = y[b*NPT + j];
            v = (v - mu)*sc + sh;
            v = v > 0.f ? v : 0.2f*v;
            mx = fmaxf(mx, v); sm += v;
        }
        r1[t] = mx; r2[t] = sm;
        __syncthreads();
        for (int o = 128; o; o >>= 1) { if (t < o) { r1[t] = fmaxf(r1[t], r1[t+o]); r2[t] += r2[t+o]; } __syncthreads(); }
        if (t == 0) {
            d_x12[b*2*EMB + e] = r1[0];
            d_x12[b*2*EMB + EMB + e] = r2[0]*(1.f/NPT);
        }
        __syncthreads();
    }
}

// ---------------- head ----------------
__global__ void k_head1(const float* __restrict__ w1, const float* __restrict__ g6,
                        const float* __restrict__ b6) {
    // grid 8 blocks x 256 threads; 64 j's per block, 4-way k-split
    int jl = threadIdx.x & 63, ks = threadIdx.x >> 6;
    int j = blockIdx.x*64 + jl;
    float acc[BB];
    #pragma unroll
    for (int b = 0; b < BB; b++) acc[b] = 0.f;
    for (int k = ks*512; k < ks*512 + 512; k++) {
        float wv = w1[k*512 + j];
        #pragma unroll
        for (int b = 0; b < BB; b++) acc[b] += d_x12[b*2*EMB + k]*wv;
    }
    __shared__ float sh[4][64][BB];
    #pragma unroll
    for (int b = 0; b < BB; b++) sh[ks][jl][b] = acc[b];
    __syncthreads();
    if (ks == 0) {
        #pragma unroll
        for (int b = 0; b < BB; b++)
            acc[b] = sh[0][jl][b] + sh[1][jl][b] + sh[2][jl][b] + sh[3][jl][b];
        float m = 0.f;
        #pragma unroll
        for (int b = 0; b < BB; b++) m += acc[b];
        m *= (1.f/BB);
        float var = 0.f;
        #pragma unroll
        for (int b = 0; b < BB; b++) { float d = acc[b]-m; var += d*d; }
        var *= (1.f/BB);
        float sc = rsqrtf(var + 1e-5f)*g6[j], bb = b6[j];
        #pragma unroll
        for (int b = 0; b < BB; b++) {
            float o = (acc[b]-m)*sc + bb;
            d_h512[b*512 + j] = o > 0.f ? o : 0.2f*o;
        }
    }
}

__global__ void k_head2(const float* __restrict__ w2, const float* __restrict__ b2,
                        const float* __restrict__ g7, const float* __restrict__ b7) {
    int j = threadIdx.x;   // 256
    float acc[BB];
    #pragma unroll
    for (int b = 0; b < BB; b++) acc[b] = 0.f;
    for (int k = 0; k < 512; k++) {
        float wv = w2[k*256 + j];
        #pragma unroll
        for (int b = 0; b < BB; b++) acc[b] += d_h512[b*512 + k]*wv;
    }
    #pragma unroll
    for (int b = 0; b < BB; b++) acc[b] += b2[j];
    float m = 0.f;
    #pragma unroll
    for (int b = 0; b < BB; b++) m += acc[b];
    m *= (1.f/BB);
    float var = 0.f;
    #pragma unroll
    for (int b = 0; b < BB; b++) { float d = acc[b]-m; var += d*d; }
    var *= (1.f/BB);
    float sc = rsqrtf(var + 1e-5f)*g7[j], bb = b7[j];
    #pragma unroll
    for (int b = 0; b < BB; b++) {
        float o = (acc[b]-m)*sc + bb;
        d_h256[b*256 + j] = o > 0.f ? o : 0.2f*o;
    }
}

__global__ void k_head3(const float* __restrict__ w3, const float* __restrict__ b3,
                        float* __restrict__ out) {
    int t = threadIdx.x;
    if (t >= BB*40) return;
    int b = t / 40, j = t % 40;
    float acc = b3[j];
    for (int k = 0; k < 256; k++) acc += d_h256[b*256 + k]*w3[k*40 + j];
    out[b*40 + j] = acc;
}

// ---------------- launch ----------------
extern "C" void kernel_launch(void* const* d_in, const int* in_sizes, int n_in,
                              void* d_out, int out_size) {
    const float* x     = (const float*)d_in[0];
    const float* w0    = (const float*)d_in[1];
    const float* b0    = (const float*)d_in[2];
    const float* g0    = (const float*)d_in[3];
    const float* be0   = (const float*)d_in[4];
    const float* wr    = (const float*)d_in[5];
    const float* br    = (const float*)d_in[6];
    const float* gr    = (const float*)d_in[7];
    const float* ber   = (const float*)d_in[8];
    const float* W     = (const float*)d_in[9];
    const float* Bv    = (const float*)d_in[10];
    const float* G     = (const float*)d_in[11];
    const float* Be    = (const float*)d_in[12];
    const float* wconv = (const float*)d_in[13];
    const float* gf    = (const float*)d_in[14];
    const float* bef   = (const float*)d_in[15];
    const float* w1    = (const float*)d_in[16];
    const float* g6    = (const float*)d_in[17];
    const float* b6    = (const float*)d_in[18];
    const float* w2    = (const float*)d_in[19];
    const float* b2    = (const float*)d_in[20];
    const float* g7    = (const float*)d_in[21];
    const float* b7    = (const float*)d_in[22];
    const float* w3    = (const float*)d_in[23];
    const float* b3    = (const float*)d_in[24];
    float* out = (float*)d_out;

    // graph build
    k_zero_deg<<<64, 256>>>();
    k_prep<<<64, 256>>>(x);
    k_knn<<<256, 256>>>();
    k_scan<<<1, 1024>>>();
    k_fill<<<64, 256>>>();

    // layer 0
    k_l0mm<<<4096, 256>>>(x, w0, wr, br);
    k_gather<<<4096, 256>>>(b0);
    k_zero_stats<<<1, 64>>>(1);
    k_colstats<<<64, 256>>>(0);
    k_colstats<<<64, 256>>>(1);
    k_l0post<<<4096, 256>>>(g0, be0, gr, ber);

    // layers 1..3
    for (int i = 1; i < 4; i++) {
        k_mm64<<<256, 256>>>((i-1)*64, W + (size_t)(i-1)*64*64);
        k_gather<<<4096, 256>>>(Bv + (i-1)*64);
        k_zero_stats<<<1, 64>>>(0);
        k_colstats<<<64, 256>>>(0);
        k_lpost<<<4096, 256>>>(i, G + (i-1)*64, Be + (i-1)*64);
    }

    // conv 256 -> 1024 + BN + leaky + pool
    dim3 cgrid(128, 8);
    k_conv<<<cgrid, 256>>>(wconv);
    k_reduce<<<1024, 256>>>(gf, bef);

    // head
    k_head1<<<8, 256>>>(w1, g6, b6);
    k_head2<<<1, 256>>>(w2, b2, g7, b7);
    k_head3<<<1, 320>>>(w3, b3, out);
}

// round 4
// speedup vs baseline: 4.9106x; 1.1165x over previous
#include <cuda_runtime.h>
#include <cuda_bf16.h>
#include <float.h>
#include <stdint.h>

// ---------------- problem constants ----------------
#define BB    8
#define NPT   2048
#define BNP   16384          // BB*NPT
#define KNN   20
#define CH    64
#define FD    256            // 4*CH
#define EMB   1024

// ---------------- scratch (device globals; no mallocs allowed) ----------------
__device__ float4 d_P4[BB*NPT];        // scrambled pts + sqnorm, [b][n] = (x,y,z,xx)
__device__ int   d_nbr[BNP*KNN];       // forward knn (global q indices)
__device__ int   d_deg[BNP];
__device__ int   d_rowstart[BNP+1];
__device__ int   d_cursor[BNP];
__device__ int   d_rev[BNP*KNN];       // reverse CSR payload (source p per in-edge)
__device__ float d_F[BNP*FD];          // concat features (h0..h3), row-major 256
__device__ float d_sup[BNP*CH];        // support = h @ W
__device__ float d_z[BNP*CH];          // gathered pre-BN
__device__ float d_rz[BNP*CH];         // layer0 residual pre-BN
__device__ float d_Y[(size_t)EMB*BNP]; // conv output [e][p], 64 MB
__device__ float d_x12[BB*2*EMB];      // pooled features (B, 2048)
__device__ float d_h512[BB*512];
__device__ float d_h256[BB*256];
__device__ float d_sumA[CH], d_sqA[CH], d_sumB[CH], d_sqB[CH];
// bf16 hi/lo operand splits for the tensor-core conv GEMM
__device__ __nv_bfloat16 d_Ahi[EMB*FD], d_Alo[EMB*FD];
__device__ __nv_bfloat16 d_Fhi[BNP*FD], d_Flo[BNP*FD];

// ---------------- warp-MMA helpers (sm_80+ baseline PTX, valid on sm_100) ----
__device__ __forceinline__ uint32_t smem_u32(const void* p) {
    uint32_t a;
    asm("{ .reg .u64 t; cvta.to.shared.u64 t, %1; cvt.u32.u64 %0, t; }" : "=r"(a) : "l"(p));
    return a;
}
__device__ __forceinline__ void ldm_x4(uint32_t* r, uint32_t addr) {
    asm volatile("ldmatrix.sync.aligned.m8n8.x4.shared.b16 {%0,%1,%2,%3}, [%4];"
        : "=r"(r[0]), "=r"(r[1]), "=r"(r[2]), "=r"(r[3]) : "r"(addr));
}
__device__ __forceinline__ void mma16816(float* c, const uint32_t* a, const uint32_t* b) {
    asm volatile(
        "mma.sync.aligned.m16n8k16.row.col.f32.bf16.bf16.f32 "
        "{%0,%1,%2,%3}, {%4,%5,%6,%7}, {%8,%9}, {%0,%1,%2,%3};"
        : "+f"(c[0]), "+f"(c[1]), "+f"(c[2]), "+f"(c[3])
        : "r"(a[0]), "r"(a[1]), "r"(a[2]), "r"(a[3]), "r"(b[0]), "r"(b[1]));
}

// ---------------- init / prep ----------------
__global__ void k_zero_deg() {
    int t = blockIdx.x*256 + threadIdx.x;
    if (t < BNP) d_deg[t] = 0;
}

__global__ void k_zero_stats(int both) {
    int t = threadIdx.x;
    if (t < CH) {
        d_sumA[t] = 0.f; d_sqA[t] = 0.f;
        if (both) { d_sumB[t] = 0.f; d_sqB[t] = 0.f; }
    }
}

// pts[b,c,n] = x[b, (c*N+n)%3, (c*N+n)/3]  (faithful to the torch view bug)
__global__ void k_prep(const float* __restrict__ x) {
    int t = blockIdx.x*256 + threadIdx.x;
    if (t >= BNP) return;
    int b = t >> 11, n = t & 2047;
    const float* xb = x + b*3*NPT;
    float v[3]; float acc = 0.f;
    #pragma unroll
    for (int c = 0; c < 3; c++) {
        int L = c*NPT + n;
        v[c] = xb[(L % 3)*NPT + (L / 3)];
        acc += v[c]*v[c];
    }
    d_P4[t] = make_float4(v[0], v[1], v[2], acc);
}

// order-preserving float -> uint key (monotone, exact)
__device__ __forceinline__ unsigned fkey(float f) {
    unsigned u = __float_as_uint(f);
    return (u & 0x80000000u) ? ~u : (u | 0x80000000u);
}

// ---------------- knn: warp per row, register top-20 + redux merge ----------------
__global__ void __launch_bounds__(256) k_knn() {
    __shared__ float4 sP[NPT];           // 32 KB
    int b = blockIdx.x >> 5;
    int chunk = blockIdx.x & 31;
    for (int i = threadIdx.x; i < NPT; i += 256)
        sP[i] = d_P4[b*NPT + i];
    __syncthreads();

    int warp = threadIdx.x >> 5, lane = threadIdx.x & 31;
    for (int r = 0; r < 8; r++) {
        int n = chunk*64 + warp*8 + r;
        float4 q = sP[n];
        float qx = q.x, qy = q.y, qz = q.z, qxx = q.w;

        float v[KNN]; int id[KNN];
        #pragma unroll
        for (int j = 0; j < KNN; j++) { v[j] = -FLT_MAX; id[j] = 0x7fffffff; }

        for (int m = lane; m < NPT; m += 32) {
            float4 pm = sP[m];
            float dot = qx*pm.x + qy*pm.y + qz*pm.z;
            float pd = (-qxx + 2.f*dot) - pm.w;
            if (pd > v[KNN-1]) {
                v[KNN-1] = pd; id[KNN-1] = m;
                #pragma unroll
                for (int j = KNN-1; j > 0; j--) {
                    if (v[j] > v[j-1]) {
                        float tv = v[j]; v[j] = v[j-1]; v[j-1] = tv;
                        int   ti = id[j]; id[j] = id[j-1]; id[j-1] = ti;
                    }
                }
            }
        }
        int pg = b*NPT + n;
        #pragma unroll 1
        for (int k = 0; k < KNN; k++) {
            unsigned mykey = fkey(v[0]);
            unsigned best = __reduce_max_sync(0xffffffffu, mykey);
            int cand = (mykey == best) ? id[0] : 0x7fffffff;
            int bmi = __reduce_min_sync(0xffffffffu, cand);
            if (mykey == best && id[0] == bmi) {
                #pragma unroll
                for (int j = 0; j < KNN-1; j++) { v[j] = v[j+1]; id[j] = id[j+1]; }
                v[KNN-1] = -FLT_MAX; id[KNN-1] = 0x7fffffff;
            }
            if (lane == 0) {
                int qg = b*NPT + bmi;
                d_nbr[pg*KNN + k] = qg;
                atomicAdd(&d_deg[qg], 1);
            }
        }
    }
}

// exclusive scan of 16384 degrees (single block)
__global__ void k_scan() {
    int t = threadIdx.x;
    int base = t*16;
    int loc[16]; int s = 0;
    #pragma unroll
    for (int i = 0; i < 16; i++) { loc[i] = s; s += d_deg[base+i]; }
    int lane = t & 31, wid = t >> 5;
    int vv = s;
    #pragma unroll
    for (int o = 1; o < 32; o <<= 1) { int u = __shfl_up_sync(0xffffffffu, vv, o); if (lane >= o) vv += u; }
    __shared__ int ws[32];
    if (lane == 31) ws[wid] = vv;
    __syncthreads();
    if (wid == 0) {
        int w = ws[lane];
        #pragma unroll
        for (int o = 1; o < 32; o <<= 1) { int u = __shfl_up_sync(0xffffffffu, w, o); if (lane >= o) w += u; }
        ws[lane] = w;
    }
    __syncthreads();
    int excl = vv - s + (wid ? ws[wid-1] : 0);
    #pragma unroll
    for (int i = 0; i < 16; i++) { int rs = excl + loc[i]; d_rowstart[base+i] = rs; d_cursor[base+i] = rs; }
    if (t == 1023) d_rowstart[BNP] = excl + s;
}

__global__ void k_fill() {
    int p = blockIdx.x*256 + threadIdx.x;
    if (p >= BNP) return;
    #pragma unroll
    for (int k = 0; k < KNN; k++) {
        int q = d_nbr[p*KNN + k];
        int pos = atomicAdd(&d_cursor[q], 1);
        d_rev[pos] = p;
    }
}

// ---------------- layer 0: support = flat@w0 ; rz = flat@wr + br ----------------
__global__ void k_l0mm(const float* __restrict__ x, const float* __restrict__ w0,
                       const float* __restrict__ wr, const float* __restrict__ br) {
    int t = blockIdx.x*256 + threadIdx.x;
    int p = t >> 6, c = t & 63;
    int b = p >> 11, n = p & 2047;
    const float* xb = x + b*3*NPT;
    float x0 = xb[n], x1 = xb[NPT + n], x2 = xb[2*NPT + n];
    d_sup[t] = x0*w0[c] + x1*w0[64+c] + x2*w0[128+c];
    d_rz[t]  = x0*wr[c] + x1*wr[64+c] + x2*wr[128+c] + br[c];
}

// ---------------- support = h @ W (64x64), h = d_F + off (ld=256) ----------------
__global__ void k_mm64(int off, const float* __restrict__ Wl) {
    __shared__ float Ws[64*64];
    __shared__ float Hs[64*64];
    int tid = threadIdx.x;
    int p0 = blockIdx.x*64;
    for (int i = tid; i < 4096; i += 256) Ws[i] = Wl[i];
    for (int i = tid; i < 4096; i += 256) {
        int r = i >> 6, k = i & 63;
        Hs[i] = d_F[(p0 + r)*FD + off + k];
    }
    __syncthreads();
    int c = tid & 63, rr = tid >> 6;
    for (int r = rr; r < 64; r += 4) {
        float acc = 0.f;
        #pragma unroll 16
        for (int k = 0; k < 64; k++) acc += Hs[r*64 + k] * Ws[k*64 + c];
        d_sup[(p0 + r)*64 + c] = acc;
    }
}

// ---------------- gather (reverse CSR) + bias ----------------
__global__ void k_gather(const float* __restrict__ bias) {
    int t = threadIdx.x;
    int q = blockIdx.x*4 + (t >> 6);
    int c = t & 63;
    float acc = bias[c];
    int s0 = d_rowstart[q], e0 = d_rowstart[q+1];
    for (int i = s0; i < e0; i++) acc += d_sup[d_rev[i]*64 + c];
    d_z[q*64 + c] = acc;
}

// ---------------- per-channel stats (sum, sumsq) ----------------
__global__ void k_colstats(int which) {
    const float* Z = which ? d_rz : d_z;
    int tid = threadIdx.x;
    int c = tid & 63, g = tid >> 6;
    int r0 = blockIdx.x*256;
    float s = 0.f, s2 = 0.f;
    for (int r = g; r < 256; r += 4) {
        float v = Z[(r0 + r)*64 + c];
        s += v; s2 += v*v;
    }
    __shared__ float sh[256], sh2[256];
    sh[tid] = s; sh2[tid] = s2;
    __syncthreads();
    if (g == 0) {
        s  = sh[c] + sh[64+c] + sh[128+c] + sh[192+c];
        s2 = sh2[c] + sh2[64+c] + sh2[128+c] + sh2[192+c];
        if (which) { atomicAdd(&d_sumB[c], s); atomicAdd(&d_sqB[c], s2); }
        else       { atomicAdd(&d_sumA[c], s); atomicAdd(&d_sqA[c], s2); }
    }
}

// ---------------- layer 0 post ----------------
__global__ void k_l0post(const float* __restrict__ g0, const float* __restrict__ be0,
                         const float* __restrict__ gr, const float* __restrict__ ber) {
    int t = blockIdx.x*256 + threadIdx.x;
    int p = t >> 6, c = t & 63;
    float mA = d_sumA[c]*(1.f/BNP);
    float vA = d_sqA[c]*(1.f/BNP) - mA*mA;
    float o = (d_z[t] - mA)*rsqrtf(vA + 1e-5f)*g0[c] + be0[c];
    o = fmaxf(o, 0.f);
    float mB = d_sumB[c]*(1.f/BNP);
    float vB = d_sqB[c]*(1.f/BNP) - mB*mB;
    float r = (d_rz[t] - mB)*rsqrtf(vB + 1e-5f)*gr[c] + ber[c];
    d_F[p*FD + c] = fmaxf(o + r, 0.f);
}

// ---------------- layers 1..3 post ----------------
__global__ void k_lpost(int layer, const float* __restrict__ G, const float* __restrict__ Be) {
    int t = blockIdx.x*256 + threadIdx.x;
    int p = t >> 6, c = t & 63;
    float m = d_sumA[c]*(1.f/BNP);
    float var = d_sqA[c]*(1.f/BNP) - m*m;
    float a = (d_z[t] - m)*rsqrtf(var + 1e-5f)*G[c] + Be[c];
    a = fmaxf(a, 0.f);
    float hp = d_F[p*FD + (layer-1)*64 + c];
    d_F[p*FD + layer*64 + c] = fmaxf(a + hp, 0.f);
}

// ---------------- bf16 hi/lo conversion ----------------
__global__ void k_cvtF() {
    int t = blockIdx.x*256 + threadIdx.x;     // < BNP*FD/4
    float4 x = ((const float4*)d_F)[t];
    __nv_bfloat16 h0 = __float2bfloat16(x.x), h1 = __float2bfloat16(x.y);
    __nv_bfloat16 h2 = __float2bfloat16(x.z), h3 = __float2bfloat16(x.w);
    __nv_bfloat16 l0 = __float2bfloat16(x.x - __bfloat162float(h0));
    __nv_bfloat16 l1 = __float2bfloat16(x.y - __bfloat162float(h1));
    __nv_bfloat16 l2 = __float2bfloat16(x.z - __bfloat162float(h2));
    __nv_bfloat16 l3 = __float2bfloat16(x.w - __bfloat162float(h3));
    ((__nv_bfloat162*)d_Fhi)[t*2]   = __nv_bfloat162(h0, h1);
    ((__nv_bfloat162*)d_Fhi)[t*2+1] = __nv_bfloat162(h2, h3);
    ((__nv_bfloat162*)d_Flo)[t*2]   = __nv_bfloat162(l0, l1);
    ((__nv_bfloat162*)d_Flo)[t*2+1] = __nv_bfloat162(l2, l3);
}

__global__ void k_cvtA(const float* __restrict__ w) {
    int t = blockIdx.x*256 + threadIdx.x;     // < EMB*FD/4
    float4 x = ((const float4*)w)[t];
    __nv_bfloat16 h0 = __float2bfloat16(x.x), h1 = __float2bfloat16(x.y);
    __nv_bfloat16 h2 = __float2bfloat16(x.z), h3 = __float2bfloat16(x.w);
    __nv_bfloat16 l0 = __float2bfloat16(x.x - __bfloat162float(h0));
    __nv_bfloat16 l1 = __float2bfloat16(x.y - __bfloat162float(h1));
    __nv_bfloat16 l2 = __float2bfloat16(x.z - __bfloat162float(h2));
    __nv_bfloat16 l3 = __float2bfloat16(x.w - __bfloat162float(h3));
    ((__nv_bfloat162*)d_Ahi)[t*2]   = __nv_bfloat162(h0, h1);
    ((__nv_bfloat162*)d_Ahi)[t*2+1] = __nv_bfloat162(h2, h3);
    ((__nv_bfloat162*)d_Alo)[t*2]   = __nv_bfloat162(l0, l1);
    ((__nv_bfloat162*)d_Alo)[t*2+1] = __nv_bfloat162(l2, l3);
}

// ---------------- conv GEMM via mma.sync (HMMA bf16, hi/lo split) -------------
// D[1024,16384] = A[1024,256] . F[16384,256]^T
// C = Ahi.Bhi + Ahi.Blo + Alo.Bhi  (fp32 accumulate)
// Block 128x128, 8 warps (2x4), warp tile 64x32. K chunked at 32 (8 chunks).
// Smem row pitch 80B: rows 0..7 hit disjoint 4-bank groups -> ldmatrix conflict-free.
#define PITCH 80
#define TSZ   (128*PITCH)

__global__ void __launch_bounds__(256) k_conv_mma() {
    __shared__ __align__(16) uint8_t sm[4*TSZ];
    uint8_t* sAhi = sm;
    uint8_t* sAlo = sm + TSZ;
    uint8_t* sBhi = sm + 2*TSZ;
    uint8_t* sBlo = sm + 3*TSZ;

    int tid = threadIdx.x, wid = tid >> 5, lane = tid & 31;
    int warp_m = wid >> 2, warp_n = wid & 3;
    int bn = blockIdx.x;   // 0..127 (p tiles)
    int bm = blockIdx.y;   // 0..7   (e tiles)

    const uint4* gAhi = (const uint4*)d_Ahi;
    const uint4* gAlo = (const uint4*)d_Alo;
    const uint4* gBhi = (const uint4*)d_Fhi;
    const uint4* gBlo = (const uint4*)d_Flo;

    float C[4][4][4];
    #pragma unroll
    for (int i = 0; i < 4; i++)
        #pragma unroll
        for (int j = 0; j < 4; j++)
            #pragma unroll
            for (int q = 0; q < 4; q++) C[i][j][q] = 0.f;

    // ldmatrix per-lane address components
    // A x4: lanes 0-7 rows m0..7 @k, 8-15 rows m8..15 @k, 16-23 rows m0..7 @k+8, 24-31 rows m8..15 @k+8
    int rowA  = warp_m*64 + (lane & 15);
    int halfA = lane >> 4;
    uint32_t aAhi = smem_u32(sAhi) + rowA*PITCH + halfA*16;
    uint32_t aAlo = smem_u32(sAlo) + rowA*PITCH + halfA*16;
    // B x4 over n16 x k16: lanes 0-7 rows n0..7 @k, 8-15 rows n0..7 @k+8,
    //                      16-23 rows n8..15 @k, 24-31 rows n8..15 @k+8
    int rowB  = warp_n*32 + (lane & 7) + ((lane >> 4) << 3);
    int halfB = (lane >> 3) & 1;
    uint32_t aBhi = smem_u32(sBhi) + rowB*PITCH + halfB*16;
    uint32_t aBlo = smem_u32(sBlo) + rowB*PITCH + halfB*16;

    for (int kc = 0; kc < 8; kc++) {
        __syncthreads();   // previous chunk consumed
        #pragma unroll
        for (int l = 0; l < 2; l++) {
            int i = tid + l*256;         // 0..511
            int row = i >> 2, c = i & 3;
            uint32_t so = row*PITCH + c*16;
            size_t ga = (size_t)(bm*128 + row)*32 + kc*4 + c;
            size_t gb = (size_t)(bn*128 + row)*32 + kc*4 + c;
            *(uint4*)(sAhi + so) = gAhi[ga];
            *(uint4*)(sAlo + so) = gAlo[ga];
            *(uint4*)(sBhi + so) = gBhi[gb];
            *(uint4*)(sBlo + so) = gBlo[gb];
        }
        __syncthreads();

        #pragma unroll
        for (int ksub = 0; ksub < 2; ksub++) {
            uint32_t koff = (ksub*2)*16;
            uint32_t bh[8], bl[8];
            ldm_x4(bh + 0, aBhi + koff);
            ldm_x4(bh + 4, aBhi + koff + 16*PITCH);
            ldm_x4(bl + 0, aBlo + koff);
            ldm_x4(bl + 4, aBlo + koff + 16*PITCH);
            #pragma unroll
            for (int mt = 0; mt < 4; mt++) {
                uint32_t ah[4], al[4];
                ldm_x4(ah, aAhi + koff + mt*16*PITCH);
                ldm_x4(al, aAlo + koff + mt*16*PITCH);
                #pragma unroll
                for (int nt = 0; nt < 4; nt++) {
                    const uint32_t* ph = &bh[(nt >> 1)*4 + (nt & 1)*2];
                    const uint32_t* pl = &bl[(nt >> 1)*4 + (nt & 1)*2];
                    mma16816(C[mt][nt], ah, ph);
                    mma16816(C[mt][nt], ah, pl);
                    mma16816(C[mt][nt], al, ph);
                }
            }
        }
    }

    // epilogue: C[mt][nt] -> d_Y.  c0,c1: row lane/4, cols (lane%4)*2+{0,1}; c2,c3: row+8
    #pragma unroll
    for (int mt = 0; mt < 4; mt++) {
        int m = bm*128 + warp_m*64 + mt*16 + (lane >> 2);
        #pragma unroll
        for (int nt = 0; nt < 4; nt++) {
            int p = bn*128 + warp_n*32 + nt*8 + (lane & 3)*2;
            *(float2*)&d_Y[(size_t)m*BNP + p]       = make_float2(C[mt][nt][0], C[mt][nt][1]);
            *(float2*)&d_Y[(size_t)(m + 8)*BNP + p] = make_float2(C[mt][nt][2], C[mt][nt][3]);
        }
    }
}

// ---------------- conv BN + leaky + per-batch max/mean pooling ----------------
__global__ void k_reduce(const float* __restrict__ gf, const float* __restrict__ bef) {
    int e = blockIdx.x;
    const float* y = d_Y + (size_t)e*BNP;
    int t = threadIdx.x;
    float s = 0.f, s2 = 0.f;
    for (int p = t; p < BNP; p += 256) { float v = y[p]; s += v; s2 += v*v; }
    __shared__ float r1[256], r2[256];
    r1[t] = s; r2[t] = s2;
    __syncthreads();
    for (int o = 128; o; o >>= 1) { if (t < o) { r1[t] += r1[t+o]; r2[t] += r2[t+o]; } __syncthreads(); }
    __shared__ float smu, srs;
    if (t == 0) {
        float mu = r1[0]*(1.f/BNP);
        float var = r2[0]*(1.f/BNP) - mu*mu;
        smu = mu; srs = rsqrtf(var + 1e-5f);
    }
    __syncthreads();
    float mu = smu, sc = srs*gf[e], sh = bef[e];
    for (int b = 0; b < BB; b++) {
        float mx = -FLT_MAX, sm = 0.f;
        for (int j = t; j < NPT; j += 256) {
            float v = y[b*NPT + j];
            v = (v - mu)*sc + sh;
            v = v > 0.f ? v : 0.2f*v;
            mx = fmaxf(mx, v); sm += v;
        }
        r1[t] = mx; r2[t] = sm;
        __syncthreads();
        for (int o = 128; o; o >>= 1) { if (t < o) { r1[t] = fmaxf(r1[t], r1[t+o]); r2[t] += r2[t+o]; } __syncthreads(); }
        if (t == 0) {
            d_x12[b*2*EMB + e] = r1[0];
            d_x12[b*2*EMB + EMB + e] = r2[0]*(1.f/NPT);
        }
        __syncthreads();
    }
}

// ---------------- head ----------------
__global__ void k_head1(const float* __restrict__ w1, const float* __restrict__ g6,
                        const float* __restrict__ b6) {
    int jl = threadIdx.x & 63, ks = threadIdx.x >> 6;
    int j = blockIdx.x*64 + jl;
    float acc[BB];
    #pragma unroll
    for (int b = 0; b < BB; b++) acc[b] = 0.f;
    for (int k = ks*512; k < ks*512 + 512; k++) {
        float wv = w1[k*512 + j];
        #pragma unroll
        for (int b = 0; b < BB; b++) acc[b] += d_x12[b*2*EMB + k]*wv;
    }
    __shared__ float sh[4][64][BB];
    #pragma unroll
    for (int b = 0; b < BB; b++) sh[ks][jl][b] = acc[b];
    __syncthreads();
    if (ks == 0) {
        #pragma unroll
        for (int b = 0; b < BB; b++)
            acc[b] = sh[0][jl][b] + sh[1][jl][b] + sh[2][jl][b] + sh[3][jl][b];
        float m = 0.f;
        #pragma unroll
        for (int b = 0; b < BB; b++) m += acc[b];
        m *= (1.f/BB);
        float var = 0.f;
        #pragma unroll
        for (int b = 0; b < BB; b++) { float d = acc[b]-m; var += d*d; }
        var *= (1.f/BB);
        float sc = rsqrtf(var + 1e-5f)*g6[j], bb = b6[j];
        #pragma unroll
        for (int b = 0; b < BB; b++) {
            float o = (acc[b]-m)*sc + bb;
            d_h512[b*512 + j] = o > 0.f ? o : 0.2f*o;
        }
    }
}

__global__ void k_head2(const float* __restrict__ w2, const float* __restrict__ b2,
                        const float* __restrict__ g7, const float* __restrict__ b7) {
    int j = threadIdx.x;
    float acc[BB];
    #pragma unroll
    for (int b = 0; b < BB; b++) acc[b] = 0.f;
    for (int k = 0; k < 512; k++) {
        float wv = w2[k*256 + j];
        #pragma unroll
        for (int b = 0; b < BB; b++) acc[b] += d_h512[b*512 + k]*wv;
    }
    #pragma unroll
    for (int b = 0; b < BB; b++) acc[b] += b2[j];
    float m = 0.f;
    #pragma unroll
    for (int b = 0; b < BB; b++) m += acc[b];
    m *= (1.f/BB);
    float var = 0.f;
    #pragma unroll
    for (int b = 0; b < BB; b++) { float d = acc[b]-m; var += d*d; }
    var *= (1.f/BB);
    float sc = rsqrtf(var + 1e-5f)*g7[j], bb = b7[j];
    #pragma unroll
    for (int b = 0; b < BB; b++) {
        float o = (acc[b]-m)*sc + bb;
        d_h256[b*256 + j] = o > 0.f ? o : 0.2f*o;
    }
}

__global__ void k_head3(const float* __restrict__ w3, const float* __restrict__ b3,
                        float* __restrict__ out) {
    int t = threadIdx.x;
    if (t >= BB*40) return;
    int b = t / 40, j = t % 40;
    float acc = b3[j];
    for (int k = 0; k < 256; k++) acc += d_h256[b*256 + k]*w3[k*40 + j];
    out[b*40 + j] = acc;
}

// ---------------- launch ----------------
extern "C" void kernel_launch(void* const* d_in, const int* in_sizes, int n_in,
                              void* d_out, int out_size) {
    const float* x     = (const float*)d_in[0];
    const float* w0    = (const float*)d_in[1];
    const float* b0    = (const float*)d_in[2];
    const float* g0    = (const float*)d_in[3];
    const float* be0   = (const float*)d_in[4];
    const float* wr    = (const float*)d_in[5];
    const float* br    = (const float*)d_in[6];
    const float* gr    = (const float*)d_in[7];
    const float* ber   = (const float*)d_in[8];
    const float* W     = (const float*)d_in[9];
    const float* Bv    = (const float*)d_in[10];
    const float* G     = (const float*)d_in[11];
    const float* Be    = (const float*)d_in[12];
    const float* wconv = (const float*)d_in[13];
    const float* gf    = (const float*)d_in[14];
    const float* bef   = (const float*)d_in[15];
    const float* w1    = (const float*)d_in[16];
    const float* g6    = (const float*)d_in[17];
    const float* b6    = (const float*)d_in[18];
    const float* w2    = (const float*)d_in[19];
    const float* b2    = (const float*)d_in[20];
    const float* g7    = (const float*)d_in[21];
    const float* b7    = (const float*)d_in[22];
    const float* w3    = (const float*)d_in[23];
    const float* b3    = (const float*)d_in[24];
    float* out = (float*)d_out;

    // graph build
    k_zero_deg<<<64, 256>>>();
    k_prep<<<64, 256>>>(x);
    k_knn<<<256, 256>>>();
    k_scan<<<1, 1024>>>();
    k_fill<<<64, 256>>>();

    // layer 0
    k_l0mm<<<4096, 256>>>(x, w0, wr, br);
    k_gather<<<4096, 256>>>(b0);
    k_zero_stats<<<1, 64>>>(1);
    k_colstats<<<64, 256>>>(0);
    k_colstats<<<64, 256>>>(1);
    k_l0post<<<4096, 256>>>(g0, be0, gr, ber);

    // layers 1..3
    for (int i = 1; i < 4; i++) {
        k_mm64<<<256, 256>>>((i-1)*64, W + (size_t)(i-1)*64*64);
        k_gather<<<4096, 256>>>(Bv + (i-1)*64);
        k_zero_stats<<<1, 64>>>(0);
        k_colstats<<<64, 256>>>(0);
        k_lpost<<<4096, 256>>>(i, G + (i-1)*64, Be + (i-1)*64);
    }

    // conv 256 -> 1024 (mma.sync bf16 hi/lo split) + BN + leaky + pool
    k_cvtA<<<256, 256>>>(wconv);
    k_cvtF<<<4096, 256>>>();
    dim3 cgrid(128, 8);
    k_conv_mma<<<cgrid, 256>>>();
    k_reduce<<<1024, 256>>>(gf, bef);

    // head
    k_head1<<<8, 256>>>(w1, g6, b6);
    k_head2<<<1, 256>>>(w2, b2, g7, b7);
    k_head3<<<1, 320>>>(w3, b3, out);
}

// round 5
// speedup vs baseline: 6.4730x; 1.3182x over previous
#include <cuda_runtime.h>
#include <cuda_bf16.h>
#include <float.h>
#include <stdint.h>

// ---------------- problem constants ----------------
#define BB    8
#define NPT   2048
#define BNP   16384          // BB*NPT
#define KNN   20
#define CH    64
#define FD    256            // 4*CH
#define EMB   1024

// ---------------- scratch (device globals; no mallocs allowed) ----------------
__device__ float4 d_P4[BB*NPT];        // scrambled pts + sqnorm
__device__ int   d_nbr[BNP*KNN];
__device__ int   d_deg[BNP];
__device__ int   d_rowstart[BNP+1];
__device__ int   d_cursor[BNP];
__device__ int   d_rev[BNP*KNN];
__device__ float d_F[BNP*FD];          // concat features (h0..h3), row-major 256
__device__ float d_sup[BNP*CH];
__device__ float d_z[BNP*CH];
__device__ float d_rz[BNP*CH];
__device__ float d_Y[(size_t)EMB*BNP]; // conv output [e][p], 64 MB
__device__ float d_x12[BB*2*EMB];
__device__ float d_h512[BB*512];
__device__ float d_h256[BB*256];
__device__ float d_sumA[4*CH], d_sqA[4*CH];   // per-layer z stats
__device__ float d_sumB[CH], d_sqB[CH];       // layer0 residual stats
__device__ __nv_bfloat16 d_Ahi[EMB*FD], d_Alo[EMB*FD];
__device__ __nv_bfloat16 d_Fhi[BNP*FD], d_Flo[BNP*FD];

// ---------------- warp-MMA helpers (sm_80+ baseline PTX) ----------------
__device__ __forceinline__ uint32_t smem_u32(const void* p) {
    uint32_t a;
    asm("{ .reg .u64 t; cvta.to.shared.u64 t, %1; cvt.u32.u64 %0, t; }" : "=r"(a) : "l"(p));
    return a;
}
__device__ __forceinline__ void ldm_x4(uint32_t* r, uint32_t addr) {
    asm volatile("ldmatrix.sync.aligned.m8n8.x4.shared.b16 {%0,%1,%2,%3}, [%4];"
        : "=r"(r[0]), "=r"(r[1]), "=r"(r[2]), "=r"(r[3]) : "r"(addr));
}
__device__ __forceinline__ void mma16816(float* c, const uint32_t* a, const uint32_t* b) {
    asm volatile(
        "mma.sync.aligned.m16n8k16.row.col.f32.bf16.bf16.f32 "
        "{%0,%1,%2,%3}, {%4,%5,%6,%7}, {%8,%9}, {%0,%1,%2,%3};"
        : "+f"(c[0]), "+f"(c[1]), "+f"(c[2]), "+f"(c[3])
        : "r"(a[0]), "r"(a[1]), "r"(a[2]), "r"(a[3]), "r"(b[0]), "r"(b[1]));
}

// ---------------- init ----------------
__global__ void k_init() {
    int t = blockIdx.x*256 + threadIdx.x;
    if (t < BNP) d_deg[t] = 0;
    if (t < 4*CH) { d_sumA[t] = 0.f; d_sqA[t] = 0.f; }
    if (t < CH)   { d_sumB[t] = 0.f; d_sqB[t] = 0.f; }
}

// pts[b,c,n] = x[b, (c*N+n)%3, (c*N+n)/3]
__global__ void k_prep(const float* __restrict__ x) {
    int t = blockIdx.x*256 + threadIdx.x;
    if (t >= BNP) return;
    int b = t >> 11, n = t & 2047;
    const float* xb = x + b*3*NPT;
    float v[3]; float acc = 0.f;
    #pragma unroll
    for (int c = 0; c < 3; c++) {
        int L = c*NPT + n;
        v[c] = xb[(L % 3)*NPT + (L / 3)];
        acc += v[c]*v[c];
    }
    d_P4[t] = make_float4(v[0], v[1], v[2], acc);
}

__device__ __forceinline__ unsigned fkey(float f) {
    unsigned u = __float_as_uint(f);
    return (u & 0x80000000u) ? ~u : (u | 0x80000000u);
}

// ---------------- knn ----------------
__global__ void __launch_bounds__(256) k_knn() {
    __shared__ float4 sP[NPT];
    int b = blockIdx.x >> 5;
    int chunk = blockIdx.x & 31;
    for (int i = threadIdx.x; i < NPT; i += 256)
        sP[i] = d_P4[b*NPT + i];
    __syncthreads();

    int warp = threadIdx.x >> 5, lane = threadIdx.x & 31;
    for (int r = 0; r < 8; r++) {
        int n = chunk*64 + warp*8 + r;
        float4 q = sP[n];
        float qx = q.x, qy = q.y, qz = q.z, qxx = q.w;

        float v[KNN]; int id[KNN];
        #pragma unroll
        for (int j = 0; j < KNN; j++) { v[j] = -FLT_MAX; id[j] = 0x7fffffff; }

        for (int m = lane; m < NPT; m += 32) {
            float4 pm = sP[m];
            float dot = qx*pm.x + qy*pm.y + qz*pm.z;
            float pd = (-qxx + 2.f*dot) - pm.w;
            if (pd > v[KNN-1]) {
                v[KNN-1] = pd; id[KNN-1] = m;
                #pragma unroll
                for (int j = KNN-1; j > 0; j--) {
                    if (v[j] > v[j-1]) {
                        float tv = v[j]; v[j] = v[j-1]; v[j-1] = tv;
                        int   ti = id[j]; id[j] = id[j-1]; id[j-1] = ti;
                    }
                }
            }
        }
        int pg = b*NPT + n;
        #pragma unroll 1
        for (int k = 0; k < KNN; k++) {
            unsigned mykey = fkey(v[0]);
            unsigned best = __reduce_max_sync(0xffffffffu, mykey);
            int cand = (mykey == best) ? id[0] : 0x7fffffff;
            int bmi = __reduce_min_sync(0xffffffffu, cand);
            if (mykey == best && id[0] == bmi) {
                #pragma unroll
                for (int j = 0; j < KNN-1; j++) { v[j] = v[j+1]; id[j] = id[j+1]; }
                v[KNN-1] = -FLT_MAX; id[KNN-1] = 0x7fffffff;
            }
            if (lane == 0) {
                int qg = b*NPT + bmi;
                d_nbr[pg*KNN + k] = qg;
                atomicAdd(&d_deg[qg], 1);
            }
        }
    }
}

// exclusive scan of 16384 degrees (single block, int4 loads)
__global__ void k_scan() {
    int t = threadIdx.x;
    int loc[16]; int s = 0;
    const int4* dg4 = (const int4*)d_deg;
    int4 q[4];
    #pragma unroll
    for (int i = 0; i < 4; i++) q[i] = dg4[t*4 + i];
    const int* qq = (const int*)q;
    #pragma unroll
    for (int i = 0; i < 16; i++) { loc[i] = s; s += qq[i]; }
    int lane = t & 31, wid = t >> 5;
    int vv = s;
    #pragma unroll
    for (int o = 1; o < 32; o <<= 1) { int u = __shfl_up_sync(0xffffffffu, vv, o); if (lane >= o) vv += u; }
    __shared__ int ws[32];
    if (lane == 31) ws[wid] = vv;
    __syncthreads();
    if (wid == 0) {
        int w = ws[lane];
        #pragma unroll
        for (int o = 1; o < 32; o <<= 1) { int u = __shfl_up_sync(0xffffffffu, w, o); if (lane >= o) w += u; }
        ws[lane] = w;
    }
    __syncthreads();
    int excl = vv - s + (wid ? ws[wid-1] : 0);
    int base = t*16;
    #pragma unroll
    for (int i = 0; i < 16; i++) { int rs = excl + loc[i]; d_rowstart[base+i] = rs; d_cursor[base+i] = rs; }
    if (t == 1023) d_rowstart[BNP] = excl + s;
}

__global__ void k_fill() {
    int p = blockIdx.x*256 + threadIdx.x;
    if (p >= BNP) return;
    #pragma unroll
    for (int k = 0; k < KNN; k++) {
        int q = d_nbr[p*KNN + k];
        int pos = atomicAdd(&d_cursor[q], 1);
        d_rev[pos] = p;
    }
}

// ---------------- layer 0: sup0 = flat@w0 ; rz = flat@wr + br (+ rz stats) ----
__global__ void k_l0mm(const float* __restrict__ x, const float* __restrict__ w0,
                       const float* __restrict__ wr, const float* __restrict__ br) {
    int tid = threadIdx.x;
    int t = blockIdx.x*256 + tid;
    int p = t >> 6, c = t & 63;
    int b = p >> 11, n = p & 2047;
    const float* xb = x + b*3*NPT;
    float x0 = xb[n], x1 = xb[NPT + n], x2 = xb[2*NPT + n];
    d_sup[t] = x0*w0[c] + x1*w0[64+c] + x2*w0[128+c];
    float rz = x0*wr[c] + x1*wr[64+c] + x2*wr[128+c] + br[c];
    d_rz[t] = rz;
    __shared__ float s1[256], s2[256];
    s1[tid] = rz; s2[tid] = rz*rz;
    __syncthreads();
    if (tid < 64) {
        float a = s1[tid] + s1[64+tid] + s1[128+tid] + s1[192+tid];
        float q = s2[tid] + s2[64+tid] + s2[128+tid] + s2[192+tid];
        atomicAdd(&d_sumB[tid], a);
        atomicAdd(&d_sqB[tid], q);
    }
}

// ---------------- gather (reverse CSR) + bias + z stats ----------------
__global__ void k_gather_stats(const float* __restrict__ bias, int layer) {
    int t = threadIdx.x;
    int q = blockIdx.x*4 + (t >> 6);
    int c = t & 63;
    float acc = bias[c];
    int s0 = d_rowstart[q], e0 = d_rowstart[q+1];
    for (int i = s0; i < e0; i++) acc += d_sup[d_rev[i]*64 + c];
    d_z[q*64 + c] = acc;
    __shared__ float s1[256], s2[256];
    s1[t] = acc; s2[t] = acc*acc;
    __syncthreads();
    if (t < 64) {
        float a = s1[t] + s1[64+t] + s1[128+t] + s1[192+t];
        float qq = s2[t] + s2[64+t] + s2[128+t] + s2[192+t];
        atomicAdd(&d_sumA[layer*64 + t], a);
        atomicAdd(&d_sqA[layer*64 + t], qq);
    }
}

// ---------------- fused post (layer 0) + mm for layer 1 ----------------
__global__ void __launch_bounds__(256) k_post0_mm(
        const float* __restrict__ g0, const float* __restrict__ be0,
        const float* __restrict__ gr, const float* __restrict__ ber,
        const float* __restrict__ W1) {
    __shared__ float Hs[64*64];
    __shared__ float Ws[64*64];
    int tid = threadIdx.x;
    int p0 = blockIdx.x*64;
    int c = tid & 63, rg = tid >> 6;
    float mA = d_sumA[c]*(1.f/BNP);
    float vA = d_sqA[c]*(1.f/BNP) - mA*mA;
    float sA = rsqrtf(vA + 1e-5f)*g0[c], bA = be0[c];
    float mB = d_sumB[c]*(1.f/BNP);
    float vB = d_sqB[c]*(1.f/BNP) - mB*mB;
    float sB = rsqrtf(vB + 1e-5f)*gr[c], bB = ber[c];
    #pragma unroll
    for (int i = 0; i < 16; i++) {
        int r = rg + i*4, p = p0 + r;
        float o = fmaxf((d_z[p*64+c] - mA)*sA + bA, 0.f);
        float rr = (d_rz[p*64+c] - mB)*sB + bB;
        float h = fmaxf(o + rr, 0.f);
        Hs[r*64+c] = h;
        d_F[p*FD + c] = h;
        __nv_bfloat16 hi = __float2bfloat16(h);
        d_Fhi[p*FD + c] = hi;
        d_Flo[p*FD + c] = __float2bfloat16(h - __bfloat162float(hi));
    }
    for (int i = tid; i < 4096; i += 256) Ws[i] = W1[i];
    __syncthreads();
    for (int r = rg; r < 64; r += 4) {
        float acc = 0.f;
        #pragma unroll 16
        for (int k = 0; k < 64; k++) acc += Hs[r*64+k]*Ws[k*64+c];
        d_sup[(p0+r)*64+c] = acc;
    }
}

// ---------------- fused post (layers 1,2) + mm for next layer ----------------
__global__ void __launch_bounds__(256) k_postL_mm(int layer,
        const float* __restrict__ G, const float* __restrict__ Be,
        const float* __restrict__ Wn) {
    __shared__ float Hs[64*64];
    __shared__ float Ws[64*64];
    int tid = threadIdx.x;
    int p0 = blockIdx.x*64;
    int c = tid & 63, rg = tid >> 6;
    float m = d_sumA[layer*64+c]*(1.f/BNP);
    float v = d_sqA[layer*64+c]*(1.f/BNP) - m*m;
    float sc = rsqrtf(v + 1e-5f)*G[c], bc = Be[c];
    #pragma unroll
    for (int i = 0; i < 16; i++) {
        int r = rg + i*4, p = p0 + r;
        float a = fmaxf((d_z[p*64+c] - m)*sc + bc, 0.f);
        float h = fmaxf(a + d_F[p*FD + (layer-1)*64 + c], 0.f);
        Hs[r*64+c] = h;
        d_F[p*FD + layer*64 + c] = h;
        __nv_bfloat16 hi = __float2bfloat16(h);
        d_Fhi[p*FD + layer*64 + c] = hi;
        d_Flo[p*FD + layer*64 + c] = __float2bfloat16(h - __bfloat162float(hi));
    }
    for (int i = tid; i < 4096; i += 256) Ws[i] = Wn[i];
    __syncthreads();
    for (int r = rg; r < 64; r += 4) {
        float acc = 0.f;
        #pragma unroll 16
        for (int k = 0; k < 64; k++) acc += Hs[r*64+k]*Ws[k*64+c];
        d_sup[(p0+r)*64+c] = acc;
    }
}

// ---------------- post layer 3 (no mm; fp32 F slot not needed) ----------------
__global__ void k_post3(const float* __restrict__ G, const float* __restrict__ Be) {
    int t = blockIdx.x*256 + threadIdx.x;
    int p = t >> 6, c = t & 63;
    float m = d_sumA[3*64+c]*(1.f/BNP);
    float v = d_sqA[3*64+c]*(1.f/BNP) - m*m;
    float a = fmaxf((d_z[t] - m)*rsqrtf(v + 1e-5f)*G[c] + Be[c], 0.f);
    float h = fmaxf(a + d_F[p*FD + 2*64 + c], 0.f);
    __nv_bfloat16 hi = __float2bfloat16(h);
    d_Fhi[p*FD + 3*64 + c] = hi;
    d_Flo[p*FD + 3*64 + c] = __float2bfloat16(h - __bfloat162float(hi));
}

// ---------------- bf16 hi/lo conversion of wconv ----------------
__global__ void k_cvtA(const float* __restrict__ w) {
    int t = blockIdx.x*256 + threadIdx.x;
    float4 x = ((const float4*)w)[t];
    __nv_bfloat16 h0 = __float2bfloat16(x.x), h1 = __float2bfloat16(x.y);
    __nv_bfloat16 h2 = __float2bfloat16(x.z), h3 = __float2bfloat16(x.w);
    __nv_bfloat16 l0 = __float2bfloat16(x.x - __bfloat162float(h0));
    __nv_bfloat16 l1 = __float2bfloat16(x.y - __bfloat162float(h1));
    __nv_bfloat16 l2 = __float2bfloat16(x.z - __bfloat162float(h2));
    __nv_bfloat16 l3 = __float2bfloat16(x.w - __bfloat162float(h3));
    ((__nv_bfloat162*)d_Ahi)[t*2]   = __nv_bfloat162(h0, h1);
    ((__nv_bfloat162*)d_Ahi)[t*2+1] = __nv_bfloat162(h2, h3);
    ((__nv_bfloat162*)d_Alo)[t*2]   = __nv_bfloat162(l0, l1);
    ((__nv_bfloat162*)d_Alo)[t*2+1] = __nv_bfloat162(l2, l3);
}

// ---------------- conv GEMM via mma.sync (HMMA bf16, hi/lo split) -------------
#define PITCH 80
#define TSZ   (128*PITCH)

__global__ void __launch_bounds__(256) k_conv_mma() {
    __shared__ __align__(16) uint8_t sm[4*TSZ];
    uint8_t* sAhi = sm;
    uint8_t* sAlo = sm + TSZ;
    uint8_t* sBhi = sm + 2*TSZ;
    uint8_t* sBlo = sm + 3*TSZ;

    int tid = threadIdx.x, wid = tid >> 5, lane = tid & 31;
    int warp_m = wid >> 2, warp_n = wid & 3;
    int bn = blockIdx.x;
    int bm = blockIdx.y;

    const uint4* gAhi = (const uint4*)d_Ahi;
    const uint4* gAlo = (const uint4*)d_Alo;
    const uint4* gBhi = (const uint4*)d_Fhi;
    const uint4* gBlo = (const uint4*)d_Flo;

    float C[4][4][4];
    #pragma unroll
    for (int i = 0; i < 4; i++)
        #pragma unroll
        for (int j = 0; j < 4; j++)
            #pragma unroll
            for (int q = 0; q < 4; q++) C[i][j][q] = 0.f;

    int rowA  = warp_m*64 + (lane & 15);
    int halfA = lane >> 4;
    uint32_t aAhi = smem_u32(sAhi) + rowA*PITCH + halfA*16;
    uint32_t aAlo = smem_u32(sAlo) + rowA*PITCH + halfA*16;
    int rowB  = warp_n*32 + (lane & 7) + ((lane >> 4) << 3);
    int halfB = (lane >> 3) & 1;
    uint32_t aBhi = smem_u32(sBhi) + rowB*PITCH + halfB*16;
    uint32_t aBlo = smem_u32(sBlo) + rowB*PITCH + halfB*16;

    for (int kc = 0; kc < 8; kc++) {
        __syncthreads();
        #pragma unroll
        for (int l = 0; l < 2; l++) {
            int i = tid + l*256;
            int row = i >> 2, c = i & 3;
            uint32_t so = row*PITCH + c*16;
            size_t ga = (size_t)(bm*128 + row)*32 + kc*4 + c;
            size_t gb = (size_t)(bn*128 + row)*32 + kc*4 + c;
            *(uint4*)(sAhi + so) = gAhi[ga];
            *(uint4*)(sAlo + so) = gAlo[ga];
            *(uint4*)(sBhi + so) = gBhi[gb];
            *(uint4*)(sBlo + so) = gBlo[gb];
        }
        __syncthreads();

        #pragma unroll
        for (int ksub = 0; ksub < 2; ksub++) {
            uint32_t koff = (ksub*2)*16;
            uint32_t bh[8], bl[8];
            ldm_x4(bh + 0, aBhi + koff);
            ldm_x4(bh + 4, aBhi + koff + 16*PITCH);
            ldm_x4(bl + 0, aBlo + koff);
            ldm_x4(bl + 4, aBlo + koff + 16*PITCH);
            #pragma unroll
            for (int mt = 0; mt < 4; mt++) {
                uint32_t ah[4], al[4];
                ldm_x4(ah, aAhi + koff + mt*16*PITCH);
                ldm_x4(al, aAlo + koff + mt*16*PITCH);
                #pragma unroll
                for (int nt = 0; nt < 4; nt++) {
                    const uint32_t* ph = &bh[(nt >> 1)*4 + (nt & 1)*2];
                    const uint32_t* pl = &bl[(nt >> 1)*4 + (nt & 1)*2];
                    mma16816(C[mt][nt], ah, ph);
                    mma16816(C[mt][nt], ah, pl);
                    mma16816(C[mt][nt], al, ph);
                }
            }
        }
    }

    #pragma unroll
    for (int mt = 0; mt < 4; mt++) {
        int m = bm*128 + warp_m*64 + mt*16 + (lane >> 2);
        #pragma unroll
        for (int nt = 0; nt < 4; nt++) {
            int p = bn*128 + warp_n*32 + nt*8 + (lane & 3)*2;
            *(float2*)&d_Y[(size_t)m*BNP + p]       = make_float2(C[mt][nt][0], C[mt][nt][1]);
            *(float2*)&d_Y[(size_t)(m + 8)*BNP + p] = make_float2(C[mt][nt][2], C[mt][nt][3]);
        }
    }
}

// ---------------- conv BN + leaky + per-batch max/mean pooling ----------------
__global__ void k_reduce(const float* __restrict__ gf, const float* __restrict__ bef) {
    int e = blockIdx.x;
    const float* y = d_Y + (size_t)e*BNP;
    int t = threadIdx.x, lane = t & 31, w = t >> 5;
    float s = 0.f, s2 = 0.f;
    for (int p = t; p < BNP; p += 256) { float v = y[p]; s += v; s2 += v*v; }
    #pragma unroll
    for (int o = 16; o; o >>= 1) {
        s  += __shfl_xor_sync(0xffffffffu, s, o);
        s2 += __shfl_xor_sync(0xffffffffu, s2, o);
    }
    __shared__ float w1a[8], w2a[8];
    __shared__ float smu, srs;
    if (lane == 0) { w1a[w] = s; w2a[w] = s2; }
    __syncthreads();
    if (t == 0) {
        float S = 0.f, S2 = 0.f;
        #pragma unroll
        for (int i = 0; i < 8; i++) { S += w1a[i]; S2 += w2a[i]; }
        float mu = S*(1.f/BNP);
        float var = S2*(1.f/BNP) - mu*mu;
        smu = mu; srs = rsqrtf(var + 1e-5f);
    }
    __syncthreads();
    float mu = smu, sc = srs*gf[e], sh = bef[e];
    for (int b = 0; b < BB; b++) {
        float mx = -FLT_MAX, sm = 0.f;
        for (int j = t; j < NPT; j += 256) {
            float v = y[b*NPT + j];
            v = (v - mu)*sc + sh;
            v = v > 0.f ? v : 0.2f*v;
            mx = fmaxf(mx, v); sm += v;
        }
        #pragma unroll
        for (int o = 16; o; o >>= 1) {
            mx = fmaxf(mx, __shfl_xor_sync(0xffffffffu, mx, o));
            sm += __shfl_xor_sync(0xffffffffu, sm, o);
        }
        if (lane == 0) { w1a[w] = mx; w2a[w] = sm; }
        __syncthreads();
        if (t == 0) {
            float MX = w1a[0], SM = w2a[0];
            #pragma unroll
            for (int i = 1; i < 8; i++) { MX = fmaxf(MX, w1a[i]); SM += w2a[i]; }
            d_x12[b*2*EMB + e] = MX;
            d_x12[b*2*EMB + EMB + e] = SM*(1.f/NPT);
        }
        __syncthreads();
    }
}

// ---------------- head (k-split parallel) ----------------
__global__ void k_head1(const float* __restrict__ w1, const float* __restrict__ g6,
                        const float* __restrict__ b6) {
    // grid 32; 16 j per block; 16-way k-split of 128 each
    int jl = threadIdx.x & 15, ks = threadIdx.x >> 4;
    int j = blockIdx.x*16 + jl;
    float acc[BB];
    #pragma unroll
    for (int b = 0; b < BB; b++) acc[b] = 0.f;
    for (int k = ks*128; k < ks*128 + 128; k++) {
        float wv = w1[k*512 + j];
        #pragma unroll
        for (int b = 0; b < BB; b++) acc[b] += d_x12[b*2*EMB + k]*wv;
    }
    __shared__ float sh[16][16][BB];
    #pragma unroll
    for (int b = 0; b < BB; b++) sh[ks][jl][b] = acc[b];
    __syncthreads();
    if (ks == 0) {
        #pragma unroll
        for (int b = 0; b < BB; b++) {
            float s = 0.f;
            #pragma unroll
            for (int i = 0; i < 16; i++) s += sh[i][jl][b];
            acc[b] = s;
        }
        float m = 0.f;
        #pragma unroll
        for (int b = 0; b < BB; b++) m += acc[b];
        m *= (1.f/BB);
        float var = 0.f;
        #pragma unroll
        for (int b = 0; b < BB; b++) { float d = acc[b]-m; var += d*d; }
        var *= (1.f/BB);
        float sc = rsqrtf(var + 1e-5f)*g6[j], bb = b6[j];
        #pragma unroll
        for (int b = 0; b < BB; b++) {
            float o = (acc[b]-m)*sc + bb;
            d_h512[b*512 + j] = o > 0.f ? o : 0.2f*o;
        }
    }
}

__global__ void k_head2(const float* __restrict__ w2, const float* __restrict__ b2,
                        const float* __restrict__ g7, const float* __restrict__ b7) {
    // grid 8; 32 j per block; 8-way k-split of 64 each
    int jl = threadIdx.x & 31, ks = threadIdx.x >> 5;
    int j = blockIdx.x*32 + jl;
    float acc[BB];
    #pragma unroll
    for (int b = 0; b < BB; b++) acc[b] = 0.f;
    for (int k = ks*64; k < ks*64 + 64; k++) {
        float wv = w2[k*256 + j];
        #pragma unroll
        for (int b = 0; b < BB; b++) acc[b] += d_h512[b*512 + k]*wv;
    }
    __shared__ float sh[8][32][BB];
    #pragma unroll
    for (int b = 0; b < BB; b++) sh[ks][jl][b] = acc[b];
    __syncthreads();
    if (ks == 0) {
        #pragma unroll
        for (int b = 0; b < BB; b++) {
            float s = 0.f;
            #pragma unroll
            for (int i = 0; i < 8; i++) s += sh[i][jl][b];
            acc[b] = s + b2[j];
        }
        float m = 0.f;
        #pragma unroll
        for (int b = 0; b < BB; b++) m += acc[b];
        m *= (1.f/BB);
        float var = 0.f;
        #pragma unroll
        for (int b = 0; b < BB; b++) { float d = acc[b]-m; var += d*d; }
        var *= (1.f/BB);
        float sc = rsqrtf(var + 1e-5f)*g7[j], bb = b7[j];
        #pragma unroll
        for (int b = 0; b < BB; b++) {
            float o = (acc[b]-m)*sc + bb;
            d_h256[b*256 + j] = o > 0.f ? o : 0.2f*o;
        }
    }
}

__global__ void k_head3(const float* __restrict__ w3, const float* __restrict__ b3,
                        float* __restrict__ out) {
    // 1 block 256: jl = j (40 used), 4-way k-split of 64 each
    int jl = threadIdx.x & 63, ks = threadIdx.x >> 6;
    float acc[BB];
    #pragma unroll
    for (int b = 0; b < BB; b++) acc[b] = 0.f;
    if (jl < 40) {
        for (int k = ks*64; k < ks*64 + 64; k++) {
            float wv = w3[k*40 + jl];
            #pragma unroll
            for (int b = 0; b < BB; b++) acc[b] += d_h256[b*256 + k]*wv;
        }
    }
    __shared__ float sh[4][64][BB];
    #pragma unroll
    for (int b = 0; b < BB; b++) sh[ks][jl][b] = acc[b];
    __syncthreads();
    if (ks == 0 && jl < 40) {
        #pragma unroll
        for (int b = 0; b < BB; b++) {
            float s = b3[jl];
            #pragma unroll
            for (int i = 0; i < 4; i++) s += sh[i][jl][b];
            out[b*40 + jl] = s;
        }
    }
}

// ---------------- launch ----------------
extern "C" void kernel_launch(void* const* d_in, const int* in_sizes, int n_in,
                              void* d_out, int out_size) {
    const float* x     = (const float*)d_in[0];
    const float* w0    = (const float*)d_in[1];
    const float* b0    = (const float*)d_in[2];
    const float* g0    = (const float*)d_in[3];
    const float* be0   = (const float*)d_in[4];
    const float* wr    = (const float*)d_in[5];
    const float* br    = (const float*)d_in[6];
    const float* gr    = (const float*)d_in[7];
    const float* ber   = (const float*)d_in[8];
    const float* W     = (const float*)d_in[9];
    const float* Bv    = (const float*)d_in[10];
    const float* G     = (const float*)d_in[11];
    const float* Be    = (const float*)d_in[12];
    const float* wconv = (const float*)d_in[13];
    const float* gf    = (const float*)d_in[14];
    const float* bef   = (const float*)d_in[15];
    const float* w1    = (const float*)d_in[16];
    const float* g6    = (const float*)d_in[17];
    const float* b6    = (const float*)d_in[18];
    const float* w2    = (const float*)d_in[19];
    const float* b2    = (const float*)d_in[20];
    const float* g7    = (const float*)d_in[21];
    const float* b7    = (const float*)d_in[22];
    const float* w3    = (const float*)d_in[23];
    const float* b3    = (const float*)d_in[24];
    float* out = (float*)d_out;

    // graph build
    k_init<<<64, 256>>>();
    k_prep<<<64, 256>>>(x);
    k_knn<<<256, 256>>>();
    k_scan<<<1, 1024>>>();
    k_fill<<<64, 256>>>();
    k_cvtA<<<256, 256>>>(wconv);

    // layer 0
    k_l0mm<<<4096, 256>>>(x, w0, wr, br);
    k_gather_stats<<<4096, 256>>>(b0, 0);
    k_post0_mm<<<256, 256>>>(g0, be0, gr, ber, W);

    // layer 1
    k_gather_stats<<<4096, 256>>>(Bv, 1);
    k_postL_mm<<<256, 256>>>(1, G, Be, W + 4096);
    // layer 2
    k_gather_stats<<<4096, 256>>>(Bv + 64, 2);
    k_postL_mm<<<256, 256>>>(2, G + 64, Be + 64, W + 8192);
    // layer 3
    k_gather_stats<<<4096, 256>>>(Bv + 128, 3);
    k_post3<<<4096, 256>>>(G + 128, Be + 128);

    // conv 256 -> 1024 + BN + leaky + pool
    dim3 cgrid(128, 8);
    k_conv_mma<<<cgrid, 256>>>();
    k_reduce<<<1024, 256>>>(gf, bef);

    // head
    k_head1<<<32, 256>>>(w1, g6, b6);
    k_head2<<<8, 256>>>(w2, b2, g7, b7);
    k_head3<<<1, 256>>>(w3, b3, out);
}

// round 6
// speedup vs baseline: 6.5027x; 1.0046x over previous
#include <cuda_runtime.h>
#include <cuda_bf16.h>
#include <float.h>
#include <stdint.h>

// ---------------- problem constants ----------------
#define BB    8
#define NPT   2048
#define BNP   16384          // BB*NPT
#define KNN   20
#define CH    64
#define FD    256            // 4*CH
#define EMB   1024

// ---------------- scratch (device globals; no mallocs allowed) ----------------
__device__ float4 d_P4[BB*NPT];
__device__ int   d_nbr[BNP*KNN];
__device__ int   d_deg[BNP];
__device__ int   d_rowstart[BNP+1];
__device__ int   d_cursor[BNP];
__device__ int   d_rev[BNP*KNN];
__device__ float d_F[BNP*FD];
__device__ float d_sup[BNP*CH];
__device__ float d_z[BNP*CH];
__device__ float d_rz[BNP*CH];
__device__ float d_Y[(size_t)EMB*BNP]; // conv output [e][p], 64 MB
__device__ float d_x12[BB*2*EMB];
__device__ float d_h512[BB*512];
__device__ float d_h256[BB*256];
__device__ float d_sumA[4*CH], d_sqA[4*CH];
__device__ float d_sumB[CH], d_sqB[CH];
__device__ float d_sumY[EMB], d_sqY[EMB];    // conv BN stats (fused in epilogue)
__device__ __nv_bfloat16 d_Ahi[EMB*FD], d_Alo[EMB*FD];
__device__ __nv_bfloat16 d_Fhi[BNP*FD], d_Flo[BNP*FD];

// ---------------- warp-MMA / cp.async helpers (sm_80+ baseline PTX) ----------
__device__ __forceinline__ uint32_t smem_u32(const void* p) {
    uint32_t a;
    asm("{ .reg .u64 t; cvta.to.shared.u64 t, %1; cvt.u32.u64 %0, t; }" : "=r"(a) : "l"(p));
    return a;
}
__device__ __forceinline__ void ldm_x4(uint32_t* r, uint32_t addr) {
    asm volatile("ldmatrix.sync.aligned.m8n8.x4.shared.b16 {%0,%1,%2,%3}, [%4];"
        : "=r"(r[0]), "=r"(r[1]), "=r"(r[2]), "=r"(r[3]) : "r"(addr));
}
__device__ __forceinline__ void mma16816(float* c, const uint32_t* a, const uint32_t* b) {
    asm volatile(
        "mma.sync.aligned.m16n8k16.row.col.f32.bf16.bf16.f32 "
        "{%0,%1,%2,%3}, {%4,%5,%6,%7}, {%8,%9}, {%0,%1,%2,%3};"
        : "+f"(c[0]), "+f"(c[1]), "+f"(c[2]), "+f"(c[3])
        : "r"(a[0]), "r"(a[1]), "r"(a[2]), "r"(a[3]), "r"(b[0]), "r"(b[1]));
}
__device__ __forceinline__ void cp16(uint32_t sdst, const void* gsrc) {
    asm volatile("cp.async.cg.shared.global [%0], [%1], 16;" :: "r"(sdst), "l"(gsrc));
}
#define CP_COMMIT() asm volatile("cp.async.commit_group;" ::: "memory")
#define CP_WAIT0()  asm volatile("cp.async.wait_group 0;" ::: "memory")

// ---------------- init ----------------
__global__ void k_init() {
    int t = blockIdx.x*256 + threadIdx.x;
    if (t < BNP) d_deg[t] = 0;
    if (t < 4*CH) { d_sumA[t] = 0.f; d_sqA[t] = 0.f; }
    if (t < CH)   { d_sumB[t] = 0.f; d_sqB[t] = 0.f; }
    if (t < EMB)  { d_sumY[t] = 0.f; d_sqY[t] = 0.f; }
}

// pts[b,c,n] = x[b, (c*N+n)%3, (c*N+n)/3]
__global__ void k_prep(const float* __restrict__ x) {
    int t = blockIdx.x*256 + threadIdx.x;
    if (t >= BNP) return;
    int b = t >> 11, n = t & 2047;
    const float* xb = x + b*3*NPT;
    float v[3]; float acc = 0.f;
    #pragma unroll
    for (int c = 0; c < 3; c++) {
        int L = c*NPT + n;
        v[c] = xb[(L % 3)*NPT + (L / 3)];
        acc += v[c]*v[c];
    }
    d_P4[t] = make_float4(v[0], v[1], v[2], acc);
}

__device__ __forceinline__ unsigned fkey(float f) {
    unsigned u = __float_as_uint(f);
    return (u & 0x80000000u) ? ~u : (u | 0x80000000u);
}

// ---------------- knn ----------------
__global__ void __launch_bounds__(256) k_knn() {
    __shared__ float4 sP[NPT];
    int b = blockIdx.x >> 5;
    int chunk = blockIdx.x & 31;
    for (int i = threadIdx.x; i < NPT; i += 256)
        sP[i] = d_P4[b*NPT + i];
    __syncthreads();

    int warp = threadIdx.x >> 5, lane = threadIdx.x & 31;
    for (int r = 0; r < 8; r++) {
        int n = chunk*64 + warp*8 + r;
        float4 q = sP[n];
        float qx = q.x, qy = q.y, qz = q.z, qxx = q.w;

        float v[KNN]; int id[KNN];
        #pragma unroll
        for (int j = 0; j < KNN; j++) { v[j] = -FLT_MAX; id[j] = 0x7fffffff; }

        for (int m = lane; m < NPT; m += 32) {
            float4 pm = sP[m];
            float dot = qx*pm.x + qy*pm.y + qz*pm.z;
            float pd = (-qxx + 2.f*dot) - pm.w;
            if (pd > v[KNN-1]) {
                v[KNN-1] = pd; id[KNN-1] = m;
                #pragma unroll
                for (int j = KNN-1; j > 0; j--) {
                    if (v[j] > v[j-1]) {
                        float tv = v[j]; v[j] = v[j-1]; v[j-1] = tv;
                        int   ti = id[j]; id[j] = id[j-1]; id[j-1] = ti;
                    }
                }
            }
        }
        int pg = b*NPT + n;
        #pragma unroll 1
        for (int k = 0; k < KNN; k++) {
            unsigned mykey = fkey(v[0]);
            unsigned best = __reduce_max_sync(0xffffffffu, mykey);
            int cand = (mykey == best) ? id[0] : 0x7fffffff;
            int bmi = __reduce_min_sync(0xffffffffu, cand);
            if (mykey == best && id[0] == bmi) {
                #pragma unroll
                for (int j = 0; j < KNN-1; j++) { v[j] = v[j+1]; id[j] = id[j+1]; }
                v[KNN-1] = -FLT_MAX; id[KNN-1] = 0x7fffffff;
            }
            if (lane == 0) {
                int qg = b*NPT + bmi;
                d_nbr[pg*KNN + k] = qg;
                atomicAdd(&d_deg[qg], 1);
            }
        }
    }
}

// exclusive scan of 16384 degrees (single block, int4 loads)
__global__ void k_scan() {
    int t = threadIdx.x;
    int loc[16]; int s = 0;
    const int4* dg4 = (const int4*)d_deg;
    int4 q[4];
    #pragma unroll
    for (int i = 0; i < 4; i++) q[i] = dg4[t*4 + i];
    const int* qq = (const int*)q;
    #pragma unroll
    for (int i = 0; i < 16; i++) { loc[i] = s; s += qq[i]; }
    int lane = t & 31, wid = t >> 5;
    int vv = s;
    #pragma unroll
    for (int o = 1; o < 32; o <<= 1) { int u = __shfl_up_sync(0xffffffffu, vv, o); if (lane >= o) vv += u; }
    __shared__ int ws[32];
    if (lane == 31) ws[wid] = vv;
    __syncthreads();
    if (wid == 0) {
        int w = ws[lane];
        #pragma unroll
        for (int o = 1; o < 32; o <<= 1) { int u = __shfl_up_sync(0xffffffffu, w, o); if (lane >= o) w += u; }
        ws[lane] = w;
    }
    __syncthreads();
    int excl = vv - s + (wid ? ws[wid-1] : 0);
    int base = t*16;
    #pragma unroll
    for (int i = 0; i < 16; i++) { int rs = excl + loc[i]; d_rowstart[base+i] = rs; d_cursor[base+i] = rs; }
    if (t == 1023) d_rowstart[BNP] = excl + s;
}

__global__ void k_fill() {
    int p = blockIdx.x*256 + threadIdx.x;
    if (p >= BNP) return;
    #pragma unroll
    for (int k = 0; k < KNN; k++) {
        int q = d_nbr[p*KNN + k];
        int pos = atomicAdd(&d_cursor[q], 1);
        d_rev[pos] = p;
    }
}

// ---------------- layer 0: sup0 = flat@w0 ; rz = flat@wr + br (+ rz stats) ----
__global__ void k_l0mm(const float* __restrict__ x, const float* __restrict__ w0,
                       const float* __restrict__ wr, const float* __restrict__ br) {
    int tid = threadIdx.x;
    int t = blockIdx.x*256 + tid;
    int p = t >> 6, c = t & 63;
    int b = p >> 11, n = p & 2047;
    const float* xb = x + b*3*NPT;
    float x0 = xb[n], x1 = xb[NPT + n], x2 = xb[2*NPT + n];
    d_sup[t] = x0*w0[c] + x1*w0[64+c] + x2*w0[128+c];
    float rz = x0*wr[c] + x1*wr[64+c] + x2*wr[128+c] + br[c];
    d_rz[t] = rz;
    __shared__ float s1[256], s2[256];
    s1[tid] = rz; s2[tid] = rz*rz;
    __syncthreads();
    if (tid < 64) {
        float a = s1[tid] + s1[64+tid] + s1[128+tid] + s1[192+tid];
        float q = s2[tid] + s2[64+tid] + s2[128+tid] + s2[192+tid];
        atomicAdd(&d_sumB[tid], a);
        atomicAdd(&d_sqB[tid], q);
    }
}

// ---------------- gather (reverse CSR) + bias + z stats ----------------
__global__ void k_gather_stats(const float* __restrict__ bias, int layer) {
    int t = threadIdx.x;
    int q = blockIdx.x*4 + (t >> 6);
    int c = t & 63;
    float acc = bias[c];
    int s0 = d_rowstart[q], e0 = d_rowstart[q+1];
    for (int i = s0; i < e0; i++) acc += d_sup[d_rev[i]*64 + c];
    d_z[q*64 + c] = acc;
    __shared__ float s1[256], s2[256];
    s1[t] = acc; s2[t] = acc*acc;
    __syncthreads();
    if (t < 64) {
        float a = s1[t] + s1[64+t] + s1[128+t] + s1[192+t];
        float qq = s2[t] + s2[64+t] + s2[128+t] + s2[192+t];
        atomicAdd(&d_sumA[layer*64 + t], a);
        atomicAdd(&d_sqA[layer*64 + t], qq);
    }
}

// ---------------- fused post (layer 0) + mm for layer 1 ----------------
__global__ void __launch_bounds__(256) k_post0_mm(
        const float* __restrict__ g0, const float* __restrict__ be0,
        const float* __restrict__ gr, const float* __restrict__ ber,
        const float* __restrict__ W1) {
    __shared__ float Hs[64*64];
    __shared__ float Ws[64*64];
    int tid = threadIdx.x;
    int p0 = blockIdx.x*64;
    int c = tid & 63, rg = tid >> 6;
    float mA = d_sumA[c]*(1.f/BNP);
    float vA = d_sqA[c]*(1.f/BNP) - mA*mA;
    float sA = rsqrtf(vA + 1e-5f)*g0[c], bA = be0[c];
    float mB = d_sumB[c]*(1.f/BNP);
    float vB = d_sqB[c]*(1.f/BNP) - mB*mB;
    float sB = rsqrtf(vB + 1e-5f)*gr[c], bB = ber[c];
    #pragma unroll
    for (int i = 0; i < 16; i++) {
        int r = rg + i*4, p = p0 + r;
        float o = fmaxf((d_z[p*64+c] - mA)*sA + bA, 0.f);
        float rr = (d_rz[p*64+c] - mB)*sB + bB;
        float h = fmaxf(o + rr, 0.f);
        Hs[r*64+c] = h;
        d_F[p*FD + c] = h;
        __nv_bfloat16 hi = __float2bfloat16(h);
        d_Fhi[p*FD + c] = hi;
        d_Flo[p*FD + c] = __float2bfloat16(h - __bfloat162float(hi));
    }
    for (int i = tid; i < 4096; i += 256) Ws[i] = W1[i];
    __syncthreads();
    for (int r = rg; r < 64; r += 4) {
        float acc = 0.f;
        #pragma unroll 16
        for (int k = 0; k < 64; k++) acc += Hs[r*64+k]*Ws[k*64+c];
        d_sup[(p0+r)*64+c] = acc;
    }
}

// ---------------- fused post (layers 1,2) + mm for next layer ----------------
__global__ void __launch_bounds__(256) k_postL_mm(int layer,
        const float* __restrict__ G, const float* __restrict__ Be,
        const float* __restrict__ Wn) {
    __shared__ float Hs[64*64];
    __shared__ float Ws[64*64];
    int tid = threadIdx.x;
    int p0 = blockIdx.x*64;
    int c = tid & 63, rg = tid >> 6;
    float m = d_sumA[layer*64+c]*(1.f/BNP);
    float v = d_sqA[layer*64+c]*(1.f/BNP) - m*m;
    float sc = rsqrtf(v + 1e-5f)*G[c], bc = Be[c];
    #pragma unroll
    for (int i = 0; i < 16; i++) {
        int r = rg + i*4, p = p0 + r;
        float a = fmaxf((d_z[p*64+c] - m)*sc + bc, 0.f);
        float h = fmaxf(a + d_F[p*FD + (layer-1)*64 + c], 0.f);
        Hs[r*64+c] = h;
        d_F[p*FD + layer*64 + c] = h;
        __nv_bfloat16 hi = __float2bfloat16(h);
        d_Fhi[p*FD + layer*64 + c] = hi;
        d_Flo[p*FD + layer*64 + c] = __float2bfloat16(h - __bfloat162float(hi));
    }
    for (int i = tid; i < 4096; i += 256) Ws[i] = Wn[i];
    __syncthreads();
    for (int r = rg; r < 64; r += 4) {
        float acc = 0.f;
        #pragma unroll 16
        for (int k = 0; k < 64; k++) acc += Hs[r*64+k]*Ws[k*64+c];
        d_sup[(p0+r)*64+c] = acc;
    }
}

// ---------------- post layer 3 ----------------
__global__ void k_post3(const float* __restrict__ G, const float* __restrict__ Be) {
    int t = blockIdx.x*256 + threadIdx.x;
    int p = t >> 6, c = t & 63;
    float m = d_sumA[3*64+c]*(1.f/BNP);
    float v = d_sqA[3*64+c]*(1.f/BNP) - m*m;
    float a = fmaxf((d_z[t] - m)*rsqrtf(v + 1e-5f)*G[c] + Be[c], 0.f);
    float h = fmaxf(a + d_F[p*FD + 2*64 + c], 0.f);
    __nv_bfloat16 hi = __float2bfloat16(h);
    d_Fhi[p*FD + 3*64 + c] = hi;
    d_Flo[p*FD + 3*64 + c] = __float2bfloat16(h - __bfloat162float(hi));
}

// ---------------- bf16 hi/lo conversion of wconv ----------------
__global__ void k_cvtA(const float* __restrict__ w) {
    int t = blockIdx.x*256 + threadIdx.x;
    float4 x = ((const float4*)w)[t];
    __nv_bfloat16 h0 = __float2bfloat16(x.x), h1 = __float2bfloat16(x.y);
    __nv_bfloat16 h2 = __float2bfloat16(x.z), h3 = __float2bfloat16(x.w);
    __nv_bfloat16 l0 = __float2bfloat16(x.x - __bfloat162float(h0));
    __nv_bfloat16 l1 = __float2bfloat16(x.y - __bfloat162float(h1));
    __nv_bfloat16 l2 = __float2bfloat16(x.z - __bfloat162float(h2));
    __nv_bfloat16 l3 = __float2bfloat16(x.w - __bfloat162float(h3));
    ((__nv_bfloat162*)d_Ahi)[t*2]   = __nv_bfloat162(h0, h1);
    ((__nv_bfloat162*)d_Ahi)[t*2+1] = __nv_bfloat162(h2, h3);
    ((__nv_bfloat162*)d_Alo)[t*2]   = __nv_bfloat162(l0, l1);
    ((__nv_bfloat162*)d_Alo)[t*2+1] = __nv_bfloat162(l2, l3);
}

// ---------------- conv GEMM via mma.sync, cp.async 2-stage, fused BN stats ---
#define PITCH 80
#define TSZ   (128*PITCH)     // 10240 B per tile (rows hold 64B of data, pitch 80)
#define STAGE (4*TSZ)         // 40960 B per stage
#define SMEM_CONV (2*STAGE)   // 81920 B dynamic

__global__ void __launch_bounds__(256) k_conv_mma() {
    extern __shared__ __align__(16) uint8_t sm[];
    uint32_t sb = smem_u32(sm);

    int tid = threadIdx.x, wid = tid >> 5, lane = tid & 31;
    int warp_m = wid >> 2, warp_n = wid & 3;
    int bn = blockIdx.x;
    int bm = blockIdx.y;

    const uint4* gAhi = (const uint4*)d_Ahi;
    const uint4* gAlo = (const uint4*)d_Alo;
    const uint4* gBhi = (const uint4*)d_Fhi;
    const uint4* gBlo = (const uint4*)d_Flo;

    float C[4][4][4];
    #pragma unroll
    for (int i = 0; i < 4; i++)
        #pragma unroll
        for (int j = 0; j < 4; j++)
            #pragma unroll
            for (int q = 0; q < 4; q++) C[i][j][q] = 0.f;

    // per-lane ldmatrix offsets (within a stage)
    int rowA  = warp_m*64 + (lane & 15);
    int halfA = lane >> 4;
    uint32_t oAhi = rowA*PITCH + halfA*16;            // + 0*TSZ
    uint32_t oAlo = TSZ + rowA*PITCH + halfA*16;
    int rowB  = warp_n*32 + (lane & 7) + ((lane >> 4) << 3);
    int halfB = (lane >> 3) & 1;
    uint32_t oBhi = 2*TSZ + rowB*PITCH + halfB*16;
    uint32_t oBlo = 3*TSZ + rowB*PITCH + halfB*16;

    // per-thread copy indices
    int crow = tid >> 1;                 // two threads per row? No: 512 iters over 2 l
    // issue loads for chunk kc into stage s
    auto issue = [&](int kc, int s) {
        uint32_t base = sb + s*STAGE;
        #pragma unroll
        for (int l = 0; l < 2; l++) {
            int i = tid + l*256;         // 0..511
            int row = i >> 2, c = i & 3;
            uint32_t so = row*PITCH + c*16;
            size_t ga = (size_t)(bm*128 + row)*32 + kc*4 + c;
            size_t gb = (size_t)(bn*128 + row)*32 + kc*4 + c;
            cp16(base + so,          gAhi + ga);
            cp16(base + TSZ + so,    gAlo + ga);
            cp16(base + 2*TSZ + so,  gBhi + gb);
            cp16(base + 3*TSZ + so,  gBlo + gb);
        }
        CP_COMMIT();
    };
    (void)crow;

    issue(0, 0);
    for (int kc = 0; kc < 8; kc++) {
        int s = kc & 1;
        CP_WAIT0();
        __syncthreads();
        if (kc + 1 < 8) issue(kc + 1, s ^ 1);
        uint32_t stb = sb + s*STAGE;

        #pragma unroll
        for (int ksub = 0; ksub < 2; ksub++) {
            uint32_t koff = (ksub*2)*16;
            uint32_t bh[8], bl[8];
            ldm_x4(bh + 0, stb + oBhi + koff);
            ldm_x4(bh + 4, stb + oBhi + koff + 16*PITCH);
            ldm_x4(bl + 0, stb + oBlo + koff);
            ldm_x4(bl + 4, stb + oBlo + koff + 16*PITCH);
            #pragma unroll
            for (int mt = 0; mt < 4; mt++) {
                uint32_t ah[4], al[4];
                ldm_x4(ah, stb + oAhi + koff + mt*16*PITCH);
                ldm_x4(al, stb + oAlo + koff + mt*16*PITCH);
                #pragma unroll
                for (int nt = 0; nt < 4; nt++) {
                    const uint32_t* ph = &bh[(nt >> 1)*4 + (nt & 1)*2];
                    const uint32_t* pl = &bl[(nt >> 1)*4 + (nt & 1)*2];
                    mma16816(C[mt][nt], ah, ph);
                    mma16816(C[mt][nt], ah, pl);
                    mma16816(C[mt][nt], al, ph);
                }
            }
        }
        __syncthreads();
    }

    // epilogue: store + fused per-e BN partial stats (quad reduce + RED)
    #pragma unroll
    for (int mt = 0; mt < 4; mt++) {
        int e = bm*128 + warp_m*64 + mt*16 + (lane >> 2);
        float s0 = 0.f, q0 = 0.f, s1 = 0.f, q1 = 0.f;
        #pragma unroll
        for (int nt = 0; nt < 4; nt++) {
            int p = bn*128 + warp_n*32 + nt*8 + (lane & 3)*2;
            float a0 = C[mt][nt][0], a1 = C[mt][nt][1];
            float a2 = C[mt][nt][2], a3 = C[mt][nt][3];
            *(float2*)&d_Y[(size_t)e*BNP + p]       = make_float2(a0, a1);
            *(float2*)&d_Y[(size_t)(e + 8)*BNP + p] = make_float2(a2, a3);
            s0 += a0 + a1; q0 += a0*a0 + a1*a1;
            s1 += a2 + a3; q1 += a2*a2 + a3*a3;
        }
        #pragma unroll
        for (int o = 1; o < 4; o <<= 1) {
            s0 += __shfl_xor_sync(0xffffffffu, s0, o);
            q0 += __shfl_xor_sync(0xffffffffu, q0, o);
            s1 += __shfl_xor_sync(0xffffffffu, s1, o);
            q1 += __shfl_xor_sync(0xffffffffu, q1, o);
        }
        if ((lane & 3) == 0) {
            atomicAdd(&d_sumY[e], s0);     atomicAdd(&d_sqY[e], q0);
            atomicAdd(&d_sumY[e + 8], s1); atomicAdd(&d_sqY[e + 8], q1);
        }
    }
}

// ---------------- conv BN + leaky + pooling (single pass, stats precomputed) --
__global__ void k_reduce(const float* __restrict__ gf, const float* __restrict__ bef) {
    int e = blockIdx.x;
    const float* y = d_Y + (size_t)e*BNP;
    int t = threadIdx.x, lane = t & 31, w = t >> 5;
    float mu = d_sumY[e]*(1.f/BNP);
    float var = d_sqY[e]*(1.f/BNP) - mu*mu;
    float sc = rsqrtf(var + 1e-5f)*gf[e], sh = bef[e];
    __shared__ float w1a[8], w2a[8];
    for (int b = 0; b < BB; b++) {
        float mx = -FLT_MAX, sm = 0.f;
        for (int j = t; j < NPT; j += 256) {
            float v = y[b*NPT + j];
            v = (v - mu)*sc + sh;
            v = v > 0.f ? v : 0.2f*v;
            mx = fmaxf(mx, v); sm += v;
        }
        #pragma unroll
        for (int o = 16; o; o >>= 1) {
            mx = fmaxf(mx, __shfl_xor_sync(0xffffffffu, mx, o));
            sm += __shfl_xor_sync(0xffffffffu, sm, o);
        }
        if (lane == 0) { w1a[w] = mx; w2a[w] = sm; }
        __syncthreads();
        if (t == 0) {
            float MX = w1a[0], SM = w2a[0];
            #pragma unroll
            for (int i = 1; i < 8; i++) { MX = fmaxf(MX, w1a[i]); SM += w2a[i]; }
            d_x12[b*2*EMB + e] = MX;
            d_x12[b*2*EMB + EMB + e] = SM*(1.f/NPT);
        }
        __syncthreads();
    }
}

// ---------------- head (k-split parallel) ----------------
__global__ void k_head1(const float* __restrict__ w1, const float* __restrict__ g6,
                        const float* __restrict__ b6) {
    int jl = threadIdx.x & 15, ks = threadIdx.x >> 4;
    int j = blockIdx.x*16 + jl;
    float acc[BB];
    #pragma unroll
    for (int b = 0; b < BB; b++) acc[b] = 0.f;
    for (int k = ks*128; k < ks*128 + 128; k++) {
        float wv = w1[k*512 + j];
        #pragma unroll
        for (int b = 0; b < BB; b++) acc[b] += d_x12[b*2*EMB + k]*wv;
    }
    __shared__ float sh[16][16][BB];
    #pragma unroll
    for (int b = 0; b < BB; b++) sh[ks][jl][b] = acc[b];
    __syncthreads();
    if (ks == 0) {
        #pragma unroll
        for (int b = 0; b < BB; b++) {
            float s = 0.f;
            #pragma unroll
            for (int i = 0; i < 16; i++) s += sh[i][jl][b];
            acc[b] = s;
        }
        float m = 0.f;
        #pragma unroll
        for (int b = 0; b < BB; b++) m += acc[b];
        m *= (1.f/BB);
        float var = 0.f;
        #pragma unroll
        for (int b = 0; b < BB; b++) { float d = acc[b]-m; var += d*d; }
        var *= (1.f/BB);
        float sc = rsqrtf(var + 1e-5f)*g6[j], bb = b6[j];
        #pragma unroll
        for (int b = 0; b < BB; b++) {
            float o = (acc[b]-m)*sc + bb;
            d_h512[b*512 + j] = o > 0.f ? o : 0.2f*o;
        }
    }
}

__global__ void k_head2(const float* __restrict__ w2, const float* __restrict__ b2,
                        const float* __restrict__ g7, const float* __restrict__ b7) {
    int jl = threadIdx.x & 31, ks = threadIdx.x >> 5;
    int j = blockIdx.x*32 + jl;
    float acc[BB];
    #pragma unroll
    for (int b = 0; b < BB; b++) acc[b] = 0.f;
    for (int k = ks*64; k < ks*64 + 64; k++) {
        float wv = w2[k*256 + j];
        #pragma unroll
        for (int b = 0; b < BB; b++) acc[b] += d_h512[b*512 + k]*wv;
    }
    __shared__ float sh[8][32][BB];
    #pragma unroll
    for (int b = 0; b < BB; b++) sh[ks][jl][b] = acc[b];
    __syncthreads();
    if (ks == 0) {
        #pragma unroll
        for (int b = 0; b < BB; b++) {
            float s = 0.f;
            #pragma unroll
            for (int i = 0; i < 8; i++) s += sh[i][jl][b];
            acc[b] = s + b2[j];
        }
        float m = 0.f;
        #pragma unroll
        for (int b = 0; b < BB; b++) m += acc[b];
        m *= (1.f/BB);
        float var = 0.f;
        #pragma unroll
        for (int b = 0; b < BB; b++) { float d = acc[b]-m; var += d*d; }
        var *= (1.f/BB);
        float sc = rsqrtf(var + 1e-5f)*g7[j], bb = b7[j];
        #pragma unroll
        for (int b = 0; b < BB; b++) {
            float o = (acc[b]-m)*sc + bb;
            d_h256[b*256 + j] = o > 0.f ? o : 0.2f*o;
        }
    }
}

__global__ void k_head3(const float* __restrict__ w3, const float* __restrict__ b3,
                        float* __restrict__ out) {
    int jl = threadIdx.x & 63, ks = threadIdx.x >> 6;
    float acc[BB];
    #pragma unroll
    for (int b = 0; b < BB; b++) acc[b] = 0.f;
    if (jl < 40) {
        for (int k = ks*64; k < ks*64 + 64; k++) {
            float wv = w3[k*40 + jl];
            #pragma unroll
            for (int b = 0; b < BB; b++) acc[b] += d_h256[b*256 + k]*wv;
        }
    }
    __shared__ float sh[4][64][BB];
    #pragma unroll
    for (int b = 0; b < BB; b++) sh[ks][jl][b] = acc[b];
    __syncthreads();
    if (ks == 0 && jl < 40) {
        #pragma unroll
        for (int b = 0; b < BB; b++) {
            float s = b3[jl];
            #pragma unroll
            for (int i = 0; i < 4; i++) s += sh[i][jl][b];
            out[b*40 + jl] = s;
        }
    }
}

// ---------------- launch ----------------
extern "C" void kernel_launch(void* const* d_in, const int* in_sizes, int n_in,
                              void* d_out, int out_size) {
    const float* x     = (const float*)d_in[0];
    const float* w0    = (const float*)d_in[1];
    const float* b0    = (const float*)d_in[2];
    const float* g0    = (const float*)d_in[3];
    const float* be0   = (const float*)d_in[4];
    const float* wr    = (const float*)d_in[5];
    const float* br    = (const float*)d_in[6];
    const float* gr    = (const float*)d_in[7];
    const float* ber   = (const float*)d_in[8];
    const float* W     = (const float*)d_in[9];
    const float* Bv    = (const float*)d_in[10];
    const float* G     = (const float*)d_in[11];
    const float* Be    = (const float*)d_in[12];
    const float* wconv = (const float*)d_in[13];
    const float* gf    = (const float*)d_in[14];
    const float* bef   = (const float*)d_in[15];
    const float* w1    = (const float*)d_in[16];
    const float* g6    = (const float*)d_in[17];
    const float* b6    = (const float*)d_in[18];
    const float* w2    = (const float*)d_in[19];
    const float* b2    = (const float*)d_in[20];
    const float* g7    = (const float*)d_in[21];
    const float* b7    = (const float*)d_in[22];
    const float* w3    = (const float*)d_in[23];
    const float* b3    = (const float*)d_in[24];
    float* out = (float*)d_out;

    static int smem_set = 0;
    if (!smem_set) {
        cudaFuncSetAttribute(k_conv_mma, cudaFuncAttributeMaxDynamicSharedMemorySize, SMEM_CONV);
        smem_set = 1;
    }

    // graph build (k_cvtA moved before k_knn so ncu's capture slot hits k_knn)
    k_init<<<64, 256>>>();
    k_prep<<<64, 256>>>(x);
    k_cvtA<<<256, 256>>>(wconv);
    k_knn<<<256, 256>>>();
    k_scan<<<1, 1024>>>();
    k_fill<<<64, 256>>>();

    // layer 0
    k_l0mm<<<4096, 256>>>(x, w0, wr, br);
    k_gather_stats<<<4096, 256>>>(b0, 0);
    k_post0_mm<<<256, 256>>>(g0, be0, gr, ber, W);

    // layers 1..3
    k_gather_stats<<<4096, 256>>>(Bv, 1);
    k_postL_mm<<<256, 256>>>(1, G, Be, W + 4096);
    k_gather_stats<<<4096, 256>>>(Bv + 64, 2);
    k_postL_mm<<<256, 256>>>(2, G + 64, Be + 64, W + 8192);
    k_gather_stats<<<4096, 256>>>(Bv + 128, 3);
    k_post3<<<4096, 256>>>(G + 128, Be + 128);

    // conv 256 -> 1024 + fused BN stats, then single-pass BN+leaky+pool
    dim3 cgrid(128, 8);
    k_conv_mma<<<cgrid, 256, SMEM_CONV>>>();
    k_reduce<<<1024, 256>>>(gf, bef);

    // head
    k_head1<<<32, 256>>>(w1, g6, b6);
    k_head2<<<8, 256>>>(w2, b2, g7, b7);
    k_head3<<<1, 256>>>(w3, b3, out);
}

// round 7
// speedup vs baseline: 9.2247x; 1.4186x over previous
#include <cuda_runtime.h>
#include <cuda_bf16.h>
#include <float.h>
#include <stdint.h>

// ---------------- problem constants ----------------
#define BB    8
#define NPT   2048
#define BNP   16384          // BB*NPT
#define KNN   20
#define CH    64
#define FD    256            // 4*CH
#define EMB   1024

// ---------------- scratch (device globals; no mallocs allowed) ----------------
__device__ float4 d_P4[BB*NPT];
__device__ int   d_nbr[BNP*KNN];
__device__ int   d_deg[BNP];
__device__ int   d_rowstart[BNP+1];
__device__ int   d_cursor[BNP];
__device__ int   d_rev[BNP*KNN];
__device__ float d_F[BNP*FD];
__device__ float d_sup[BNP*CH];
__device__ float d_z[BNP*CH];
__device__ float d_rz[BNP*CH];
__device__ float d_Y[(size_t)EMB*BNP]; // conv output [e][p], 64 MB
__device__ float d_x12[BB*2*EMB];
__device__ float d_h512[BB*512];
__device__ float d_h256[BB*256];
__device__ float d_sumA[4*CH], d_sqA[4*CH];
__device__ float d_sumB[CH], d_sqB[CH];
__device__ float d_sumY[EMB], d_sqY[EMB];    // conv BN stats (fused in epilogue)
__device__ __nv_bfloat16 d_Ahi[EMB*FD], d_Alo[EMB*FD];
__device__ __nv_bfloat16 d_Fhi[BNP*FD], d_Flo[BNP*FD];

// ---------------- warp-MMA / cp.async helpers (sm_80+ baseline PTX) ----------
__device__ __forceinline__ uint32_t smem_u32(const void* p) {
    uint32_t a;
    asm("{ .reg .u64 t; cvta.to.shared.u64 t, %1; cvt.u32.u64 %0, t; }" : "=r"(a) : "l"(p));
    return a;
}
__device__ __forceinline__ void ldm_x4(uint32_t* r, uint32_t addr) {
    asm volatile("ldmatrix.sync.aligned.m8n8.x4.shared.b16 {%0,%1,%2,%3}, [%4];"
        : "=r"(r[0]), "=r"(r[1]), "=r"(r[2]), "=r"(r[3]) : "r"(addr));
}
__device__ __forceinline__ void mma16816(float* c, const uint32_t* a, const uint32_t* b) {
    asm volatile(
        "mma.sync.aligned.m16n8k16.row.col.f32.bf16.bf16.f32 "
        "{%0,%1,%2,%3}, {%4,%5,%6,%7}, {%8,%9}, {%0,%1,%2,%3};"
        : "+f"(c[0]), "+f"(c[1]), "+f"(c[2]), "+f"(c[3])
        : "r"(a[0]), "r"(a[1]), "r"(a[2]), "r"(a[3]), "r"(b[0]), "r"(b[1]));
}
__device__ __forceinline__ void cp16(uint32_t sdst, const void* gsrc) {
    asm volatile("cp.async.cg.shared.global [%0], [%1], 16;" :: "r"(sdst), "l"(gsrc));
}
#define CP_COMMIT() asm volatile("cp.async.commit_group;" ::: "memory")
#define CP_WAIT0()  asm volatile("cp.async.wait_group 0;" ::: "memory")

// ---------------- init ----------------
__global__ void k_init() {
    int t = blockIdx.x*256 + threadIdx.x;
    if (t < BNP) d_deg[t] = 0;
    if (t < 4*CH) { d_sumA[t] = 0.f; d_sqA[t] = 0.f; }
    if (t < CH)   { d_sumB[t] = 0.f; d_sqB[t] = 0.f; }
    if (t < EMB)  { d_sumY[t] = 0.f; d_sqY[t] = 0.f; }
}

// pts[b,c,n] = x[b, (c*N+n)%3, (c*N+n)/3]
__global__ void k_prep(const float* __restrict__ x) {
    int t = blockIdx.x*256 + threadIdx.x;
    if (t >= BNP) return;
    int b = t >> 11, n = t & 2047;
    const float* xb = x + b*3*NPT;
    float v[3]; float acc = 0.f;
    #pragma unroll
    for (int c = 0; c < 3; c++) {
        int L = c*NPT + n;
        v[c] = xb[(L % 3)*NPT + (L / 3)];
        acc += v[c]*v[c];
    }
    d_P4[t] = make_float4(v[0], v[1], v[2], acc);
}

__device__ __forceinline__ unsigned fkey(float f) {
    unsigned u = __float_as_uint(f);
    return (u & 0x80000000u) ? ~u : (u | 0x80000000u);
}

// identical arithmetic in both KNN passes (explicit intrinsics -> deterministic)
__device__ __forceinline__ float pdist(float4 q, float4 pm) {
    float dot = __fmaf_rn(q.x, pm.x, __fmaf_rn(q.y, pm.y, __fmul_rn(q.z, pm.z)));
    return __fadd_rn(__fmaf_rn(2.f, dot, -q.w), -pm.w);
}

// ---------------- knn: two-pass threshold + ballot compaction (exact) --------
__global__ void __launch_bounds__(256) k_knn() {
    __shared__ float4 sP[NPT];           // 32 KB
    __shared__ float sv[8][128];         // survivor values per warp
    __shared__ int   si[8][128];         // survivor indices per warp
    int b = blockIdx.x >> 7;             // 8 batches x 128 chunks
    int chunk = blockIdx.x & 127;        // 16 rows per chunk
    for (int i = threadIdx.x; i < NPT; i += 256)
        sP[i] = d_P4[b*NPT + i];
    __syncthreads();

    int warp = threadIdx.x >> 5, lane = threadIdx.x & 31;
    for (int r = 0; r < 2; r++) {
        int n = chunk*16 + warp*2 + r;
        float4 q = sP[n];

        // pass A: per-lane max of pd (4 independent accumulators)
        float a0 = -FLT_MAX, a1 = -FLT_MAX, a2 = -FLT_MAX, a3 = -FLT_MAX;
        for (int m = lane; m < NPT; m += 128) {
            a0 = fmaxf(a0, pdist(q, sP[m]));
            a1 = fmaxf(a1, pdist(q, sP[m + 32]));
            a2 = fmaxf(a2, pdist(q, sP[m + 64]));
            a3 = fmaxf(a3, pdist(q, sP[m + 96]));
        }
        float vmax = fmaxf(fmaxf(a0, a1), fmaxf(a2, a3));

        // tau = 20th largest of the 32 lane maxima (pop loop, duplicates counted)
        unsigned mykey = fkey(vmax);
        unsigned tkey = 0;
        #pragma unroll 1
        for (int k = 0; k < KNN; k++) {
            tkey = __reduce_max_sync(0xffffffffu, mykey);
            unsigned msk = __ballot_sync(0xffffffffu, mykey == tkey);
            if (lane == __ffs(msk) - 1) mykey = 0;
        }
        float tval = (tkey & 0x80000000u) ? __uint_as_float(tkey & 0x7fffffffu)
                                          : __uint_as_float(~tkey);

        // pass B: compact survivors (pd >= tval) into shared buffer
        int base = 0;
        for (int m = lane; m < NPT; m += 32) {
            float pd = pdist(q, sP[m]);
            bool s = (pd >= tval);
            unsigned msk = __ballot_sync(0xffffffffu, s);
            if (s) {
                int pos = base + __popc(msk & ((1u << lane) - 1));
                if (pos < 128) { sv[warp][pos] = pd; si[warp][pos] = m; }
            }
            base += __popc(msk);
        }
        __syncwarp();
        int S = base < 128 ? base : 128;

        // distribute <=4 survivors per lane, sort desc by (value, index asc)
        float v[4]; int id[4];
        #pragma unroll
        for (int j = 0; j < 4; j++) {
            int idx = lane + j*32;
            if (idx < S) { v[j] = sv[warp][idx]; id[j] = si[warp][idx]; }
            else         { v[j] = -FLT_MAX;      id[j] = 0x7fffffff; }
        }
        #define CE(A_, B_) { \
            bool sw_ = (v[B_] > v[A_]) || (v[B_] == v[A_] && id[B_] < id[A_]); \
            if (sw_) { float tv_ = v[A_]; v[A_] = v[B_]; v[B_] = tv_; \
                       int ti_ = id[A_]; id[A_] = id[B_]; id[B_] = ti_; } }
        CE(0,1) CE(2,3) CE(0,2) CE(1,3) CE(1,2)
        #undef CE

        // exact top-20 pop merge (value desc, index asc = lax.top_k ties)
        int pg = b*NPT + n;
        #pragma unroll 1
        for (int k = 0; k < KNN; k++) {
            unsigned mk = fkey(v[0]);
            unsigned best = __reduce_max_sync(0xffffffffu, mk);
            int cand = (mk == best) ? id[0] : 0x7fffffff;
            int bmi = __reduce_min_sync(0xffffffffu, cand);
            if (mk == best && id[0] == bmi) {
                v[0] = v[1]; id[0] = id[1];
                v[1] = v[2]; id[1] = id[2];
                v[2] = v[3]; id[2] = id[3];
                v[3] = -FLT_MAX; id[3] = 0x7fffffff;
            }
            if (lane == 0) {
                int qg = b*NPT + bmi;
                d_nbr[pg*KNN + k] = qg;
                atomicAdd(&d_deg[qg], 1);
            }
        }
        __syncwarp();   // sv/si reused next row
    }
}

// exclusive scan of 16384 degrees (single block, int4 loads)
__global__ void k_scan() {
    int t = threadIdx.x;
    int loc[16]; int s = 0;
    const int4* dg4 = (const int4*)d_deg;
    int4 q[4];
    #pragma unroll
    for (int i = 0; i < 4; i++) q[i] = dg4[t*4 + i];
    const int* qq = (const int*)q;
    #pragma unroll
    for (int i = 0; i < 16; i++) { loc[i] = s; s += qq[i]; }
    int lane = t & 31, wid = t >> 5;
    int vv = s;
    #pragma unroll
    for (int o = 1; o < 32; o <<= 1) { int u = __shfl_up_sync(0xffffffffu, vv, o); if (lane >= o) vv += u; }
    __shared__ int ws[32];
    if (lane == 31) ws[wid] = vv;
    __syncthreads();
    if (wid == 0) {
        int w = ws[lane];
        #pragma unroll
        for (int o = 1; o < 32; o <<= 1) { int u = __shfl_up_sync(0xffffffffu, w, o); if (lane >= o) w += u; }
        ws[lane] = w;
    }
    __syncthreads();
    int excl = vv - s + (wid ? ws[wid-1] : 0);
    int base = t*16;
    #pragma unroll
    for (int i = 0; i < 16; i++) { int rs = excl + loc[i]; d_rowstart[base+i] = rs; d_cursor[base+i] = rs; }
    if (t == 1023) d_rowstart[BNP] = excl + s;
}

__global__ void k_fill() {
    int p = blockIdx.x*256 + threadIdx.x;
    if (p >= BNP) return;
    #pragma unroll
    for (int k = 0; k < KNN; k++) {
        int q = d_nbr[p*KNN + k];
        int pos = atomicAdd(&d_cursor[q], 1);
        d_rev[pos] = p;
    }
}

// ---------------- layer 0: sup0 = flat@w0 ; rz = flat@wr + br (+ rz stats) ----
__global__ void k_l0mm(const float* __restrict__ x, const float* __restrict__ w0,
                       const float* __restrict__ wr, const float* __restrict__ br) {
    int tid = threadIdx.x;
    int t = blockIdx.x*256 + tid;
    int p = t >> 6, c = t & 63;
    int b = p >> 11, n = p & 2047;
    const float* xb = x + b*3*NPT;
    float x0 = xb[n], x1 = xb[NPT + n], x2 = xb[2*NPT + n];
    d_sup[t] = x0*w0[c] + x1*w0[64+c] + x2*w0[128+c];
    float rz = x0*wr[c] + x1*wr[64+c] + x2*wr[128+c] + br[c];
    d_rz[t] = rz;
    __shared__ float s1[256], s2[256];
    s1[tid] = rz; s2[tid] = rz*rz;
    __syncthreads();
    if (tid < 64) {
        float a = s1[tid] + s1[64+tid] + s1[128+tid] + s1[192+tid];
        float q = s2[tid] + s2[64+tid] + s2[128+tid] + s2[192+tid];
        atomicAdd(&d_sumB[tid], a);
        atomicAdd(&d_sqB[tid], q);
    }
}

// ---------------- gather (reverse CSR) + bias + z stats ----------------
__global__ void k_gather_stats(const float* __restrict__ bias, int layer) {
    int t = threadIdx.x;
    int q = blockIdx.x*4 + (t >> 6);
    int c = t & 63;
    float acc = bias[c];
    int s0 = d_rowstart[q], e0 = d_rowstart[q+1];
    for (int i = s0; i < e0; i++) acc += d_sup[d_rev[i]*64 + c];
    d_z[q*64 + c] = acc;
    __shared__ float s1[256], s2[256];
    s1[t] = acc; s2[t] = acc*acc;
    __syncthreads();
    if (t < 64) {
        float a = s1[t] + s1[64+t] + s1[128+t] + s1[192+t];
        float qq = s2[t] + s2[64+t] + s2[128+t] + s2[192+t];
        atomicAdd(&d_sumA[layer*64 + t], a);
        atomicAdd(&d_sqA[layer*64 + t], qq);
    }
}

// ---------------- fused post (layer 0) + mm for layer 1 ----------------
__global__ void __launch_bounds__(256) k_post0_mm(
        const float* __restrict__ g0, const float* __restrict__ be0,
        const float* __restrict__ gr, const float* __restrict__ ber,
        const float* __restrict__ W1) {
    __shared__ float Hs[64*64];
    __shared__ float Ws[64*64];
    int tid = threadIdx.x;
    int p0 = blockIdx.x*64;
    int c = tid & 63, rg = tid >> 6;
    float mA = d_sumA[c]*(1.f/BNP);
    float vA = d_sqA[c]*(1.f/BNP) - mA*mA;
    float sA = rsqrtf(vA + 1e-5f)*g0[c], bA = be0[c];
    float mB = d_sumB[c]*(1.f/BNP);
    float vB = d_sqB[c]*(1.f/BNP) - mB*mB;
    float sB = rsqrtf(vB + 1e-5f)*gr[c], bB = ber[c];
    #pragma unroll
    for (int i = 0; i < 16; i++) {
        int r = rg + i*4, p = p0 + r;
        float o = fmaxf((d_z[p*64+c] - mA)*sA + bA, 0.f);
        float rr = (d_rz[p*64+c] - mB)*sB + bB;
        float h = fmaxf(o + rr, 0.f);
        Hs[r*64+c] = h;
        d_F[p*FD + c] = h;
        __nv_bfloat16 hi = __float2bfloat16(h);
        d_Fhi[p*FD + c] = hi;
        d_Flo[p*FD + c] = __float2bfloat16(h - __bfloat162float(hi));
    }
    for (int i = tid; i < 4096; i += 256) Ws[i] = W1[i];
    __syncthreads();
    for (int r = rg; r < 64; r += 4) {
        float acc = 0.f;
        #pragma unroll 16
        for (int k = 0; k < 64; k++) acc += Hs[r*64+k]*Ws[k*64+c];
        d_sup[(p0+r)*64+c] = acc;
    }
}

// ---------------- fused post (layers 1,2) + mm for next layer ----------------
__global__ void __launch_bounds__(256) k_postL_mm(int layer,
        const float* __restrict__ G, const float* __restrict__ Be,
        const float* __restrict__ Wn) {
    __shared__ float Hs[64*64];
    __shared__ float Ws[64*64];
    int tid = threadIdx.x;
    int p0 = blockIdx.x*64;
    int c = tid & 63, rg = tid >> 6;
    float m = d_sumA[layer*64+c]*(1.f/BNP);
    float v = d_sqA[layer*64+c]*(1.f/BNP) - m*m;
    float sc = rsqrtf(v + 1e-5f)*G[c], bc = Be[c];
    #pragma unroll
    for (int i = 0; i < 16; i++) {
        int r = rg + i*4, p = p0 + r;
        float a = fmaxf((d_z[p*64+c] - m)*sc + bc, 0.f);
        float h = fmaxf(a + d_F[p*FD + (layer-1)*64 + c], 0.f);
        Hs[r*64+c] = h;
        d_F[p*FD + layer*64 + c] = h;
        __nv_bfloat16 hi = __float2bfloat16(h);
        d_Fhi[p*FD + layer*64 + c] = hi;
        d_Flo[p*FD + layer*64 + c] = __float2bfloat16(h - __bfloat162float(hi));
    }
    for (int i = tid; i < 4096; i += 256) Ws[i] = Wn[i];
    __syncthreads();
    for (int r = rg; r < 64; r += 4) {
        float acc = 0.f;
        #pragma unroll 16
        for (int k = 0; k < 64; k++) acc += Hs[r*64+k]*Ws[k*64+c];
        d_sup[(p0+r)*64+c] = acc;
    }
}

// ---------------- post layer 3 ----------------
__global__ void k_post3(const float* __restrict__ G, const float* __restrict__ Be) {
    int t = blockIdx.x*256 + threadIdx.x;
    int p = t >> 6, c = t & 63;
    float m = d_sumA[3*64+c]*(1.f/BNP);
    float v = d_sqA[3*64+c]*(1.f/BNP) - m*m;
    float a = fmaxf((d_z[t] - m)*rsqrtf(v + 1e-5f)*G[c] + Be[c], 0.f);
    float h = fmaxf(a + d_F[p*FD + 2*64 + c], 0.f);
    __nv_bfloat16 hi = __float2bfloat16(h);
    d_Fhi[p*FD + 3*64 + c] = hi;
    d_Flo[p*FD + 3*64 + c] = __float2bfloat16(h - __bfloat162float(hi));
}

// ---------------- bf16 hi/lo conversion of wconv ----------------
__global__ void k_cvtA(const float* __restrict__ w) {
    int t = blockIdx.x*256 + threadIdx.x;
    float4 x = ((const float4*)w)[t];
    __nv_bfloat16 h0 = __float2bfloat16(x.x), h1 = __float2bfloat16(x.y);
    __nv_bfloat16 h2 = __float2bfloat16(x.z), h3 = __float2bfloat16(x.w);
    __nv_bfloat16 l0 = __float2bfloat16(x.x - __bfloat162float(h0));
    __nv_bfloat16 l1 = __float2bfloat16(x.y - __bfloat162float(h1));
    __nv_bfloat16 l2 = __float2bfloat16(x.z - __bfloat162float(h2));
    __nv_bfloat16 l3 = __float2bfloat16(x.w - __bfloat162float(h3));
    ((__nv_bfloat162*)d_Ahi)[t*2]   = __nv_bfloat162(h0, h1);
    ((__nv_bfloat162*)d_Ahi)[t*2+1] = __nv_bfloat162(h2, h3);
    ((__nv_bfloat162*)d_Alo)[t*2]   = __nv_bfloat162(l0, l1);
    ((__nv_bfloat162*)d_Alo)[t*2+1] = __nv_bfloat162(l2, l3);
}

// ---------------- conv GEMM via mma.sync, cp.async 2-stage, fused BN stats ---
#define PITCH 80
#define TSZ   (128*PITCH)
#define STAGE (4*TSZ)
#define SMEM_CONV (2*STAGE)

__global__ void __launch_bounds__(256) k_conv_mma() {
    extern __shared__ __align__(16) uint8_t sm[];
    uint32_t sb = smem_u32(sm);

    int tid = threadIdx.x, wid = tid >> 5, lane = tid & 31;
    int warp_m = wid >> 2, warp_n = wid & 3;
    int bn = blockIdx.x;
    int bm = blockIdx.y;

    const uint4* gAhi = (const uint4*)d_Ahi;
    const uint4* gAlo = (const uint4*)d_Alo;
    const uint4* gBhi = (const uint4*)d_Fhi;
    const uint4* gBlo = (const uint4*)d_Flo;

    float C[4][4][4];
    #pragma unroll
    for (int i = 0; i < 4; i++)
        #pragma unroll
        for (int j = 0; j < 4; j++)
            #pragma unroll
            for (int q = 0; q < 4; q++) C[i][j][q] = 0.f;

    int rowA  = warp_m*64 + (lane & 15);
    int halfA = lane >> 4;
    uint32_t oAhi = rowA*PITCH + halfA*16;
    uint32_t oAlo = TSZ + rowA*PITCH + halfA*16;
    int rowB  = warp_n*32 + (lane & 7) + ((lane >> 4) << 3);
    int halfB = (lane >> 3) & 1;
    uint32_t oBhi = 2*TSZ + rowB*PITCH + halfB*16;
    uint32_t oBlo = 3*TSZ + rowB*PITCH + halfB*16;

    auto issue = [&](int kc, int s) {
        uint32_t base = sb + s*STAGE;
        #pragma unroll
        for (int l = 0; l < 2; l++) {
            int i = tid + l*256;
            int row = i >> 2, c = i & 3;
            uint32_t so = row*PITCH + c*16;
            size_t ga = (size_t)(bm*128 + row)*32 + kc*4 + c;
            size_t gb = (size_t)(bn*128 + row)*32 + kc*4 + c;
            cp16(base + so,          gAhi + ga);
            cp16(base + TSZ + so,    gAlo + ga);
            cp16(base + 2*TSZ + so,  gBhi + gb);
            cp16(base + 3*TSZ + so,  gBlo + gb);
        }
        CP_COMMIT();
    };

    issue(0, 0);
    for (int kc = 0; kc < 8; kc++) {
        int s = kc & 1;
        CP_WAIT0();
        __syncthreads();
        if (kc + 1 < 8) issue(kc + 1, s ^ 1);
        uint32_t stb = sb + s*STAGE;

        #pragma unroll
        for (int ksub = 0; ksub < 2; ksub++) {
            uint32_t koff = (ksub*2)*16;
            uint32_t bh[8], bl[8];
            ldm_x4(bh + 0, stb + oBhi + koff);
            ldm_x4(bh + 4, stb + oBhi + koff + 16*PITCH);
            ldm_x4(bl + 0, stb + oBlo + koff);
            ldm_x4(bl + 4, stb + oBlo + koff + 16*PITCH);
            #pragma unroll
            for (int mt = 0; mt < 4; mt++) {
                uint32_t ah[4], al[4];
                ldm_x4(ah, stb + oAhi + koff + mt*16*PITCH);
                ldm_x4(al, stb + oAlo + koff + mt*16*PITCH);
                #pragma unroll
                for (int nt = 0; nt < 4; nt++) {
                    const uint32_t* ph = &bh[(nt >> 1)*4 + (nt & 1)*2];
                    const uint32_t* pl = &bl[(nt >> 1)*4 + (nt & 1)*2];
                    mma16816(C[mt][nt], ah, ph);
                    mma16816(C[mt][nt], ah, pl);
                    mma16816(C[mt][nt], al, ph);
                }
            }
        }
        __syncthreads();
    }

    // epilogue: store + fused per-e BN partial stats (quad reduce + RED)
    #pragma unroll
    for (int mt = 0; mt < 4; mt++) {
        int e = bm*128 + warp_m*64 + mt*16 + (lane >> 2);
        float s0 = 0.f, q0 = 0.f, s1 = 0.f, q1 = 0.f;
        #pragma unroll
        for (int nt = 0; nt < 4; nt++) {
            int p = bn*128 + warp_n*32 + nt*8 + (lane & 3)*2;
            float a0 = C[mt][nt][0], a1 = C[mt][nt][1];
            float a2 = C[mt][nt][2], a3 = C[mt][nt][3];
            *(float2*)&d_Y[(size_t)e*BNP + p]       = make_float2(a0, a1);
            *(float2*)&d_Y[(size_t)(e + 8)*BNP + p] = make_float2(a2, a3);
            s0 += a0 + a1; q0 += a0*a0 + a1*a1;
            s1 += a2 + a3; q1 += a2*a2 + a3*a3;
        }
        #pragma unroll
        for (int o = 1; o < 4; o <<= 1) {
            s0 += __shfl_xor_sync(0xffffffffu, s0, o);
            q0 += __shfl_xor_sync(0xffffffffu, q0, o);
            s1 += __shfl_xor_sync(0xffffffffu, s1, o);
            q1 += __shfl_xor_sync(0xffffffffu, q1, o);
        }
        if ((lane & 3) == 0) {
            atomicAdd(&d_sumY[e], s0);     atomicAdd(&d_sqY[e], q0);
            atomicAdd(&d_sumY[e + 8], s1); atomicAdd(&d_sqY[e + 8], q1);
        }
    }
}

// ---------------- conv BN + leaky + pooling (single pass, stats precomputed) --
__global__ void k_reduce(const float* __restrict__ gf, const float* __restrict__ bef) {
    int e = blockIdx.x;
    const float* y = d_Y + (size_t)e*BNP;
    int t = threadIdx.x, lane = t & 31, w = t >> 5;
    float mu = d_sumY[e]*(1.f/BNP);
    float var = d_sqY[e]*(1.f/BNP) - mu*mu;
    float sc = rsqrtf(var + 1e-5f)*gf[e], sh = bef[e];
    __shared__ float w1a[8], w2a[8];
    for (int b = 0; b < BB; b++) {
        float mx = -FLT_MAX, sm = 0.f;
        for (int j = t; j < NPT; j += 256) {
            float v = y[b*NPT + j];
            v = (v - mu)*sc + sh;
            v = v > 0.f ? v : 0.2f*v;
            mx = fmaxf(mx, v); sm += v;
        }
        #pragma unroll
        for (int o = 16; o; o >>= 1) {
            mx = fmaxf(mx, __shfl_xor_sync(0xffffffffu, mx, o));
            sm += __shfl_xor_sync(0xffffffffu, sm, o);
        }
        if (lane == 0) { w1a[w] = mx; w2a[w] = sm; }
        __syncthreads();
        if (t == 0) {
            float MX = w1a[0], SM = w2a[0];
            #pragma unroll
            for (int i = 1; i < 8; i++) { MX = fmaxf(MX, w1a[i]); SM += w2a[i]; }
            d_x12[b*2*EMB + e] = MX;
            d_x12[b*2*EMB + EMB + e] = SM*(1.f/NPT);
        }
        __syncthreads();
    }
}

// ---------------- head (k-split parallel) ----------------
__global__ void k_head1(const float* __restrict__ w1, const float* __restrict__ g6,
                        const float* __restrict__ b6) {
    int jl = threadIdx.x & 15, ks = threadIdx.x >> 4;
    int j = blockIdx.x*16 + jl;
    float acc[BB];
    #pragma unroll
    for (int b = 0; b < BB; b++) acc[b] = 0.f;
    for (int k = ks*128; k < ks*128 + 128; k++) {
        float wv = w1[k*512 + j];
        #pragma unroll
        for (int b = 0; b < BB; b++) acc[b] += d_x12[b*2*EMB + k]*wv;
    }
    __shared__ float sh[16][16][BB];
    #pragma unroll
    for (int b = 0; b < BB; b++) sh[ks][jl][b] = acc[b];
    __syncthreads();
    if (ks == 0) {
        #pragma unroll
        for (int b = 0; b < BB; b++) {
            float s = 0.f;
            #pragma unroll
            for (int i = 0; i < 16; i++) s += sh[i][jl][b];
            acc[b] = s;
        }
        float m = 0.f;
        #pragma unroll
        for (int b = 0; b < BB; b++) m += acc[b];
        m *= (1.f/BB);
        float var = 0.f;
        #pragma unroll
        for (int b = 0; b < BB; b++) { float d = acc[b]-m; var += d*d; }
        var *= (1.f/BB);
        float sc = rsqrtf(var + 1e-5f)*g6[j], bb = b6[j];
        #pragma unroll
        for (int b = 0; b < BB; b++) {
            float o = (acc[b]-m)*sc + bb;
            d_h512[b*512 + j] = o > 0.f ? o : 0.2f*o;
        }
    }
}

__global__ void k_head2(const float* __restrict__ w2, const float* __restrict__ b2,
                        const float* __restrict__ g7, const float* __restrict__ b7) {
    int jl = threadIdx.x & 31, ks = threadIdx.x >> 5;
    int j = blockIdx.x*32 + jl;
    float acc[BB];
    #pragma unroll
    for (int b = 0; b < BB; b++) acc[b] = 0.f;
    for (int k = ks*64; k < ks*64 + 64; k++) {
        float wv = w2[k*256 + j];
        #pragma unroll
        for (int b = 0; b < BB; b++) acc[b] += d_h512[b*512 + k]*wv;
    }
    __shared__ float sh[8][32][BB];
    #pragma unroll
    for (int b = 0; b < BB; b++) sh[ks][jl][b] = acc[b];
    __syncthreads();
    if (ks == 0) {
        #pragma unroll
        for (int b = 0; b < BB; b++) {
            float s = 0.f;
            #pragma unroll
            for (int i = 0; i < 8; i++) s += sh[i][jl][b];
            acc[b] = s + b2[j];
        }
        float m = 0.f;
        #pragma unroll
        for (int b = 0; b < BB; b++) m += acc[b];
        m *= (1.f/BB);
        float var = 0.f;
        #pragma unroll
        for (int b = 0; b < BB; b++) { float d = acc[b]-m; var += d*d; }
        var *= (1.f/BB);
        float sc = rsqrtf(var + 1e-5f)*g7[j], bb = b7[j];
        #pragma unroll
        for (int b = 0; b < BB; b++) {
            float o = (acc[b]-m)*sc + bb;
            d_h256[b*256 + j] = o > 0.f ? o : 0.2f*o;
        }
    }
}

__global__ void k_head3(const float* __restrict__ w3, const float* __restrict__ b3,
                        float* __restrict__ out) {
    int jl = threadIdx.x & 63, ks = threadIdx.x >> 6;
    float acc[BB];
    #pragma unroll
    for (int b = 0; b < BB; b++) acc[b] = 0.f;
    if (jl < 40) {
        for (int k = ks*64; k < ks*64 + 64; k++) {
            float wv = w3[k*40 + jl];
            #pragma unroll
            for (int b = 0; b < BB; b++) acc[b] += d_h256[b*256 + k]*wv;
        }
    }
    __shared__ float sh[4][64][BB];
    #pragma unroll
    for (int b = 0; b < BB; b++) sh[ks][jl][b] = acc[b];
    __syncthreads();
    if (ks == 0 && jl < 40) {
        #pragma unroll
        for (int b = 0; b < BB; b++) {
            float s = b3[jl];
            #pragma unroll
            for (int i = 0; i < 4; i++) s += sh[i][jl][b];
            out[b*40 + jl] = s;
        }
    }
}

// ---------------- launch ----------------
extern "C" void kernel_launch(void* const* d_in, const int* in_sizes, int n_in,
                              void* d_out, int out_size) {
    const float* x     = (const float*)d_in[0];
    const float* w0    = (const float*)d_in[1];
    const float* b0    = (const float*)d_in[2];
    const float* g0    = (const float*)d_in[3];
    const float* be0   = (const float*)d_in[4];
    const float* wr    = (const float*)d_in[5];
    const float* br    = (const float*)d_in[6];
    const float* gr    = (const float*)d_in[7];
    const float* ber   = (const float*)d_in[8];
    const float* W     = (const float*)d_in[9];
    const float* Bv    = (const float*)d_in[10];
    const float* G     = (const float*)d_in[11];
    const float* Be    = (const float*)d_in[12];
    const float* wconv = (const float*)d_in[13];
    const float* gf    = (const float*)d_in[14];
    const float* bef   = (const float*)d_in[15];
    const float* w1    = (const float*)d_in[16];
    const float* g6    = (const float*)d_in[17];
    const float* b6    = (const float*)d_in[18];
    const float* w2    = (const float*)d_in[19];
    const float* b2    = (const float*)d_in[20];
    const float* g7    = (const float*)d_in[21];
    const float* b7    = (const float*)d_in[22];
    const float* w3    = (const float*)d_in[23];
    const float* b3    = (const float*)d_in[24];
    float* out = (float*)d_out;

    static int smem_set = 0;
    if (!smem_set) {
        cudaFuncSetAttribute(k_conv_mma, cudaFuncAttributeMaxDynamicSharedMemorySize, SMEM_CONV);
        smem_set = 1;
    }

    // graph build (k_knn kept in the ncu capture slot)
    k_init<<<64, 256>>>();
    k_prep<<<64, 256>>>(x);
    k_cvtA<<<256, 256>>>(wconv);
    k_knn<<<1024, 256>>>();
    k_scan<<<1, 1024>>>();
    k_fill<<<64, 256>>>();

    // layer 0
    k_l0mm<<<4096, 256>>>(x, w0, wr, br);
    k_gather_stats<<<4096, 256>>>(b0, 0);
    k_post0_mm<<<256, 256>>>(g0, be0, gr, ber, W);

    // layers 1..3
    k_gather_stats<<<4096, 256>>>(Bv, 1);
    k_postL_mm<<<256, 256>>>(1, G, Be, W + 4096);
    k_gather_stats<<<4096, 256>>>(Bv + 64, 2);
    k_postL_mm<<<256, 256>>>(2, G + 64, Be + 64, W + 8192);
    k_gather_stats<<<4096, 256>>>(Bv + 128, 3);
    k_post3<<<4096, 256>>>(G + 128, Be + 128);

    // conv 256 -> 1024 + fused BN stats, then single-pass BN+leaky+pool
    dim3 cgrid(128, 8);
    k_conv_mma<<<cgrid, 256, SMEM_CONV>>>();
    k_reduce<<<1024, 256>>>(gf, bef);

    // head
    k_head1<<<32, 256>>>(w1, g6, b6);
    k_head2<<<8, 256>>>(w2, b2, g7, b7);
    k_head3<<<1, 256>>>(w3, b3, out);
}

// round 9
// speedup vs baseline: 9.6880x; 1.0502x over previous
#include <cuda_runtime.h>
#include <cuda_fp16.h>
#include <float.h>
#include <stdint.h>

// ---------------- problem constants ----------------
#define BB    8
#define NPT   2048
#define BNP   16384          // BB*NPT
#define KNN   20
#define CH    64
#define FD    256            // 4*CH
#define EMB   1024

// ---------------- scratch (device globals; no mallocs allowed) ----------------
__device__ float4 d_P4[BB*NPT];
__device__ int   d_nbr[BNP*KNN];
__device__ int   d_deg[BNP];
__device__ int   d_rowstart[BNP+1];
__device__ int   d_cursor[BNP];
__device__ int   d_bsum[16];
__device__ int   d_rev[BNP*KNN];
__device__ float d_F[BNP*FD];
__device__ float d_sup[BNP*CH];
__device__ float d_z[BNP*CH];
__device__ float d_rz[BNP*CH];
__device__ float d_Y[(size_t)EMB*BNP]; // conv output [e][p], 64 MB
__device__ float d_x12[BB*2*EMB];
__device__ float d_h512[BB*512];
__device__ float d_h256[BB*256];
__device__ float d_sumA[4*CH], d_sqA[4*CH];
__device__ float d_sumB[CH], d_sqB[CH];
__device__ float d_sumY[EMB], d_sqY[EMB];
__device__ __half d_Ah[EMB*FD], d_Al[EMB*FD];   // wconv fp16 hi/lo
__device__ __half d_Fh[BNP*FD], d_Fl[BNP*FD];   // features fp16 hi/lo

// ---------------- warp-MMA / cp.async helpers (sm_80+ baseline PTX) ----------
__device__ __forceinline__ uint32_t smem_u32(const void* p) {
    uint32_t a;
    asm("{ .reg .u64 t; cvta.to.shared.u64 t, %1; cvt.u32.u64 %0, t; }" : "=r"(a) : "l"(p));
    return a;
}
__device__ __forceinline__ void ldm_x4(uint32_t* r, uint32_t addr) {
    asm volatile("ldmatrix.sync.aligned.m8n8.x4.shared.b16 {%0,%1,%2,%3}, [%4];"
        : "=r"(r[0]), "=r"(r[1]), "=r"(r[2]), "=r"(r[3]) : "r"(addr));
}
__device__ __forceinline__ void mma16816h(float* c, const uint32_t* a, const uint32_t* b) {
    asm volatile(
        "mma.sync.aligned.m16n8k16.row.col.f32.f16.f16.f32 "
        "{%0,%1,%2,%3}, {%4,%5,%6,%7}, {%8,%9}, {%0,%1,%2,%3};"
        : "+f"(c[0]), "+f"(c[1]), "+f"(c[2]), "+f"(c[3])
        : "r"(a[0]), "r"(a[1]), "r"(a[2]), "r"(a[3]), "r"(b[0]), "r"(b[1]));
}
__device__ __forceinline__ void cp16(uint32_t sdst, const void* gsrc) {
    asm volatile("cp.async.cg.shared.global [%0], [%1], 16;" :: "r"(sdst), "l"(gsrc));
}
#define CP_COMMIT() asm volatile("cp.async.commit_group;" ::: "memory")
#define CP_WAIT0()  asm volatile("cp.async.wait_group 0;" ::: "memory")

// ---------------- init ----------------
__global__ void k_init() {
    int t = blockIdx.x*256 + threadIdx.x;
    if (t < BNP) d_deg[t] = 0;
    if (t < 4*CH) { d_sumA[t] = 0.f; d_sqA[t] = 0.f; }
    if (t < CH)   { d_sumB[t] = 0.f; d_sqB[t] = 0.f; }
    if (t < EMB)  { d_sumY[t] = 0.f; d_sqY[t] = 0.f; }
}

// pts[b,c,n] = x[b, (c*N+n)%3, (c*N+n)/3]
__global__ void k_prep(const float* __restrict__ x) {
    int t = blockIdx.x*256 + threadIdx.x;
    if (t >= BNP) return;
    int b = t >> 11, n = t & 2047;
    const float* xb = x + b*3*NPT;
    float v[3]; float acc = 0.f;
    #pragma unroll
    for (int c = 0; c < 3; c++) {
        int L = c*NPT + n;
        v[c] = xb[(L % 3)*NPT + (L / 3)];
        acc += v[c]*v[c];
    }
    d_P4[t] = make_float4(v[0], v[1], v[2], acc);
}

// ---------------- fp16 hi/lo conversion of wconv ----------------
__global__ void k_cvtA(const float* __restrict__ w) {
    int t = blockIdx.x*256 + threadIdx.x;   // < EMB*FD/4 = 65536
    float4 x = ((const float4*)w)[t];
    __half h0 = __float2half_rn(x.x), h1 = __float2half_rn(x.y);
    __half h2 = __float2half_rn(x.z), h3 = __float2half_rn(x.w);
    __half l0 = __float2half_rn(x.x - __half2float(h0));
    __half l1 = __float2half_rn(x.y - __half2float(h1));
    __half l2 = __float2half_rn(x.z - __half2float(h2));
    __half l3 = __float2half_rn(x.w - __half2float(h3));
    ((__half2*)d_Ah)[t*2]   = __half2(h0, h1);
    ((__half2*)d_Ah)[t*2+1] = __half2(h2, h3);
    ((__half2*)d_Al)[t*2]   = __half2(l0, l1);
    ((__half2*)d_Al)[t*2+1] = __half2(l2, l3);
}

__device__ __forceinline__ unsigned fkey(float f) {
    unsigned u = __float_as_uint(f);
    return (u & 0x80000000u) ? ~u : (u | 0x80000000u);
}

// identical arithmetic in both KNN passes (explicit intrinsics -> deterministic)
__device__ __forceinline__ float pdist(float4 q, float4 pm) {
    float dot = __fmaf_rn(q.x, pm.x, __fmaf_rn(q.y, pm.y, __fmul_rn(q.z, pm.z)));
    return __fadd_rn(__fmaf_rn(2.f, dot, -q.w), -pm.w);
}

// ---------------- knn: two-pass threshold, 2 rows per warp share loads -------
__global__ void __launch_bounds__(256) k_knn() {
    __shared__ float4 sP[NPT];               // 32 KB
    __shared__ float sv[8][2][128];
    __shared__ int   si[8][2][128];
    int b = blockIdx.x >> 7;                 // 8 batches x 128 chunks
    int chunk = blockIdx.x & 127;            // 16 rows per chunk
    for (int i = threadIdx.x; i < NPT; i += 256)
        sP[i] = d_P4[b*NPT + i];
    __syncthreads();

    int warp = threadIdx.x >> 5, lane = threadIdx.x & 31;
    int n0 = chunk*16 + warp*2;
    float4 q0 = sP[n0], q1 = sP[n0 + 1];

    // pass A: shared pm loads, per-lane maxes for both rows
    float m00 = -FLT_MAX, m01 = -FLT_MAX, m10 = -FLT_MAX, m11 = -FLT_MAX;
    for (int m = lane; m < NPT; m += 64) {
        float4 pa = sP[m], pb = sP[m + 32];
        m00 = fmaxf(m00, pdist(q0, pa)); m01 = fmaxf(m01, pdist(q0, pb));
        m10 = fmaxf(m10, pdist(q1, pa)); m11 = fmaxf(m11, pdist(q1, pb));
    }
    float vmax0 = fmaxf(m00, m01), vmax1 = fmaxf(m10, m11);

    // tau_r = 20th largest of 32 lane maxima
    float tval[2];
    #pragma unroll
    for (int r = 0; r < 2; r++) {
        unsigned mykey = fkey(r ? vmax1 : vmax0);
        unsigned tkey = 0;
        #pragma unroll 1
        for (int k = 0; k < KNN; k++) {
            tkey = __reduce_max_sync(0xffffffffu, mykey);
            unsigned msk = __ballot_sync(0xffffffffu, mykey == tkey);
            if (lane == __ffs(msk) - 1) mykey = 0;
        }
        tval[r] = (tkey & 0x80000000u) ? __uint_as_float(tkey & 0x7fffffffu)
                                       : __uint_as_float(~tkey);
    }

    // pass B: shared pm loads, compact survivors for both rows
    int base0 = 0, base1 = 0;
    for (int m = lane; m < NPT; m += 32) {
        float4 pm = sP[m];
        float pd0 = pdist(q0, pm);
        float pd1 = pdist(q1, pm);
        bool s0 = (pd0 >= tval[0]);
        unsigned k0 = __ballot_sync(0xffffffffu, s0);
        if (s0) {
            int pos = base0 + __popc(k0 & ((1u << lane) - 1));
            if (pos < 128) { sv[warp][0][pos] = pd0; si[warp][0][pos] = m; }
        }
        base0 += __popc(k0);
        bool s1 = (pd1 >= tval[1]);
        unsigned k1 = __ballot_sync(0xffffffffu, s1);
        if (s1) {
            int pos = base1 + __popc(k1 & ((1u << lane) - 1));
            if (pos < 128) { sv[warp][1][pos] = pd1; si[warp][1][pos] = m; }
        }
        base1 += __popc(k1);
    }
    __syncwarp();

    #pragma unroll 1
    for (int r = 0; r < 2; r++) {
        int S = (r ? base1 : base0);
        if (S > 128) S = 128;
        float v[4]; int id[4];
        #pragma unroll
        for (int j = 0; j < 4; j++) {
            int idx = lane + j*32;
            if (idx < S) { v[j] = sv[warp][r][idx]; id[j] = si[warp][r][idx]; }
            else         { v[j] = -FLT_MAX;         id[j] = 0x7fffffff; }
        }
        #define CE(A_, B_) { \
            bool sw_ = (v[B_] > v[A_]) || (v[B_] == v[A_] && id[B_] < id[A_]); \
            if (sw_) { float tv_ = v[A_]; v[A_] = v[B_]; v[B_] = tv_; \
                       int ti_ = id[A_]; id[A_] = id[B_]; id[B_] = ti_; } }
        CE(0,1) CE(2,3) CE(0,2) CE(1,3) CE(1,2)
        #undef CE

        int pg = b*NPT + n0 + r;
        #pragma unroll 1
        for (int k = 0; k < KNN; k++) {
            unsigned mk = fkey(v[0]);
            unsigned best = __reduce_max_sync(0xffffffffu, mk);
            int cand = (mk == best) ? id[0] : 0x7fffffff;
            int bmi = __reduce_min_sync(0xffffffffu, cand);
            if (mk == best && id[0] == bmi) {
                v[0] = v[1]; id[0] = id[1];
                v[1] = v[2]; id[1] = id[2];
                v[2] = v[3]; id[2] = id[3];
                v[3] = -FLT_MAX; id[3] = 0x7fffffff;
            }
            if (lane == 0) {
                int qg = b*NPT + bmi;
                d_nbr[pg*KNN + k] = qg;
                atomicAdd(&d_deg[qg], 1);
            }
        }
    }
}

// ---------------- parallel scan: block-local (16x1024) + offset apply --------
__global__ void k_scanA() {
    int t = threadIdx.x, g = blockIdx.x*1024 + t;
    int v = d_deg[g];
    int lane = t & 31, wid = t >> 5;
    int vv = v;
    #pragma unroll
    for (int o = 1; o < 32; o <<= 1) { int u = __shfl_up_sync(0xffffffffu, vv, o); if (lane >= o) vv += u; }
    __shared__ int ws[32];
    if (lane == 31) ws[wid] = vv;
    __syncthreads();
    if (wid == 0) {
        int w = ws[lane];
        #pragma unroll
        for (int o = 1; o < 32; o <<= 1) { int u = __shfl_up_sync(0xffffffffu, w, o); if (lane >= o) w += u; }
        ws[lane] = w;
    }
    __syncthreads();
    int incl = vv + (wid ? ws[wid-1] : 0);
    d_rowstart[g] = incl - v;            // block-local exclusive
    if (t == 1023) d_bsum[blockIdx.x] = incl;
}

__global__ void k_scanB() {
    int g = blockIdx.x*256 + threadIdx.x;
    int sb = g >> 10;
    int off = 0;
    #pragma unroll 1
    for (int i = 0; i < sb; i++) off += d_bsum[i];
    int rs = d_rowstart[g] + off;
    d_rowstart[g] = rs;
    d_cursor[g] = rs;
    if (g == BNP - 1) {
        int tot = 0;
        #pragma unroll
        for (int i = 0; i < 16; i++) tot += d_bsum[i];
        d_rowstart[BNP] = tot;
    }
}

__global__ void k_fill() {
    int p = blockIdx.x*256 + threadIdx.x;
    if (p >= BNP) return;
    #pragma unroll
    for (int k = 0; k < KNN; k++) {
        int q = d_nbr[p*KNN + k];
        int pos = atomicAdd(&d_cursor[q], 1);
        d_rev[pos] = p;
    }
}

// ---------------- layer 0: sup0 = flat@w0 ; rz = flat@wr + br (+ rz stats) ----
__global__ void k_l0mm(const float* __restrict__ x, const float* __restrict__ w0,
                       const float* __restrict__ wr, const float* __restrict__ br) {
    int tid = threadIdx.x;
    int t = blockIdx.x*256 + tid;
    int p = t >> 6, c = t & 63;
    int b = p >> 11, n = p & 2047;
    const float* xb = x + b*3*NPT;
    float x0 = xb[n], x1 = xb[NPT + n], x2 = xb[2*NPT + n];
    d_sup[t] = x0*w0[c] + x1*w0[64+c] + x2*w0[128+c];
    float rz = x0*wr[c] + x1*wr[64+c] + x2*wr[128+c] + br[c];
    d_rz[t] = rz;
    __shared__ float s1[256], s2[256];
    s1[tid] = rz; s2[tid] = rz*rz;
    __syncthreads();
    if (tid < 64) {
        float a = s1[tid] + s1[64+tid] + s1[128+tid] + s1[192+tid];
        float q = s2[tid] + s2[64+tid] + s2[128+tid] + s2[192+tid];
        atomicAdd(&d_sumB[tid], a);
        atomicAdd(&d_sqB[tid], q);
    }
}

// ---------------- gather (reverse CSR) + bias + z stats ----------------
__global__ void k_gather_stats(const float* __restrict__ bias, int layer) {
    int t = threadIdx.x;
    int q = blockIdx.x*4 + (t >> 6);
    int c = t & 63;
    float acc = bias[c];
    int s0 = d_rowstart[q], e0 = d_rowstart[q+1];
    for (int i = s0; i < e0; i++) acc += d_sup[d_rev[i]*64 + c];
    d_z[q*64 + c] = acc;
    __shared__ float s1[256], s2[256];
    s1[t] = acc; s2[t] = acc*acc;
    __syncthreads();
    if (t < 64) {
        float a = s1[t] + s1[64+t] + s1[128+t] + s1[192+t];
        float qq = s2[t] + s2[64+t] + s2[128+t] + s2[192+t];
        atomicAdd(&d_sumA[layer*64 + t], a);
        atomicAdd(&d_sqA[layer*64 + t], qq);
    }
}

// ---------------- fused post (layer 0) + mm for layer 1 ----------------
__global__ void __launch_bounds__(256) k_post0_mm(
        const float* __restrict__ g0, const float* __restrict__ be0,
        const float* __restrict__ gr, const float* __restrict__ ber,
        const float* __restrict__ W1) {
    __shared__ float Hs[64*64];
    __shared__ float Ws[64*64];
    int tid = threadIdx.x;
    int p0 = blockIdx.x*64;
    int c = tid & 63, rg = tid >> 6;
    float mA = d_sumA[c]*(1.f/BNP);
    float vA = d_sqA[c]*(1.f/BNP) - mA*mA;
    float sA = rsqrtf(vA + 1e-5f)*g0[c], bA = be0[c];
    float mB = d_sumB[c]*(1.f/BNP);
    float vB = d_sqB[c]*(1.f/BNP) - mB*mB;
    float sB = rsqrtf(vB + 1e-5f)*gr[c], bB = ber[c];
    #pragma unroll
    for (int i = 0; i < 16; i++) {
        int r = rg + i*4, p = p0 + r;
        float o = fmaxf((d_z[p*64+c] - mA)*sA + bA, 0.f);
        float rr = (d_rz[p*64+c] - mB)*sB + bB;
        float h = fmaxf(o + rr, 0.f);
        Hs[r*64+c] = h;
        d_F[p*FD + c] = h;
        __half hi = __float2half_rn(h);
        d_Fh[p*FD + c] = hi;
        d_Fl[p*FD + c] = __float2half_rn(h - __half2float(hi));
    }
    for (int i = tid; i < 4096; i += 256) Ws[i] = W1[i];
    __syncthreads();
    for (int r = rg; r < 64; r += 4) {
        float acc = 0.f;
        #pragma unroll 16
        for (int k = 0; k < 64; k++) acc += Hs[r*64+k]*Ws[k*64+c];
        d_sup[(p0+r)*64+c] = acc;
    }
}

// ---------------- fused post (layers 1,2) + mm for next layer ----------------
__global__ void __launch_bounds__(256) k_postL_mm(int layer,
        const float* __restrict__ G, const float* __restrict__ Be,
        const float* __restrict__ Wn) {
    __shared__ float Hs[64*64];
    __shared__ float Ws[64*64];
    int tid = threadIdx.x;
    int p0 = blockIdx.x*64;
    int c = tid & 63, rg = tid >> 6;
    float m = d_sumA[layer*64+c]*(1.f/BNP);
    float v = d_sqA[layer*64+c]*(1.f/BNP) - m*m;
    float sc = rsqrtf(v + 1e-5f)*G[c], bc = Be[c];
    #pragma unroll
    for (int i = 0; i < 16; i++) {
        int r = rg + i*4, p = p0 + r;
        float a = fmaxf((d_z[p*64+c] - m)*sc + bc, 0.f);
        float h = fmaxf(a + d_F[p*FD + (layer-1)*64 + c], 0.f);
        Hs[r*64+c] = h;
        d_F[p*FD + layer*64 + c] = h;
        __half hi = __float2half_rn(h);
        d_Fh[p*FD + layer*64 + c] = hi;
        d_Fl[p*FD + layer*64 + c] = __float2half_rn(h - __half2float(hi));
    }
    for (int i = tid; i < 4096; i += 256) Ws[i] = Wn[i];
    __syncthreads();
    for (int r = rg; r < 64; r += 4) {
        float acc = 0.f;
        #pragma unroll 16
        for (int k = 0; k < 64; k++) acc += Hs[r*64+k]*Ws[k*64+c];
        d_sup[(p0+r)*64+c] = acc;
    }
}

// ---------------- post layer 3 ----------------
__global__ void k_post3(const float* __restrict__ G, const float* __restrict__ Be) {
    int t = blockIdx.x*256 + threadIdx.x;
    int p = t >> 6, c = t & 63;
    float m = d_sumA[3*64+c]*(1.f/BNP);
    float v = d_sqA[3*64+c]*(1.f/BNP) - m*m;
    float a = fmaxf((d_z[t] - m)*rsqrtf(v + 1e-5f)*G[c] + Be[c], 0.f);
    float h = fmaxf(a + d_F[p*FD + 2*64 + c], 0.f);
    __half hi = __float2half_rn(h);
    d_Fh[p*FD + 3*64 + c] = hi;
    d_Fl[p*FD + 3*64 + c] = __float2half_rn(h - __half2float(hi));
}

// ---------------- conv GEMM: fp16 3-term split, cp.async 2-stage -------------
// C = Ah.Bh + Al.Bh + Ah.Bl  (error ~2^-22, fp32 accumulate)
#define PITCH 80
#define TSZ   (128*PITCH)     // 10240 B per tile
#define STAGE (4*TSZ)         // Ah, Al, Bh, Bl
#define SMEM_CONV (2*STAGE)   // 81920 B

__global__ void __launch_bounds__(256) k_conv_mma() {
    extern __shared__ __align__(16) uint8_t sm[];
    uint32_t sb = smem_u32(sm);

    int tid = threadIdx.x, wid = tid >> 5, lane = tid & 31;
    int warp_m = wid >> 2, warp_n = wid & 3;
    int bn = blockIdx.x;
    int bm = blockIdx.y;

    const uint4* gAh = (const uint4*)d_Ah;
    const uint4* gAl = (const uint4*)d_Al;
    const uint4* gBh = (const uint4*)d_Fh;
    const uint4* gBl = (const uint4*)d_Fl;

    float C[4][4][4];
    #pragma unroll
    for (int i = 0; i < 4; i++)
        #pragma unroll
        for (int j = 0; j < 4; j++)
            #pragma unroll
            for (int q = 0; q < 4; q++) C[i][j][q] = 0.f;

    int rowA  = warp_m*64 + (lane & 15);
    int halfA = lane >> 4;
    uint32_t oAh = rowA*PITCH + halfA*16;
    uint32_t oAl = TSZ + rowA*PITCH + halfA*16;
    int rowB  = warp_n*32 + (lane & 7) + ((lane >> 4) << 3);
    int halfB = (lane >> 3) & 1;
    uint32_t oBh = 2*TSZ + rowB*PITCH + halfB*16;
    uint32_t oBl = 3*TSZ + rowB*PITCH + halfB*16;

    auto issue = [&](int kc, int s) {
        uint32_t base = sb + s*STAGE;
        #pragma unroll
        for (int l = 0; l < 2; l++) {
            int i = tid + l*256;
            int row = i >> 2, c = i & 3;
            uint32_t so = row*PITCH + c*16;
            size_t ga = (size_t)(bm*128 + row)*32 + kc*4 + c;
            size_t gb = (size_t)(bn*128 + row)*32 + kc*4 + c;
            cp16(base + so,          gAh + ga);
            cp16(base + TSZ + so,    gAl + ga);
            cp16(base + 2*TSZ + so,  gBh + gb);
            cp16(base + 3*TSZ + so,  gBl + gb);
        }
        CP_COMMIT();
    };

    issue(0, 0);
    for (int kc = 0; kc < 8; kc++) {
        int s = kc & 1;
        CP_WAIT0();
        __syncthreads();
        if (kc + 1 < 8) issue(kc + 1, s ^ 1);
        uint32_t stb = sb + s*STAGE;

        #pragma unroll
        for (int ksub = 0; ksub < 2; ksub++) {
            uint32_t koff = (ksub*2)*16;
            uint32_t bh[8], bl[8];
            ldm_x4(bh + 0, stb + oBh + koff);
            ldm_x4(bh + 4, stb + oBh + koff + 16*PITCH);
            ldm_x4(bl + 0, stb + oBl + koff);
            ldm_x4(bl + 4, stb + oBl + koff + 16*PITCH);
            #pragma unroll
            for (int mt = 0; mt < 4; mt++) {
                uint32_t ah[4], al[4];
                ldm_x4(ah, stb + oAh + koff + mt*16*PITCH);
                ldm_x4(al, stb + oAl + koff + mt*16*PITCH);
                #pragma unroll
                for (int nt = 0; nt < 4; nt++) {
                    const uint32_t* ph = &bh[(nt >> 1)*4 + (nt & 1)*2];
                    const uint32_t* pl = &bl[(nt >> 1)*4 + (nt & 1)*2];
                    mma16816h(C[mt][nt], ah, ph);
                    mma16816h(C[mt][nt], al, ph);
                    mma16816h(C[mt][nt], ah, pl);
                }
            }
        }
        __syncthreads();
    }

    // epilogue: store + fused per-e BN partial stats (quad reduce + RED)
    #pragma unroll
    for (int mt = 0; mt < 4; mt++) {
        int e = bm*128 + warp_m*64 + mt*16 + (lane >> 2);
        float s0 = 0.f, q0 = 0.f, s1 = 0.f, q1 = 0.f;
        #pragma unroll
        for (int nt = 0; nt < 4; nt++) {
            int p = bn*128 + warp_n*32 + nt*8 + (lane & 3)*2;
            float a0 = C[mt][nt][0], a1 = C[mt][nt][1];
            float a2 = C[mt][nt][2], a3 = C[mt][nt][3];
            *(float2*)&d_Y[(size_t)e*BNP + p]       = make_float2(a0, a1);
            *(float2*)&d_Y[(size_t)(e + 8)*BNP + p] = make_float2(a2, a3);
            s0 += a0 + a1; q0 += a0*a0 + a1*a1;
            s1 += a2 + a3; q1 += a2*a2 + a3*a3;
        }
        #pragma unroll
        for (int o = 1; o < 4; o <<= 1) {
            s0 += __shfl_xor_sync(0xffffffffu, s0, o);
            q0 += __shfl_xor_sync(0xffffffffu, q0, o);
            s1 += __shfl_xor_sync(0xffffffffu, s1, o);
            q1 += __shfl_xor_sync(0xffffffffu, q1, o);
        }
        if ((lane & 3) == 0) {
            atomicAdd(&d_sumY[e], s0);     atomicAdd(&d_sqY[e], q0);
            atomicAdd(&d_sumY[e + 8], s1); atomicAdd(&d_sqY[e + 8], q1);
        }
    }
}

// ---------------- conv BN + leaky + pooling (single pass, stats precomputed) --
__global__ void k_reduce(const float* __restrict__ gf, const float* __restrict__ bef) {
    int e = blockIdx.x;
    const float* y = d_Y + (size_t)e*BNP;
    int t = threadIdx.x, lane = t & 31, w = t >> 5;
    float mu = d_sumY[e]*(1.f/BNP);
    float var = d_sqY[e]*(1.f/BNP) - mu*mu;
    float sc = rsqrtf(var + 1e-5f)*gf[e], sh = bef[e];
    __shared__ float w1a[8], w2a[8];
    for (int b = 0; b < BB; b++) {
        float mx = -FLT_MAX, sm = 0.f;
        for (int j = t; j < NPT; j += 256) {
            float v = y[b*NPT + j];
            v = (v - mu)*sc + sh;
            v = v > 0.f ? v : 0.2f*v;
            mx = fmaxf(mx, v); sm += v;
        }
        #pragma unroll
        for (int o = 16; o; o >>= 1) {
            mx = fmaxf(mx, __shfl_xor_sync(0xffffffffu, mx, o));
            sm += __shfl_xor_sync(0xffffffffu, sm, o);
        }
        if (lane == 0) { w1a[w] = mx; w2a[w] = sm; }
        __syncthreads();
        if (t == 0) {
            float MX = w1a[0], SM = w2a[0];
            #pragma unroll
            for (int i = 1; i < 8; i++) { MX = fmaxf(MX, w1a[i]); SM += w2a[i]; }
            d_x12[b*2*EMB + e] = MX;
            d_x12[b*2*EMB + EMB + e] = SM*(1.f/NPT);
        }
        __syncthreads();
    }
}

// ---------------- head (k-split parallel) ----------------
__global__ void k_head1(const float* __restrict__ w1, const float* __restrict__ g6,
                        const float* __restrict__ b6) {
    int jl = threadIdx.x & 15, ks = threadIdx.x >> 4;
    int j = blockIdx.x*16 + jl;
    float acc[BB];
    #pragma unroll
    for (int b = 0; b < BB; b++) acc[b] = 0.f;
    for (int k = ks*128; k < ks*128 + 128; k++) {
        float wv = w1[k*512 + j];
        #pragma unroll
        for (int b = 0; b < BB; b++) acc[b] += d_x12[b*2*EMB + k]*wv;
    }
    __shared__ float sh[16][16][BB];
    #pragma unroll
    for (int b = 0; b < BB; b++) sh[ks][jl][b] = acc[b];
    __syncthreads();
    if (ks == 0) {
        #pragma unroll
        for (int b = 0; b < BB; b++) {
            float s = 0.f;
            #pragma unroll
            for (int i = 0; i < 16; i++) s += sh[i][jl][b];
            acc[b] = s;
        }
        float m = 0.f;
        #pragma unroll
        for (int b = 0; b < BB; b++) m += acc[b];
        m *= (1.f/BB);
        float var = 0.f;
        #pragma unroll
        for (int b = 0; b < BB; b++) { float d = acc[b]-m; var += d*d; }
        var *= (1.f/BB);
        float sc = rsqrtf(var + 1e-5f)*g6[j], bb = b6[j];
        #pragma unroll
        for (int b = 0; b < BB; b++) {
            float o = (acc[b]-m)*sc + bb;
            d_h512[b*512 + j] = o > 0.f ? o : 0.2f*o;
        }
    }
}

__global__ void k_head2(const float* __restrict__ w2, const float* __restrict__ b2,
                        const float* __restrict__ g7, const float* __restrict__ b7) {
    int jl = threadIdx.x & 31, ks = threadIdx.x >> 5;
    int j = blockIdx.x*32 + jl;
    float acc[BB];
    #pragma unroll
    for (int b = 0; b < BB; b++) acc[b] = 0.f;
    for (int k = ks*64; k < ks*64 + 64; k++) {
        float wv = w2[k*256 + j];
        #pragma unroll
        for (int b = 0; b < BB; b++) acc[b] += d_h512[b*512 + k]*wv;
    }
    __shared__ float sh[8][32][BB];
    #pragma unroll
    for (int b = 0; b < BB; b++) sh[ks][jl][b] = acc[b];
    __syncthreads();
    if (ks == 0) {
        #pragma unroll
        for (int b = 0; b < BB; b++) {
            float s = 0.f;
            #pragma unroll
            for (int i = 0; i < 8; i++) s += sh[i][jl][b];
            acc[b] = s + b2[j];
        }
        float m = 0.f;
        #pragma unroll
        for (int b = 0; b < BB; b++) m += acc[b];
        m *= (1.f/BB);
        float var = 0.f;
        #pragma unroll
        for (int b = 0; b < BB; b++) { float d = acc[b]-m; var += d*d; }
        var *= (1.f/BB);
        float sc = rsqrtf(var + 1e-5f)*g7[j], bb = b7[j];
        #pragma unroll
        for (int b = 0; b < BB; b++) {
            float o = (acc[b]-m)*sc + bb;
            d_h256[b*256 + j] = o > 0.f ? o : 0.2f*o;
        }
    }
}

__global__ void k_head3(const float* __restrict__ w3, const float* __restrict__ b3,
                        float* __restrict__ out) {
    int jl = threadIdx.x & 63, ks = threadIdx.x >> 6;
    float acc[BB];
    #pragma unroll
    for (int b = 0; b < BB; b++) acc[b] = 0.f;
    if (jl < 40) {
        for (int k = ks*64; k < ks*64 + 64; k++) {
            float wv = w3[k*40 + jl];
            #pragma unroll
            for (int b = 0; b < BB; b++) acc[b] += d_h256[b*256 + k]*wv;
        }
    }
    __shared__ float sh[4][64][BB];
    #pragma unroll
    for (int b = 0; b < BB; b++) sh[ks][jl][b] = acc[b];
    __syncthreads();
    if (ks == 0 && jl < 40) {
        #pragma unroll
        for (int b = 0; b < BB; b++) {
            float s = b3[jl];
            #pragma unroll
            for (int i = 0; i < 4; i++) s += sh[i][jl][b];
            out[b*40 + jl] = s;
        }
    }
}

// ---------------- launch ----------------
extern "C" void kernel_launch(void* const* d_in, const int* in_sizes, int n_in,
                              void* d_out, int out_size) {
    const float* x     = (const float*)d_in[0];
    const float* w0    = (const float*)d_in[1];
    const float* b0    = (const float*)d_in[2];
    const float* g0    = (const float*)d_in[3];
    const float* be0   = (const float*)d_in[4];
    const float* wr    = (const float*)d_in[5];
    const float* br    = (const float*)d_in[6];
    const float* gr    = (const float*)d_in[7];
    const float* ber   = (const float*)d_in[8];
    const float* W     = (const float*)d_in[9];
    const float* Bv    = (const float*)d_in[10];
    const float* G     = (const float*)d_in[11];
    const float* Be    = (const float*)d_in[12];
    const float* wconv = (const float*)d_in[13];
    const float* gf    = (const float*)d_in[14];
    const float* bef   = (const float*)d_in[15];
    const float* w1    = (const float*)d_in[16];
    const float* g6    = (const float*)d_in[17];
    const float* b6    = (const float*)d_in[18];
    const float* w2    = (const float*)d_in[19];
    const float* b2    = (const float*)d_in[20];
    const float* g7    = (const float*)d_in[21];
    const float* b7    = (const float*)d_in[22];
    const float* w3    = (const float*)d_in[23];
    const float* b3    = (const float*)d_in[24];
    float* out = (float*)d_out;

    static int smem_set = 0;
    if (!smem_set) {
        cudaFuncSetAttribute(k_conv_mma, cudaFuncAttributeMaxDynamicSharedMemorySize, SMEM_CONV);
        smem_set = 1;
    }

    // graph build (k_knn kept in the 4th = captured slot)
    k_init<<<64, 256>>>();
    k_prep<<<64, 256>>>(x);
    k_cvtA<<<256, 256>>>(wconv);
    k_knn<<<1024, 256>>>();
    k_scanA<<<16, 1024>>>();
    k_scanB<<<64, 256>>>();
    k_fill<<<64, 256>>>();

    // layer 0
    k_l0mm<<<4096, 256>>>(x, w0, wr, br);
    k_gather_stats<<<4096, 256>>>(b0, 0);
    k_post0_mm<<<256, 256>>>(g0, be0, gr, ber, W);

    // layers 1..3
    k_gather_stats<<<4096, 256>>>(Bv, 1);
    k_postL_mm<<<256, 256>>>(1, G, Be, W + 4096);
    k_gather_stats<<<4096, 256>>>(Bv + 64, 2);
    k_postL_mm<<<256, 256>>>(2, G + 64, Be + 64, W + 8192);
    k_gather_stats<<<4096, 256>>>(Bv + 128, 3);
    k_post3<<<4096, 256>>>(G + 128, Be + 128);

    // conv 256 -> 1024 (fp16 3-term) + fused BN stats, then BN+leaky+pool
    dim3 cgrid(128, 8);
    k_conv_mma<<<cgrid, 256, SMEM_CONV>>>();
    k_reduce<<<1024, 256>>>(gf, bef);

    // head
    k_head1<<<32, 256>>>(w1, g6, b6);
    k_head2<<<8, 256>>>(w2, b2, g7, b7);
    k_head3<<<1, 256>>>(w3, b3, out);
}

// round 10
// speedup vs baseline: 10.2161x; 1.0545x over previous
#include <cuda_runtime.h>
#include <cuda_fp16.h>
#include <float.h>
#include <stdint.h>

// ---------------- problem constants ----------------
#define BB    8
#define NPT   2048
#define BNP   16384          // BB*NPT
#define KNN   20
#define CH    64
#define FD    256            // 4*CH
#define EMB   1024

// ---------------- scratch (device globals; no mallocs allowed) ----------------
__device__ float4 d_P4[BB*NPT];
__device__ int   d_nbr[BNP*KNN];
__device__ int   d_deg[BNP];
__device__ int   d_rowstart[BNP+1];
__device__ int   d_cursor[BNP];
__device__ int   d_bsum[16];
__device__ int   d_rev[BNP*KNN];
__device__ float d_F[BNP*FD];
__device__ float d_sup[BNP*CH];
__device__ float d_z[BNP*CH];
__device__ float d_rz[BNP*CH];
__device__ __half d_Yh[(size_t)EMB*BNP];   // conv output fp16 [e][p], 32 MB
__device__ unsigned d_maxK[BB*EMB], d_minK[BB*EMB];  // per (b,e) raw-y extrema keys
__device__ float d_x12[BB*2*EMB];
__device__ float d_h512[BB*512];
__device__ float d_h256[BB*256];
__device__ float d_sumA[4*CH], d_sqA[4*CH];
__device__ float d_sumB[CH], d_sqB[CH];
__device__ float d_sumY[EMB], d_sqY[EMB];
__device__ __half d_Ah[EMB*FD], d_Al[EMB*FD];   // wconv fp16 hi/lo
__device__ __half d_Fh[BNP*FD], d_Fl[BNP*FD];   // features fp16 hi/lo

// ---------------- helpers ----------------
__device__ __forceinline__ uint32_t smem_u32(const void* p) {
    uint32_t a;
    asm("{ .reg .u64 t; cvta.to.shared.u64 t, %1; cvt.u32.u64 %0, t; }" : "=r"(a) : "l"(p));
    return a;
}
__device__ __forceinline__ void ldm_x4(uint32_t* r, uint32_t addr) {
    asm volatile("ldmatrix.sync.aligned.m8n8.x4.shared.b16 {%0,%1,%2,%3}, [%4];"
        : "=r"(r[0]), "=r"(r[1]), "=r"(r[2]), "=r"(r[3]) : "r"(addr));
}
__device__ __forceinline__ void mma16816h(float* c, const uint32_t* a, const uint32_t* b) {
    asm volatile(
        "mma.sync.aligned.m16n8k16.row.col.f32.f16.f16.f32 "
        "{%0,%1,%2,%3}, {%4,%5,%6,%7}, {%8,%9}, {%0,%1,%2,%3};"
        : "+f"(c[0]), "+f"(c[1]), "+f"(c[2]), "+f"(c[3])
        : "r"(a[0]), "r"(a[1]), "r"(a[2]), "r"(a[3]), "r"(b[0]), "r"(b[1]));
}
__device__ __forceinline__ void cp16(uint32_t sdst, const void* gsrc) {
    asm volatile("cp.async.cg.shared.global [%0], [%1], 16;" :: "r"(sdst), "l"(gsrc));
}
#define CP_COMMIT() asm volatile("cp.async.commit_group;" ::: "memory")
#define CP_WAIT0()  asm volatile("cp.async.wait_group 0;" ::: "memory")

__device__ __forceinline__ unsigned fkey(float f) {
    unsigned u = __float_as_uint(f);
    return (u & 0x80000000u) ? ~u : (u | 0x80000000u);
}
__device__ __forceinline__ float unkey(unsigned k) {
    return (k & 0x80000000u) ? __uint_as_float(k & 0x7fffffffu) : __uint_as_float(~k);
}

// ---------------- begin: zero stats/deg + wconv fp16 hi/lo split -------------
__global__ void k_begin(const float* __restrict__ w) {
    int t = blockIdx.x*256 + threadIdx.x;   // 65536 threads
    if (t < BNP) d_deg[t] = 0;
    if (t < 4*CH) { d_sumA[t] = 0.f; d_sqA[t] = 0.f; }
    if (t < CH)   { d_sumB[t] = 0.f; d_sqB[t] = 0.f; }
    if (t < EMB)  { d_sumY[t] = 0.f; d_sqY[t] = 0.f; }
    if (t < BB*EMB) { d_maxK[t] = 0u; d_minK[t] = 0xFFFFFFFFu; }
    float4 x = ((const float4*)w)[t];       // EMB*FD/4 = 65536
    __half h0 = __float2half_rn(x.x), h1 = __float2half_rn(x.y);
    __half h2 = __float2half_rn(x.z), h3 = __float2half_rn(x.w);
    __half l0 = __float2half_rn(x.x - __half2float(h0));
    __half l1 = __float2half_rn(x.y - __half2float(h1));
    __half l2 = __float2half_rn(x.z - __half2float(h2));
    __half l3 = __float2half_rn(x.w - __half2float(h3));
    ((__half2*)d_Ah)[t*2]   = __half2(h0, h1);
    ((__half2*)d_Ah)[t*2+1] = __half2(h2, h3);
    ((__half2*)d_Al)[t*2]   = __half2(l0, l1);
    ((__half2*)d_Al)[t*2+1] = __half2(l2, l3);
}

// pts[b,c,n] = x[b, (c*N+n)%3, (c*N+n)/3]
__global__ void k_prep(const float* __restrict__ x) {
    int t = blockIdx.x*256 + threadIdx.x;
    if (t >= BNP) return;
    int b = t >> 11, n = t & 2047;
    const float* xb = x + b*3*NPT;
    float v[3]; float acc = 0.f;
    #pragma unroll
    for (int c = 0; c < 3; c++) {
        int L = c*NPT + n;
        v[c] = xb[(L % 3)*NPT + (L / 3)];
        acc += v[c]*v[c];
    }
    d_P4[t] = make_float4(v[0], v[1], v[2], acc);
}

// identical arithmetic in both KNN passes (explicit intrinsics -> deterministic)
__device__ __forceinline__ float pdist(float4 q, float4 pm) {
    float dot = __fmaf_rn(q.x, pm.x, __fmaf_rn(q.y, pm.y, __fmul_rn(q.z, pm.z)));
    return __fadd_rn(__fmaf_rn(2.f, dot, -q.w), -pm.w);
}

// ---------------- knn: two-pass threshold, 2 rows per warp share loads -------
__global__ void __launch_bounds__(256) k_knn() {
    __shared__ float4 sP[NPT];               // 32 KB
    __shared__ float sv[8][2][128];
    __shared__ int   si[8][2][128];
    int b = blockIdx.x >> 7;                 // 8 batches x 128 chunks
    int chunk = blockIdx.x & 127;            // 16 rows per chunk
    for (int i = threadIdx.x; i < NPT; i += 256)
        sP[i] = d_P4[b*NPT + i];
    __syncthreads();

    int warp = threadIdx.x >> 5, lane = threadIdx.x & 31;
    int n0 = chunk*16 + warp*2;
    float4 q0 = sP[n0], q1 = sP[n0 + 1];

    float m00 = -FLT_MAX, m01 = -FLT_MAX, m10 = -FLT_MAX, m11 = -FLT_MAX;
    for (int m = lane; m < NPT; m += 64) {
        float4 pa = sP[m], pb = sP[m + 32];
        m00 = fmaxf(m00, pdist(q0, pa)); m01 = fmaxf(m01, pdist(q0, pb));
        m10 = fmaxf(m10, pdist(q1, pa)); m11 = fmaxf(m11, pdist(q1, pb));
    }
    float vmax0 = fmaxf(m00, m01), vmax1 = fmaxf(m10, m11);

    float tval[2];
    #pragma unroll
    for (int r = 0; r < 2; r++) {
        unsigned mykey = fkey(r ? vmax1 : vmax0);
        unsigned tkey = 0;
        #pragma unroll 1
        for (int k = 0; k < KNN; k++) {
            tkey = __reduce_max_sync(0xffffffffu, mykey);
            unsigned msk = __ballot_sync(0xffffffffu, mykey == tkey);
            if (lane == __ffs(msk) - 1) mykey = 0;
        }
        tval[r] = unkey(tkey);
    }

    int base0 = 0, base1 = 0;
    for (int m = lane; m < NPT; m += 32) {
        float4 pm = sP[m];
        float pd0 = pdist(q0, pm);
        float pd1 = pdist(q1, pm);
        bool s0 = (pd0 >= tval[0]);
        unsigned k0 = __ballot_sync(0xffffffffu, s0);
        if (s0) {
            int pos = base0 + __popc(k0 & ((1u << lane) - 1));
            if (pos < 128) { sv[warp][0][pos] = pd0; si[warp][0][pos] = m; }
        }
        base0 += __popc(k0);
        bool s1 = (pd1 >= tval[1]);
        unsigned k1 = __ballot_sync(0xffffffffu, s1);
        if (s1) {
            int pos = base1 + __popc(k1 & ((1u << lane) - 1));
            if (pos < 128) { sv[warp][1][pos] = pd1; si[warp][1][pos] = m; }
        }
        base1 += __popc(k1);
    }
    __syncwarp();

    #pragma unroll 1
    for (int r = 0; r < 2; r++) {
        int S = (r ? base1 : base0);
        if (S > 128) S = 128;
        float v[4]; int id[4];
        #pragma unroll
        for (int j = 0; j < 4; j++) {
            int idx = lane + j*32;
            if (idx < S) { v[j] = sv[warp][r][idx]; id[j] = si[warp][r][idx]; }
            else         { v[j] = -FLT_MAX;         id[j] = 0x7fffffff; }
        }
        #define CE(A_, B_) { \
            bool sw_ = (v[B_] > v[A_]) || (v[B_] == v[A_] && id[B_] < id[A_]); \
            if (sw_) { float tv_ = v[A_]; v[A_] = v[B_]; v[B_] = tv_; \
                       int ti_ = id[A_]; id[A_] = id[B_]; id[B_] = ti_; } }
        CE(0,1) CE(2,3) CE(0,2) CE(1,3) CE(1,2)
        #undef CE

        int pg = b*NPT + n0 + r;
        #pragma unroll 1
        for (int k = 0; k < KNN; k++) {
            unsigned mk = fkey(v[0]);
            unsigned best = __reduce_max_sync(0xffffffffu, mk);
            int cand = (mk == best) ? id[0] : 0x7fffffff;
            int bmi = __reduce_min_sync(0xffffffffu, cand);
            if (mk == best && id[0] == bmi) {
                v[0] = v[1]; id[0] = id[1];
                v[1] = v[2]; id[1] = id[2];
                v[2] = v[3]; id[2] = id[3];
                v[3] = -FLT_MAX; id[3] = 0x7fffffff;
            }
            if (lane == 0) {
                int qg = b*NPT + bmi;
                d_nbr[pg*KNN + k] = qg;
                atomicAdd(&d_deg[qg], 1);
            }
        }
    }
}

// ---------------- parallel scan ----------------
__global__ void k_scanA() {
    int t = threadIdx.x, g = blockIdx.x*1024 + t;
    int v = d_deg[g];
    int lane = t & 31, wid = t >> 5;
    int vv = v;
    #pragma unroll
    for (int o = 1; o < 32; o <<= 1) { int u = __shfl_up_sync(0xffffffffu, vv, o); if (lane >= o) vv += u; }
    __shared__ int ws[32];
    if (lane == 31) ws[wid] = vv;
    __syncthreads();
    if (wid == 0) {
        int w = ws[lane];
        #pragma unroll
        for (int o = 1; o < 32; o <<= 1) { int u = __shfl_up_sync(0xffffffffu, w, o); if (lane >= o) w += u; }
        ws[lane] = w;
    }
    __syncthreads();
    int incl = vv + (wid ? ws[wid-1] : 0);
    d_rowstart[g] = incl - v;
    if (t == 1023) d_bsum[blockIdx.x] = incl;
}

__global__ void k_scanB() {
    int g = blockIdx.x*256 + threadIdx.x;
    int sb = g >> 10;
    int off = 0;
    #pragma unroll 1
    for (int i = 0; i < sb; i++) off += d_bsum[i];
    int rs = d_rowstart[g] + off;
    d_rowstart[g] = rs;
    d_cursor[g] = rs;
    if (g == BNP - 1) {
        int tot = 0;
        #pragma unroll
        for (int i = 0; i < 16; i++) tot += d_bsum[i];
        d_rowstart[BNP] = tot;
    }
}

__global__ void k_fill() {
    int p = blockIdx.x*256 + threadIdx.x;
    if (p >= BNP) return;
    #pragma unroll
    for (int k = 0; k < KNN; k++) {
        int q = d_nbr[p*KNN + k];
        int pos = atomicAdd(&d_cursor[q], 1);
        d_rev[pos] = p;
    }
}

// ---------------- layer 0: sup0 = flat@w0 ; rz = flat@wr + br (+ rz stats) ----
__global__ void k_l0mm(const float* __restrict__ x, const float* __restrict__ w0,
                       const float* __restrict__ wr, const float* __restrict__ br) {
    int tid = threadIdx.x;
    int t = blockIdx.x*256 + tid;
    int p = t >> 6, c = t & 63;
    int b = p >> 11, n = p & 2047;
    const float* xb = x + b*3*NPT;
    float x0 = xb[n], x1 = xb[NPT + n], x2 = xb[2*NPT + n];
    d_sup[t] = x0*w0[c] + x1*w0[64+c] + x2*w0[128+c];
    float rz = x0*wr[c] + x1*wr[64+c] + x2*wr[128+c] + br[c];
    d_rz[t] = rz;
    __shared__ float s1[256], s2[256];
    s1[tid] = rz; s2[tid] = rz*rz;
    __syncthreads();
    if (tid < 64) {
        float a = s1[tid] + s1[64+tid] + s1[128+tid] + s1[192+tid];
        float q = s2[tid] + s2[64+tid] + s2[128+tid] + s2[192+tid];
        atomicAdd(&d_sumB[tid], a);
        atomicAdd(&d_sqB[tid], q);
    }
}

// ---------------- gather (reverse CSR) + bias + z stats ----------------
__global__ void k_gather_stats(const float* __restrict__ bias, int layer) {
    int t = threadIdx.x;
    int q = blockIdx.x*4 + (t >> 6);
    int c = t & 63;
    float acc = bias[c];
    int s0 = d_rowstart[q], e0 = d_rowstart[q+1];
    for (int i = s0; i < e0; i++) acc += d_sup[d_rev[i]*64 + c];
    d_z[q*64 + c] = acc;
    __shared__ float s1[256], s2[256];
    s1[t] = acc; s2[t] = acc*acc;
    __syncthreads();
    if (t < 64) {
        float a = s1[t] + s1[64+t] + s1[128+t] + s1[192+t];
        float qq = s2[t] + s2[64+t] + s2[128+t] + s2[192+t];
        atomicAdd(&d_sumA[layer*64 + t], a);
        atomicAdd(&d_sqA[layer*64 + t], qq);
    }
}

// ---------------- fused post (layer 0) + mm for layer 1 ----------------
__global__ void __launch_bounds__(256) k_post0_mm(
        const float* __restrict__ g0, const float* __restrict__ be0,
        const float* __restrict__ gr, const float* __restrict__ ber,
        const float* __restrict__ W1) {
    __shared__ float Hs[64*64];
    __shared__ float Ws[64*64];
    int tid = threadIdx.x;
    int p0 = blockIdx.x*64;
    int c = tid & 63, rg = tid >> 6;
    float mA = d_sumA[c]*(1.f/BNP);
    float vA = d_sqA[c]*(1.f/BNP) - mA*mA;
    float sA = rsqrtf(vA + 1e-5f)*g0[c], bA = be0[c];
    float mB = d_sumB[c]*(1.f/BNP);
    float vB = d_sqB[c]*(1.f/BNP) - mB*mB;
    float sB = rsqrtf(vB + 1e-5f)*gr[c], bB = ber[c];
    #pragma unroll
    for (int i = 0; i < 16; i++) {
        int r = rg + i*4, p = p0 + r;
        float o = fmaxf((d_z[p*64+c] - mA)*sA + bA, 0.f);
        float rr = (d_rz[p*64+c] - mB)*sB + bB;
        float h = fmaxf(o + rr, 0.f);
        Hs[r*64+c] = h;
        d_F[p*FD + c] = h;
        __half hi = __float2half_rn(h);
        d_Fh[p*FD + c] = hi;
        d_Fl[p*FD + c] = __float2half_rn(h - __half2float(hi));
    }
    for (int i = tid; i < 4096; i += 256) Ws[i] = W1[i];
    __syncthreads();
    for (int r = rg; r < 64; r += 4) {
        float acc = 0.f;
        #pragma unroll 16
        for (int k = 0; k < 64; k++) acc += Hs[r*64+k]*Ws[k*64+c];
        d_sup[(p0+r)*64+c] = acc;
    }
}

// ---------------- fused post (layers 1,2) + mm for next layer ----------------
__global__ void __launch_bounds__(256) k_postL_mm(int layer,
        const float* __restrict__ G, const float* __restrict__ Be,
        const float* __restrict__ Wn) {
    __shared__ float Hs[64*64];
    __shared__ float Ws[64*64];
    int tid = threadIdx.x;
    int p0 = blockIdx.x*64;
    int c = tid & 63, rg = tid >> 6;
    float m = d_sumA[layer*64+c]*(1.f/BNP);
    float v = d_sqA[layer*64+c]*(1.f/BNP) - m*m;
    float sc = rsqrtf(v + 1e-5f)*G[c], bc = Be[c];
    #pragma unroll
    for (int i = 0; i < 16; i++) {
        int r = rg + i*4, p = p0 + r;
        float a = fmaxf((d_z[p*64+c] - m)*sc + bc, 0.f);
        float h = fmaxf(a + d_F[p*FD + (layer-1)*64 + c], 0.f);
        Hs[r*64+c] = h;
        d_F[p*FD + layer*64 + c] = h;
        __half hi = __float2half_rn(h);
        d_Fh[p*FD + layer*64 + c] = hi;
        d_Fl[p*FD + layer*64 + c] = __float2half_rn(h - __half2float(hi));
    }
    for (int i = tid; i < 4096; i += 256) Ws[i] = Wn[i];
    __syncthreads();
    for (int r = rg; r < 64; r += 4) {
        float acc = 0.f;
        #pragma unroll 16
        for (int k = 0; k < 64; k++) acc += Hs[r*64+k]*Ws[k*64+c];
        d_sup[(p0+r)*64+c] = acc;
    }
}

// ---------------- post layer 3 ----------------
__global__ void k_post3(const float* __restrict__ G, const float* __restrict__ Be) {
    int t = blockIdx.x*256 + threadIdx.x;
    int p = t >> 6, c = t & 63;
    float m = d_sumA[3*64+c]*(1.f/BNP);
    float v = d_sqA[3*64+c]*(1.f/BNP) - m*m;
    float a = fmaxf((d_z[t] - m)*rsqrtf(v + 1e-5f)*G[c] + Be[c], 0.f);
    float h = fmaxf(a + d_F[p*FD + 2*64 + c], 0.f);
    __half hi = __float2half_rn(h);
    d_Fh[p*FD + 3*64 + c] = hi;
    d_Fl[p*FD + 3*64 + c] = __float2half_rn(h - __half2float(hi));
}

// ---------------- conv GEMM: fp16 3-term split, cp.async 2-stage -------------
// C = Ah.Bh + Al.Bh + Ah.Bl ; epilogue stores fp16 y + stats + raw extrema
#define PITCH 80
#define TSZ   (128*PITCH)
#define STAGE (4*TSZ)
#define SMEM_CONV (2*STAGE)   // 81920 B

__global__ void __launch_bounds__(256) k_conv_mma() {
    extern __shared__ __align__(16) uint8_t sm[];
    uint32_t sb = smem_u32(sm);

    int tid = threadIdx.x, wid = tid >> 5, lane = tid & 31;
    int warp_m = wid >> 2, warp_n = wid & 3;
    int bn = blockIdx.x;
    int bm = blockIdx.y;
    int bb = bn >> 4;                       // batch of this p-tile (128 | 2048)

    const uint4* gAh = (const uint4*)d_Ah;
    const uint4* gAl = (const uint4*)d_Al;
    const uint4* gBh = (const uint4*)d_Fh;
    const uint4* gBl = (const uint4*)d_Fl;

    float C[4][4][4];
    #pragma unroll
    for (int i = 0; i < 4; i++)
        #pragma unroll
        for (int j = 0; j < 4; j++)
            #pragma unroll
            for (int q = 0; q < 4; q++) C[i][j][q] = 0.f;

    int rowA  = warp_m*64 + (lane & 15);
    int halfA = lane >> 4;
    uint32_t oAh = rowA*PITCH + halfA*16;
    uint32_t oAl = TSZ + rowA*PITCH + halfA*16;
    int rowB  = warp_n*32 + (lane & 7) + ((lane >> 4) << 3);
    int halfB = (lane >> 3) & 1;
    uint32_t oBh = 2*TSZ + rowB*PITCH + halfB*16;
    uint32_t oBl = 3*TSZ + rowB*PITCH + halfB*16;

    auto issue = [&](int kc, int s) {
        uint32_t base = sb + s*STAGE;
        #pragma unroll
        for (int l = 0; l < 2; l++) {
            int i = tid + l*256;
            int row = i >> 2, c = i & 3;
            uint32_t so = row*PITCH + c*16;
            size_t ga = (size_t)(bm*128 + row)*32 + kc*4 + c;
            size_t gb = (size_t)(bn*128 + row)*32 + kc*4 + c;
            cp16(base + so,          gAh + ga);
            cp16(base + TSZ + so,    gAl + ga);
            cp16(base + 2*TSZ + so,  gBh + gb);
            cp16(base + 3*TSZ + so,  gBl + gb);
        }
        CP_COMMIT();
    };

    issue(0, 0);
    for (int kc = 0; kc < 8; kc++) {
        int s = kc & 1;
        CP_WAIT0();
        __syncthreads();
        if (kc + 1 < 8) issue(kc + 1, s ^ 1);
        uint32_t stb = sb + s*STAGE;

        #pragma unroll
        for (int ksub = 0; ksub < 2; ksub++) {
            uint32_t koff = (ksub*2)*16;
            uint32_t bh[8], bl[8];
            ldm_x4(bh + 0, stb + oBh + koff);
            ldm_x4(bh + 4, stb + oBh + koff + 16*PITCH);
            ldm_x4(bl + 0, stb + oBl + koff);
            ldm_x4(bl + 4, stb + oBl + koff + 16*PITCH);
            #pragma unroll
            for (int mt = 0; mt < 4; mt++) {
                uint32_t ah[4], al[4];
                ldm_x4(ah, stb + oAh + koff + mt*16*PITCH);
                ldm_x4(al, stb + oAl + koff + mt*16*PITCH);
                #pragma unroll
                for (int nt = 0; nt < 4; nt++) {
                    const uint32_t* ph = &bh[(nt >> 1)*4 + (nt & 1)*2];
                    const uint32_t* pl = &bl[(nt >> 1)*4 + (nt & 1)*2];
                    mma16816h(C[mt][nt], ah, ph);
                    mma16816h(C[mt][nt], al, ph);
                    mma16816h(C[mt][nt], ah, pl);
                }
            }
        }
        __syncthreads();
    }

    // epilogue: fp16 store + per-e BN partial stats + raw extrema (for exact max-pool)
    #pragma unroll
    for (int mt = 0; mt < 4; mt++) {
        int e = bm*128 + warp_m*64 + mt*16 + (lane >> 2);
        float s0 = 0.f, q0 = 0.f, s1 = 0.f, q1 = 0.f;
        float mx0 = -FLT_MAX, mn0 = FLT_MAX, mx1 = -FLT_MAX, mn1 = FLT_MAX;
        #pragma unroll
        for (int nt = 0; nt < 4; nt++) {
            int p = bn*128 + warp_n*32 + nt*8 + (lane & 3)*2;
            float a0 = C[mt][nt][0], a1 = C[mt][nt][1];
            float a2 = C[mt][nt][2], a3 = C[mt][nt][3];
            *(__half2*)&d_Yh[(size_t)e*BNP + p] =
                __half2(__float2half_rn(a0), __float2half_rn(a1));
            *(__half2*)&d_Yh[(size_t)(e + 8)*BNP + p] =
                __half2(__float2half_rn(a2), __float2half_rn(a3));
            s0 += a0 + a1; q0 += a0*a0 + a1*a1;
            s1 += a2 + a3; q1 += a2*a2 + a3*a3;
            mx0 = fmaxf(mx0, fmaxf(a0, a1)); mn0 = fminf(mn0, fminf(a0, a1));
            mx1 = fmaxf(mx1, fmaxf(a2, a3)); mn1 = fminf(mn1, fminf(a2, a3));
        }
        #pragma unroll
        for (int o = 1; o < 4; o <<= 1) {
            s0 += __shfl_xor_sync(0xffffffffu, s0, o);
            q0 += __shfl_xor_sync(0xffffffffu, q0, o);
            s1 += __shfl_xor_sync(0xffffffffu, s1, o);
            q1 += __shfl_xor_sync(0xffffffffu, q1, o);
            mx0 = fmaxf(mx0, __shfl_xor_sync(0xffffffffu, mx0, o));
            mn0 = fminf(mn0, __shfl_xor_sync(0xffffffffu, mn0, o));
            mx1 = fmaxf(mx1, __shfl_xor_sync(0xffffffffu, mx1, o));
            mn1 = fminf(mn1, __shfl_xor_sync(0xffffffffu, mn1, o));
        }
        if ((lane & 3) == 0) {
            atomicAdd(&d_sumY[e], s0);     atomicAdd(&d_sqY[e], q0);
            atomicAdd(&d_sumY[e + 8], s1); atomicAdd(&d_sqY[e + 8], q1);
            atomicMax(&d_maxK[bb*EMB + e], fkey(mx0));
            atomicMin(&d_minK[bb*EMB + e], fkey(mn0));
            atomicMax(&d_maxK[bb*EMB + e + 8], fkey(mx1));
            atomicMin(&d_minK[bb*EMB + e + 8], fkey(mn1));
        }
    }
}

// ---------------- BN + leaky + mean pool (max pool from exact extrema) -------
__global__ void k_reduce(const float* __restrict__ gf, const float* __restrict__ bef) {
    int e = blockIdx.x;
    const __half2* y2 = (const __half2*)(d_Yh + (size_t)e*BNP);
    int t = threadIdx.x, lane = t & 31, w = t >> 5;
    float mu = d_sumY[e]*(1.f/BNP);
    float var = d_sqY[e]*(1.f/BNP) - mu*mu;
    float sc = rsqrtf(var + 1e-5f)*gf[e], sh = bef[e];
    __shared__ float wsum[8];
    for (int b = 0; b < BB; b++) {
        float sm = 0.f;
        const __half2* yb = y2 + b*(NPT/2);
        for (int j = t; j < NPT/2; j += 256) {
            float2 v2 = __half22float2(yb[j]);
            float v0 = (v2.x - mu)*sc + sh; v0 = v0 > 0.f ? v0 : 0.2f*v0;
            float v1 = (v2.y - mu)*sc + sh; v1 = v1 > 0.f ? v1 : 0.2f*v1;
            sm += v0 + v1;
        }
        #pragma unroll
        for (int o = 16; o; o >>= 1) sm += __shfl_xor_sync(0xffffffffu, sm, o);
        if (lane == 0) wsum[w] = sm;
        __syncthreads();
        if (t == 0) {
            float SM = 0.f;
            #pragma unroll
            for (int i = 0; i < 8; i++) SM += wsum[i];
            unsigned mk = (sc >= 0.f) ? d_maxK[b*EMB + e] : d_minK[b*EMB + e];
            float raw = unkey(mk);
            float v = (raw - mu)*sc + sh;
            v = v > 0.f ? v : 0.2f*v;
            d_x12[b*2*EMB + e] = v;
            d_x12[b*2*EMB + EMB + e] = SM*(1.f/NPT);
        }
        __syncthreads();
    }
}

// ---------------- head (k-split parallel) ----------------
__global__ void k_head1(const float* __restrict__ w1, const float* __restrict__ g6,
                        const float* __restrict__ b6) {
    int jl = threadIdx.x & 15, ks = threadIdx.x >> 4;
    int j = blockIdx.x*16 + jl;
    float acc[BB];
    #pragma unroll
    for (int b = 0; b < BB; b++) acc[b] = 0.f;
    for (int k = ks*128; k < ks*128 + 128; k++) {
        float wv = w1[k*512 + j];
        #pragma unroll
        for (int b = 0; b < BB; b++) acc[b] += d_x12[b*2*EMB + k]*wv;
    }
    __shared__ float sh[16][16][BB];
    #pragma unroll
    for (int b = 0; b < BB; b++) sh[ks][jl][b] = acc[b];
    __syncthreads();
    if (ks == 0) {
        #pragma unroll
        for (int b = 0; b < BB; b++) {
            float s = 0.f;
            #pragma unroll
            for (int i = 0; i < 16; i++) s += sh[i][jl][b];
            acc[b] = s;
        }
        float m = 0.f;
        #pragma unroll
        for (int b = 0; b < BB; b++) m += acc[b];
        m *= (1.f/BB);
        float var = 0.f;
        #pragma unroll
        for (int b = 0; b < BB; b++) { float d = acc[b]-m; var += d*d; }
        var *= (1.f/BB);
        float sc = rsqrtf(var + 1e-5f)*g6[j], bb = b6[j];
        #pragma unroll
        for (int b = 0; b < BB; b++) {
            float o = (acc[b]-m)*sc + bb;
            d_h512[b*512 + j] = o > 0.f ? o : 0.2f*o;
        }
    }
}

__global__ void k_head2(const float* __restrict__ w2, const float* __restrict__ b2,
                        const float* __restrict__ g7, const float* __restrict__ b7) {
    int jl = threadIdx.x & 31, ks = threadIdx.x >> 5;
    int j = blockIdx.x*32 + jl;
    float acc[BB];
    #pragma unroll
    for (int b = 0; b < BB; b++) acc[b] = 0.f;
    for (int k = ks*64; k < ks*64 + 64; k++) {
        float wv = w2[k*256 + j];
        #pragma unroll
        for (int b = 0; b < BB; b++) acc[b] += d_h512[b*512 + k]*wv;
    }
    __shared__ float sh[8][32][BB];
    #pragma unroll
    for (int b = 0; b < BB; b++) sh[ks][jl][b] = acc[b];
    __syncthreads();
    if (ks == 0) {
        #pragma unroll
        for (int b = 0; b < BB; b++) {
            float s = 0.f;
            #pragma unroll
            for (int i = 0; i < 8; i++) s += sh[i][jl][b];
            acc[b] = s + b2[j];
        }
        float m = 0.f;
        #pragma unroll
        for (int b = 0; b < BB; b++) m += acc[b];
        m *= (1.f/BB);
        float var = 0.f;
        #pragma unroll
        for (int b = 0; b < BB; b++) { float d = acc[b]-m; var += d*d; }
        var *= (1.f/BB);
        float sc = rsqrtf(var + 1e-5f)*g7[j], bb = b7[j];
        #pragma unroll
        for (int b = 0; b < BB; b++) {
            float o = (acc[b]-m)*sc + bb;
            d_h256[b*256 + j] = o > 0.f ? o : 0.2f*o;
        }
    }
}

__global__ void k_head3(const float* __restrict__ w3, const float* __restrict__ b3,
                        float* __restrict__ out) {
    int jl = threadIdx.x & 63, ks = threadIdx.x >> 6;
    float acc[BB];
    #pragma unroll
    for (int b = 0; b < BB; b++) acc[b] = 0.f;
    if (jl < 40) {
        for (int k = ks*64; k < ks*64 + 64; k++) {
            float wv = w3[k*40 + jl];
            #pragma unroll
            for (int b = 0; b < BB; b++) acc[b] += d_h256[b*256 + k]*wv;
        }
    }
    __shared__ float sh[4][64][BB];
    #pragma unroll
    for (int b = 0; b < BB; b++) sh[ks][jl][b] = acc[b];
    __syncthreads();
    if (ks == 0 && jl < 40) {
        #pragma unroll
        for (int b = 0; b < BB; b++) {
            float s = b3[jl];
            #pragma unroll
            for (int i = 0; i < 4; i++) s += sh[i][jl][b];
            out[b*40 + jl] = s;
        }
    }
}

// ---------------- launch ----------------
extern "C" void kernel_launch(void* const* d_in, const int* in_sizes, int n_in,
                              void* d_out, int out_size) {
    const float* x     = (const float*)d_in[0];
    const float* w0    = (const float*)d_in[1];
    const float* b0    = (const float*)d_in[2];
    const float* g0    = (const float*)d_in[3];
    const float* be0   = (const float*)d_in[4];
    const float* wr    = (const float*)d_in[5];
    const float* br    = (const float*)d_in[6];
    const float* gr    = (const float*)d_in[7];
    const float* ber   = (const float*)d_in[8];
    const float* W     = (const float*)d_in[9];
    const float* Bv    = (const float*)d_in[10];
    const float* G     = (const float*)d_in[11];
    const float* Be    = (const float*)d_in[12];
    const float* wconv = (const float*)d_in[13];
    const float* gf    = (const float*)d_in[14];
    const float* bef   = (const float*)d_in[15];
    const float* w1    = (const float*)d_in[16];
    const float* g6    = (const float*)d_in[17];
    const float* b6    = (const float*)d_in[18];
    const float* w2    = (const float*)d_in[19];
    const float* b2    = (const float*)d_in[20];
    const float* g7    = (const float*)d_in[21];
    const float* b7    = (const float*)d_in[22];
    const float* w3    = (const float*)d_in[23];
    const float* b3    = (const float*)d_in[24];
    float* out = (float*)d_out;

    static int smem_set = 0;
    if (!smem_set) {
        cudaFuncSetAttribute(k_conv_mma, cudaFuncAttributeMaxDynamicSharedMemorySize, SMEM_CONV);
        smem_set = 1;
    }

    // graph build (k_knn kept in the 4th = captured slot)
    k_begin<<<256, 256>>>(wconv);
    k_prep<<<64, 256>>>(x);
    k_l0mm<<<4096, 256>>>(x, w0, wr, br);
    k_knn<<<1024, 256>>>();
    k_scanA<<<16, 1024>>>();
    k_scanB<<<64, 256>>>();
    k_fill<<<64, 256>>>();

    // layer 0
    k_gather_stats<<<4096, 256>>>(b0, 0);
    k_post0_mm<<<256, 256>>>(g0, be0, gr, ber, W);

    // layers 1..3
    k_gather_stats<<<4096, 256>>>(Bv, 1);
    k_postL_mm<<<256, 256>>>(1, G, Be, W + 4096);
    k_gather_stats<<<4096, 256>>>(Bv + 64, 2);
    k_postL_mm<<<256, 256>>>(2, G + 64, Be + 64, W + 8192);
    k_gather_stats<<<4096, 256>>>(Bv + 128, 3);
    k_post3<<<4096, 256>>>(G + 128, Be + 128);

    // conv 256 -> 1024 (fp16 3-term) + fused stats/extrema, then pool
    dim3 cgrid(128, 8);
    k_conv_mma<<<cgrid, 256, SMEM_CONV>>>();
    k_reduce<<<1024, 256>>>(gf, bef);

    // head
    k_head1<<<32, 256>>>(w1, g6, b6);
    k_head2<<<8, 256>>>(w2, b2, g7, b7);
    k_head3<<<1, 256>>>(w3, b3, out);
}